// round 5
// baseline (speedup 1.0000x reference)
#include <cuda_runtime.h>
#include <math.h>

// ---------------- problem constants ----------------
#define Bc    128
#define BUFFc 64
#define STKc  48
#define HISTc 96
#define FCc   128
#define Uc    256
#define NOUTc 82
#define WDIMc 300
#define POSDc 50
#define EDINc 350     // WDIM + POSD
#define CADc  50
#define RDINc 306     // FC + CAD + FC

// ---------------- device scratch (no allocations allowed) ----------------
__device__ float g_buff_emb[Bc * BUFFc * FCc];
__device__ float g_comp_emb[Bc * STKc * 16 * FCc];
__device__ float g_stack_emb[Bc * STKc * FCc];

__device__ float g_zx0[Bc * STKc  * 1024];   // precomputed x-projections (layer0)
__device__ float g_zx1[Bc * BUFFc * 1024];
__device__ float g_zx2[Bc * HISTc * 1024];

__device__ float g_c0[3][Bc * Uc];
__device__ float g_c1[3][Bc * Uc];
__device__ float g_h0[3][2][Bc * Uc];        // double-buffered
__device__ float g_h1[3][2][Bc * Uc];

__device__ __forceinline__ float sigm(float x) {
    return __fdividef(1.0f, 1.0f + __expf(-x));
}
__device__ __forceinline__ float tanh_(float x) {
    return __fdividef(2.0f, 1.0f + __expf(-2.0f * x)) - 1.0f;
}

// ---------------- fused LSTM step: GEMM + gates + masked state update ----------------
// One unit = one (layer, step). Block: 256 threads, tile 32b x 32u (=128 z cols:
// cols {g*256 + u0 + uu}). K = 256 (layer0 h-part) or 512 (layer1 [h0,h1]).
// grid = (32, nunits): blockIdx.x -> 4 b-tiles x 8 u-tiles.
struct SUnit {
    const float* src0;   // K rows [0,256)  source rows (b, 256)
    const float* src1;   // K rows [256,512) source or null
    const float* W;      // (K, 1024)
    const float* zx;     // precomputed x-proj, pre-offset by t*1024 (layer0) or null
    long         zx_bs;  // batch stride (T*1024)
    const float* bias;   // (1024)
    const float* h_in;   // recurrent h (for masked carry)
    float*       c;      // (B,256) in-place
    float*       h_out;  // (B,256)
    const int*   len;
    int t;
    int nkt;             // k-tiles of 32: 8 or 16
};
struct SUnits { SUnit u[6]; };

__global__ void __launch_bounds__(256, 2) lstm_step_kernel(SUnits units) {
    const SUnit U = units.u[blockIdx.y];
    const int tid = threadIdx.x;
    const int bm = blockIdx.x & 3;     // b-tile (32 rows)
    const int bu = blockIdx.x >> 2;    // u-tile (32 u)
    const int b0 = bm * 32;
    const int u0 = bu * 32;

    __shared__ float xs[2][32][33];            // [buf][m][k]
    __shared__ __align__(16) float ws_raw[2 * 32 * 128];   // [buf][k][c]; epilogue overlays zt
#define WS(bf,k,c) ws_raw[(bf) * 4096 + (k) * 128 + (c)]

    const int mi = tid & 7,  ni = tid >> 3;    // thread tile
    const int m0 = mi * 4,   n0t = ni * 4;

    const int xm = tid >> 3;                   // staged b row
    const int xk = (tid & 7) * 4;              // k float4 start
    const int wk = tid >> 5;                   // W k row base (0..7)
    const int wc4 = tid & 31;                  // W float4 col slot
    const int gcol = (wc4 >> 3) * 256 + u0 + (wc4 & 7) * 4;  // global W col

    float acc[4][4];
#pragma unroll
    for (int a = 0; a < 4; a++)
#pragma unroll
        for (int b = 0; b < 4; b++) acc[a][b] = 0.0f;

    // ---- prologue: stage k-tile 0 ----
    {
        float4 xv = *(const float4*)(U.src0 + (b0 + xm) * Uc + xk);
        xs[0][xm][xk + 0] = xv.x; xs[0][xm][xk + 1] = xv.y;
        xs[0][xm][xk + 2] = xv.z; xs[0][xm][xk + 3] = xv.w;
#pragma unroll
        for (int q = 0; q < 4; q++) {
            const int kk = wk + 8 * q;
            *(float4*)&WS(0, kk, wc4 * 4) =
                *(const float4*)(U.W + (size_t)kk * 1024 + gcol);
        }
    }
    __syncthreads();

    int buf = 0;
#pragma unroll 1
    for (int kt = 0; kt < U.nkt; kt++) {
        float4 xv, wv0, wv1, wv2, wv3;
        const bool more = (kt + 1 < U.nkt);
        if (more) {
            const int k0 = (kt + 1) * 32;
            const float* srow = (k0 < 256)
                ? U.src0 + (b0 + xm) * Uc + k0
                : U.src1 + (b0 + xm) * Uc + (k0 - 256);
            xv  = *(const float4*)(srow + xk);
            const int kw = (k0 + wk);
            wv0 = *(const float4*)(U.W + (size_t)(kw +  0) * 1024 + gcol);
            wv1 = *(const float4*)(U.W + (size_t)(kw +  8) * 1024 + gcol);
            wv2 = *(const float4*)(U.W + (size_t)(kw + 16) * 1024 + gcol);
            wv3 = *(const float4*)(U.W + (size_t)(kw + 24) * 1024 + gcol);
        }

        const float (*xsb)[33] = xs[buf];
#pragma unroll
        for (int kk = 0; kk < 32; kk++) {
            const float x0 = xsb[m0 + 0][kk];
            const float x1 = xsb[m0 + 1][kk];
            const float x2 = xsb[m0 + 2][kk];
            const float x3 = xsb[m0 + 3][kk];
            const float4 w = *(const float4*)&WS(buf, kk, n0t);
            acc[0][0] = fmaf(x0, w.x, acc[0][0]);
            acc[0][1] = fmaf(x0, w.y, acc[0][1]);
            acc[0][2] = fmaf(x0, w.z, acc[0][2]);
            acc[0][3] = fmaf(x0, w.w, acc[0][3]);
            acc[1][0] = fmaf(x1, w.x, acc[1][0]);
            acc[1][1] = fmaf(x1, w.y, acc[1][1]);
            acc[1][2] = fmaf(x1, w.z, acc[1][2]);
            acc[1][3] = fmaf(x1, w.w, acc[1][3]);
            acc[2][0] = fmaf(x2, w.x, acc[2][0]);
            acc[2][1] = fmaf(x2, w.y, acc[2][1]);
            acc[2][2] = fmaf(x2, w.z, acc[2][2]);
            acc[2][3] = fmaf(x2, w.w, acc[2][3]);
            acc[3][0] = fmaf(x3, w.x, acc[3][0]);
            acc[3][1] = fmaf(x3, w.y, acc[3][1]);
            acc[3][2] = fmaf(x3, w.z, acc[3][2]);
            acc[3][3] = fmaf(x3, w.w, acc[3][3]);
        }

        if (more) {
            const int nb = buf ^ 1;
            xs[nb][xm][xk + 0] = xv.x; xs[nb][xm][xk + 1] = xv.y;
            xs[nb][xm][xk + 2] = xv.z; xs[nb][xm][xk + 3] = xv.w;
            *(float4*)&WS(nb, wk +  0, wc4 * 4) = wv0;
            *(float4*)&WS(nb, wk +  8, wc4 * 4) = wv1;
            *(float4*)&WS(nb, wk + 16, wc4 * 4) = wv2;
            *(float4*)&WS(nb, wk + 24, wc4 * 4) = wv3;
            __syncthreads();
            buf = nb;
        }
    }

    // ---- epilogue: exchange z through SMEM (overlay on ws), gates, state update ----
    __syncthreads();
    float* zt = ws_raw;                // zt[col][b] stride 33, col in [0,128)
#pragma unroll
    for (int cc = 0; cc < 4; cc++)
#pragma unroll
        for (int a = 0; a < 4; a++)
            zt[(n0t + cc) * 33 + (m0 + a)] = acc[a][cc];
    __syncthreads();

    const int uu = tid & 31;
    const int bq = tid >> 5;
    const int colu = u0 + uu;
    const float bi = U.bias[colu];
    const float bj = U.bias[256 + colu];
    const float bf = U.bias[512 + colu];
    const float bo = U.bias[768 + colu];

#pragma unroll
    for (int q = 0; q < 4; q++) {
        const int bl = bq + 8 * q;
        const int b = b0 + bl;
        const int gidx = b * Uc + colu;
        if (U.t < U.len[b]) {
            float g0 = zt[(  0 + uu) * 33 + bl] + bi;
            float g1 = zt[( 32 + uu) * 33 + bl] + bj;
            float g2 = zt[( 64 + uu) * 33 + bl] + bf;
            float g3 = zt[( 96 + uu) * 33 + bl] + bo;
            if (U.zx) {
                const float* zr = U.zx + (size_t)b * U.zx_bs;
                g0 += zr[colu];
                g1 += zr[256 + colu];
                g2 += zr[512 + colu];
                g3 += zr[768 + colu];
            }
            const float cn = U.c[gidx] * sigm(g2 + 1.0f) + sigm(g0) * tanh_(g1);
            const float hn = tanh_(cn) * sigm(g3);
            U.c[gidx] = cn;
            U.h_out[gidx] = hn;
        } else {
            U.h_out[gidx] = U.h_in[gidx];
        }
    }
#undef WS
}

// ---------------- x-projection precompute: zx = X(rows x Din) @ W(Din x 1024) ----------------
struct XJob { const float* x; const int* ids; const float* tab;
              const float* W; float* zx; int rows, Din; };
struct XJobs { XJob j[3]; };

__global__ void xproj_kernel(XJobs jobs) {
    const XJob J = jobs.j[blockIdx.y];
    const int bm = blockIdx.x % 384;
    const int bn = blockIdx.x / 384;
    const int r0 = bm * 32;
    if (r0 >= J.rows) return;
    const int n0 = bn * 128;

    __shared__ float xs[32][33];
    __shared__ __align__(16) float ws[32][128];
    const int tid = threadIdx.x;
    const int mi = tid & 7, ni = tid >> 3;
    const int m0 = mi * 4, n0t = ni * 4;
    const int xm = tid >> 3, xk = (tid & 7) * 4;
    const int wc = (tid & 31) * 4, wk = tid >> 5;

    float acc[4][4];
#pragma unroll
    for (int a = 0; a < 4; a++)
#pragma unroll
        for (int b = 0; b < 4; b++) acc[a][b] = 0.0f;

    const int r = r0 + xm;
    const float* srow = J.ids ? (J.tab + (size_t)J.ids[r] * J.Din)
                              : (J.x + (size_t)r * J.Din);

    const int nk = (J.Din + 31) >> 5;
    for (int kt = 0; kt < nk; kt++) {
        const int k0 = kt * 32;
        __syncthreads();
#pragma unroll
        for (int j = 0; j < 4; j++) {
            const int k = k0 + xk + j;
            xs[xm][xk + j] = (k < J.Din) ? srow[k] : 0.0f;
        }
#pragma unroll
        for (int q = 0; q < 4; q++) {
            const int kk = wk + 8 * q, k = k0 + kk;
            float4 wv = make_float4(0.f, 0.f, 0.f, 0.f);
            if (k < J.Din)
                wv = *(const float4*)(J.W + (size_t)k * 1024 + n0 + wc);
            *(float4*)&ws[kk][wc] = wv;
        }
        __syncthreads();
#pragma unroll 8
        for (int kk = 0; kk < 32; kk++) {
            const float x0 = xs[m0 + 0][kk];
            const float x1 = xs[m0 + 1][kk];
            const float x2 = xs[m0 + 2][kk];
            const float x3 = xs[m0 + 3][kk];
            const float4 w = *(const float4*)&ws[kk][n0t];
            acc[0][0] = fmaf(x0, w.x, acc[0][0]);
            acc[0][1] = fmaf(x0, w.y, acc[0][1]);
            acc[0][2] = fmaf(x0, w.z, acc[0][2]);
            acc[0][3] = fmaf(x0, w.w, acc[0][3]);
            acc[1][0] = fmaf(x1, w.x, acc[1][0]);
            acc[1][1] = fmaf(x1, w.y, acc[1][1]);
            acc[1][2] = fmaf(x1, w.z, acc[1][2]);
            acc[1][3] = fmaf(x1, w.w, acc[1][3]);
            acc[2][0] = fmaf(x2, w.x, acc[2][0]);
            acc[2][1] = fmaf(x2, w.y, acc[2][1]);
            acc[2][2] = fmaf(x2, w.z, acc[2][2]);
            acc[2][3] = fmaf(x2, w.w, acc[2][3]);
            acc[3][0] = fmaf(x3, w.x, acc[3][0]);
            acc[3][1] = fmaf(x3, w.y, acc[3][1]);
            acc[3][2] = fmaf(x3, w.z, acc[3][2]);
            acc[3][3] = fmaf(x3, w.w, acc[3][3]);
        }
    }
#pragma unroll
    for (int a = 0; a < 4; a++) {
        *(float4*)(J.zx + (size_t)(r0 + m0 + a) * 1024 + n0 + n0t) =
            make_float4(acc[a][0], acc[a][1], acc[a][2], acc[a][3]);
    }
}

// ---------------- embedding: relu([w_emb[id], p_emb[pid]] @ emb_W + b) ----------------
__global__ void embed_kernel(const int* __restrict__ word_ids,
                             const int* __restrict__ pos_ids,
                             const float* __restrict__ w_emb,
                             const float* __restrict__ p_emb,
                             const float* __restrict__ W,
                             const float* __restrict__ bias,
                             float* __restrict__ out,
                             int nrows) {
    __shared__ float xs[8][EDINc];
    __shared__ int wid_s[8], pid_s[8];
    const int r0 = blockIdx.x * 8;
    const int tid = threadIdx.x;

    if (tid < 8) {
        int row = r0 + tid;
        wid_s[tid] = (row < nrows) ? word_ids[row] : 0;
        pid_s[tid] = (row < nrows) ? pos_ids[row] : 0;
    }
    __syncthreads();

    for (int idx = tid; idx < 8 * EDINc; idx += 128) {
        int r = idx / EDINc, k = idx - r * EDINc;
        float v;
        if (k < WDIMc) v = w_emb[wid_s[r] * WDIMc + k];
        else           v = p_emb[pid_s[r] * POSDc + (k - WDIMc)];
        xs[r][k] = v;
    }
    __syncthreads();

    float acc[8];
    const float bj = bias[tid];
#pragma unroll
    for (int r = 0; r < 8; r++) acc[r] = bj;

#pragma unroll 2
    for (int k = 0; k < EDINc; k++) {
        float w = W[k * FCc + tid];
#pragma unroll
        for (int r = 0; r < 8; r++) acc[r] = fmaf(xs[r][k], w, acc[r]);
    }
#pragma unroll
    for (int r = 0; r < 8; r++) {
        int row = r0 + r;
        if (row < nrows) out[row * FCc + tid] = fmaxf(acc[r], 0.0f);
    }
}

// ---------------- compose: recursive tree composition per (b, stk) ----------------
__global__ void compose_kernel(const int* __restrict__ comp_word_id,
                               const float* __restrict__ comp_emb,
                               const int* __restrict__ comp_action_id,
                               const int* __restrict__ comp_action_len,
                               const float* __restrict__ a_emb,
                               const float* __restrict__ rec_W,
                               const float* __restrict__ rec_b,
                               float* __restrict__ stack_emb) {
    const int seq = blockIdx.x;
    const int tid = threadIdx.x;
    __shared__ float vals[8][FCc];
    __shared__ float xbuf[RDINc];
    __shared__ int hid[8], did[8];

    if (tid < 8) {
        hid[tid] = comp_word_id[seq * 16 + 2 * tid];
        did[tid] = comp_word_id[seq * 16 + 2 * tid + 1];
    }
    __syncthreads();

    const float bj = rec_b[tid];
    for (int n = 0; n < 8; n++) {
        int ih = -1, idd = -1;
        for (int m = 0; m < n; m++) {
            if (hid[m] == hid[n]) ih = m;
            if (hid[m] == did[n]) idd = m;
        }
        float he = (ih  >= 0) ? vals[ih][tid]  : comp_emb[(seq * 16 + 2 * n) * FCc + tid];
        float de = (idd >= 0) ? vals[idd][tid] : comp_emb[(seq * 16 + 2 * n + 1) * FCc + tid];
        xbuf[tid] = he;
        xbuf[FCc + CADc + tid] = de;
        if (tid < CADc) xbuf[FCc + tid] = a_emb[comp_action_id[seq * 8 + n] * CADc + tid];
        __syncthreads();

        float acc = bj;
#pragma unroll 2
        for (int k = 0; k < RDINc; k++) acc = fmaf(xbuf[k], rec_W[k * FCc + tid], acc);
        vals[n][tid] = tanhf(acc);
        __syncthreads();
    }

    int al = comp_action_len[seq];
    float outv = (al == 0) ? comp_emb[(seq * 16) * FCc + tid] : vals[al - 1][tid];
    stack_emb[seq * FCc + tid] = outv;
}

// ---------------- output head ----------------
__global__ void final_kernel(const float* __restrict__ hs,
                             const float* __restrict__ hb,
                             const float* __restrict__ ha,
                             const float* __restrict__ fW,
                             const float* __restrict__ fb,
                             float* __restrict__ out) {
    const int b = blockIdx.x;
    const int tid = threadIdx.x;
    __shared__ float hcat[3 * Uc];
    for (int idx = tid; idx < 3 * Uc; idx += 128) {
        float v;
        if (idx < Uc)            v = hs[b * Uc + idx];
        else if (idx < 2 * Uc)   v = hb[b * Uc + idx - Uc];
        else                     v = ha[b * Uc + idx - 2 * Uc];
        hcat[idx] = v;
    }
    __syncthreads();
    if (tid < NOUTc) {
        float acc = fb[tid];
#pragma unroll 2
        for (int k = 0; k < 3 * Uc; k++) acc = fmaf(hcat[k], fW[k * NOUTc + tid], acc);
        out[b * NOUTc + tid] = acc;
    }
}

// ---------------- host driver ----------------
extern "C" void kernel_launch(void* const* d_in, const int* in_sizes, int n_in,
                              void* d_out, int out_size) {
    const int*   buff_word_id   = (const int*)d_in[0];
    const int*   buff_pos_id    = (const int*)d_in[1];
    const int*   comp_word_id   = (const int*)d_in[2];
    const int*   comp_pos_id    = (const int*)d_in[3];
    const int*   comp_action_id = (const int*)d_in[4];
    const int*   comp_action_len= (const int*)d_in[5];
    const int*   history_action_id = (const int*)d_in[6];
    const int*   stack_length   = (const int*)d_in[7];
    const int*   buff_length    = (const int*)d_in[8];
    const int*   history_action_length = (const int*)d_in[9];
    const float* p_emb      = (const float*)d_in[10];
    const float* comp_a_emb = (const float*)d_in[11];
    const float* hist_a_emb = (const float*)d_in[12];
    const float* w_emb      = (const float*)d_in[13];
    const float* emb_W      = (const float*)d_in[14];
    const float* emb_b      = (const float*)d_in[15];
    const float* rec_W      = (const float*)d_in[16];
    const float* rec_b      = (const float*)d_in[17];
    const float* W0s[3] = { (const float*)d_in[18], (const float*)d_in[22], (const float*)d_in[26] };
    const float* b0s[3] = { (const float*)d_in[19], (const float*)d_in[23], (const float*)d_in[27] };
    const float* W1s[3] = { (const float*)d_in[20], (const float*)d_in[24], (const float*)d_in[28] };
    const float* b1s[3] = { (const float*)d_in[21], (const float*)d_in[25], (const float*)d_in[29] };
    const float* fW  = (const float*)d_in[30];
    const float* fb  = (const float*)d_in[31];
    float* out = (float*)d_out;

    float *buff_emb_p, *comp_emb_p, *stack_emb_p;
    float *zx0_p, *zx1_p, *zx2_p;
    float *c0_p, *c1_p, *h0_p, *h1_p;
    cudaGetSymbolAddress((void**)&buff_emb_p,  g_buff_emb);
    cudaGetSymbolAddress((void**)&comp_emb_p,  g_comp_emb);
    cudaGetSymbolAddress((void**)&stack_emb_p, g_stack_emb);
    cudaGetSymbolAddress((void**)&zx0_p, g_zx0);
    cudaGetSymbolAddress((void**)&zx1_p, g_zx1);
    cudaGetSymbolAddress((void**)&zx2_p, g_zx2);
    cudaGetSymbolAddress((void**)&c0_p, g_c0);
    cudaGetSymbolAddress((void**)&c1_p, g_c1);
    cudaGetSymbolAddress((void**)&h0_p, g_h0);
    cudaGetSymbolAddress((void**)&h1_p, g_h1);

    const size_t SB = (size_t)Bc * Uc;

    cudaMemsetAsync(c0_p, 0, 3 * SB * sizeof(float));
    cudaMemsetAsync(c1_p, 0, 3 * SB * sizeof(float));
    cudaMemsetAsync(h0_p, 0, 3 * 2 * SB * sizeof(float));
    cudaMemsetAsync(h1_p, 0, 3 * 2 * SB * sizeof(float));

    // embeddings
    const int nbuff = Bc * BUFFc;
    embed_kernel<<<(nbuff + 7) / 8, 128>>>(buff_word_id, buff_pos_id, w_emb, p_emb,
                                           emb_W, emb_b, buff_emb_p, nbuff);
    const int ncomp = Bc * STKc * 16;
    embed_kernel<<<(ncomp + 7) / 8, 128>>>(comp_word_id, comp_pos_id, w_emb, p_emb,
                                           emb_W, emb_b, comp_emb_p, ncomp);

    // recursive compose -> stack_emb
    compose_kernel<<<Bc * STKc, 128>>>(comp_word_id, comp_emb_p, comp_action_id,
                                       comp_action_len, comp_a_emb, rec_W, rec_b,
                                       stack_emb_p);

    // precompute x-projections for layer0 of all three LSTMs
    {
        XJobs xj;
        xj.j[0] = XJob{ stack_emb_p, nullptr, nullptr, W0s[0], zx0_p, Bc * STKc,  FCc };
        xj.j[1] = XJob{ buff_emb_p,  nullptr, nullptr, W0s[1], zx1_p, Bc * BUFFc, FCc };
        xj.j[2] = XJob{ nullptr, history_action_id, hist_a_emb, W0s[2], zx2_p, Bc * HISTc, 50 };
        xproj_kernel<<<dim3(384 * 8, 3), 256>>>(xj);
    }

    // --- fused pipelined loop: layer0 at t=i, layer1 at t=i-1, one kernel/iter ---
    float* ZXs[3]  = { zx0_p, zx1_p, zx2_p };
    const int DIN0[3] = { FCc, FCc, 50 };
    const int Ts[3]   = { STKc, BUFFc, HISTc };
    const int* LEN[3] = { stack_length, buff_length, history_action_length };

    for (int i = 0; i <= HISTc; i++) {
        SUnits su;
        int n = 0;
        const int pin  = (i + 1) & 1;   // state t=i-1 parity
        const int pout = i & 1;         // state t=i parity
        for (int L = 0; L < 3; L++) {
            float* h0in  = h0_p + (L * 2 + pin)  * SB;
            float* h0out = h0_p + (L * 2 + pout) * SB;
            float* h1in  = h1_p + (L * 2 + pout) * SB;  // state t=i-2 parity = i&1
            float* h1out = h1_p + (L * 2 + pin)  * SB;  // state t=i-1 parity = (i-1)&1
            float* c0L = c0_p + L * SB;
            float* c1L = c1_p + L * SB;
            if (i < Ts[L]) {                  // layer0, t=i, K=256
                su.u[n++] = SUnit{ h0in, nullptr,
                                   W0s[L] + (size_t)DIN0[L] * 1024,
                                   ZXs[L] + (size_t)i * 1024, (long)Ts[L] * 1024,
                                   b0s[L], h0in, c0L, h0out, LEN[L], i, 8 };
            }
            if (i >= 1 && i <= Ts[L]) {       // layer1, t=i-1, K=512 ([h0(t), h1(t-1)])
                su.u[n++] = SUnit{ h0in, h1in,
                                   W1s[L],
                                   nullptr, 0,
                                   b1s[L], h1in, c1L, h1out, LEN[L], i - 1, 16 };
            }
        }
        if (n > 0)
            lstm_step_kernel<<<dim3(32, n), 256>>>(su);
    }

    // output head: final h1 written at i=T (T even) with parity (T-1)&1 = 1
    final_kernel<<<Bc, 128>>>(h1_p + (0 * 2 + 1) * SB,
                              h1_p + (1 * 2 + 1) * SB,
                              h1_p + (2 * 2 + 1) * SB,
                              fW, fb, out);
}

// round 6
// speedup vs baseline: 1.1146x; 1.1146x over previous
#include <cuda_runtime.h>
#include <math.h>

// ---------------- problem constants ----------------
#define Bc    128
#define BUFFc 64
#define STKc  48
#define HISTc 96
#define FCc   128
#define Uc    256
#define NOUTc 82
#define WDIMc 300
#define POSDc 50
#define EDINc 350     // WDIM + POSD
#define CADc  50
#define RDINc 306     // FC + CAD + FC

// ---------------- device scratch (no allocations allowed) ----------------
__device__ float g_buff_emb[Bc * BUFFc * FCc];
__device__ float g_comp_emb[Bc * STKc * 16 * FCc];
__device__ float g_stack_emb[Bc * STKc * FCc];

__device__ float g_zx0[Bc * STKc  * 1024];   // precomputed x-projections (layer0)
__device__ float g_zx1[Bc * BUFFc * 1024];
__device__ float g_zx2[Bc * HISTc * 1024];

__device__ float g_c0[3][Bc * Uc];
__device__ float g_c1[3][Bc * Uc];
__device__ float g_h0[3][2][Bc * Uc];        // double-buffered
__device__ float g_h1[3][2][Bc * Uc];

__device__ __forceinline__ float sigm(float x) {
    return __fdividef(1.0f, 1.0f + __expf(-x));
}
__device__ __forceinline__ float tanh_(float x) {
    return __fdividef(2.0f, 1.0f + __expf(-2.0f * x)) - 1.0f;
}

// ---------------- fused LSTM step: GEMM + gates + masked state update ----------------
// One unit = one (layer, step). Block: 128 threads, tile 32b x 16u (= 64 z cols:
// {g*256 + u0 + uu}). K = 256 (layer0 h-part) or 512 (layer1 [h0, h1]).
// grid = (nunits, 64): blockIdx.y -> 4 b-tiles x 16 u-tiles (unit-major interleave).
#define WSTRIDE 68
struct SUnit {
    const float* src0;   // K rows [0,256)
    const float* src1;   // K rows [256,512) or null
    const float* W;      // (K, 1024)
    const float* zx;     // precomputed x-proj (pre-offset by t*1024) or null
    long         zx_bs;  // batch stride of zx
    const float* bias;   // (1024)
    const float* h_in;   // recurrent h (masked carry)
    float*       c;      // (B,256) in-place
    float*       h_out;  // (B,256)
    const int*   len;
    int t;
    int nkt;             // k-tiles of 32: 8 or 16
};
struct SUnits { SUnit u[6]; };

__global__ void __launch_bounds__(128, 6) lstm_step_kernel(SUnits units) {
    const SUnit U = units.u[blockIdx.x];
    const int by = blockIdx.y;
    const int bm = by & 3;             // b-tile (32 rows)
    const int bu = by >> 2;            // u-tile (16 u)
    const int b0 = bm * 32;
    const int u0 = bu * 16;
    const int tid = threadIdx.x;

    __shared__ float xs[2][32][33];                       // [buf][m][k]
    __shared__ __align__(16) float ws_raw[2 * 32 * WSTRIDE];
#define WS(bf,k,c) ws_raw[(bf) * (32 * WSTRIDE) + (k) * WSTRIDE + (c)]

    const int mi = tid & 7,  ni = tid >> 3;   // thread tile: 4m x 4n
    const int m0 = mi * 4,   n0t = ni * 4;

    const int xm = tid >> 3;                  // x staging rows {xm, xm+16}
    const int xk = (tid & 7) * 4;
    const int wk = tid >> 4;                  // W k rows {wk, +8, +16, +24}
    const int wc4 = tid & 15;                 // 16 float4 col slots (64 cols)
    const int gcol = (wc4 >> 2) * 256 + u0 + (wc4 & 3) * 4;

    const float* srcs[2] = { U.src0, U.src1 };

    float acc[4][4];
#pragma unroll
    for (int a = 0; a < 4; a++)
#pragma unroll
        for (int b = 0; b < 4; b++) acc[a][b] = 0.0f;

    // ---- prologue: stage k-tile 0 (always src0) ----
    {
        float4 xa = *(const float4*)(U.src0 + (b0 + xm) * Uc + xk);
        float4 xb = *(const float4*)(U.src0 + (b0 + xm + 16) * Uc + xk);
        xs[0][xm][xk + 0] = xa.x; xs[0][xm][xk + 1] = xa.y;
        xs[0][xm][xk + 2] = xa.z; xs[0][xm][xk + 3] = xa.w;
        xs[0][xm + 16][xk + 0] = xb.x; xs[0][xm + 16][xk + 1] = xb.y;
        xs[0][xm + 16][xk + 2] = xb.z; xs[0][xm + 16][xk + 3] = xb.w;
#pragma unroll
        for (int q = 0; q < 4; q++) {
            const int kk = wk + 8 * q;
            *(float4*)&WS(0, kk, wc4 * 4) =
                *(const float4*)(U.W + (size_t)kk * 1024 + gcol);
        }
    }
    __syncthreads();

    int buf = 0;
#pragma unroll 1
    for (int kt = 0; kt < U.nkt; kt++) {
        float4 xa, xb, wv0, wv1, wv2, wv3;
        const bool more = (kt + 1 < U.nkt);
        if (more) {
            const int k0 = (kt + 1) * 32;
            const float* sb = srcs[k0 >> 8];
            const int ko = k0 & 255;
            xa = *(const float4*)(sb + (b0 + xm) * Uc + ko + xk);
            xb = *(const float4*)(sb + (b0 + xm + 16) * Uc + ko + xk);
            const float* wrow = U.W + (size_t)(k0 + wk) * 1024 + gcol;
            wv0 = *(const float4*)(wrow);
            wv1 = *(const float4*)(wrow +  8 * 1024);
            wv2 = *(const float4*)(wrow + 16 * 1024);
            wv3 = *(const float4*)(wrow + 24 * 1024);
        }

        const float (*xsb)[33] = xs[buf];
#pragma unroll
        for (int kk = 0; kk < 32; kk++) {
            const float x0 = xsb[m0 + 0][kk];
            const float x1 = xsb[m0 + 1][kk];
            const float x2 = xsb[m0 + 2][kk];
            const float x3 = xsb[m0 + 3][kk];
            const float4 w = *(const float4*)&WS(buf, kk, n0t);
            acc[0][0] = fmaf(x0, w.x, acc[0][0]);
            acc[0][1] = fmaf(x0, w.y, acc[0][1]);
            acc[0][2] = fmaf(x0, w.z, acc[0][2]);
            acc[0][3] = fmaf(x0, w.w, acc[0][3]);
            acc[1][0] = fmaf(x1, w.x, acc[1][0]);
            acc[1][1] = fmaf(x1, w.y, acc[1][1]);
            acc[1][2] = fmaf(x1, w.z, acc[1][2]);
            acc[1][3] = fmaf(x1, w.w, acc[1][3]);
            acc[2][0] = fmaf(x2, w.x, acc[2][0]);
            acc[2][1] = fmaf(x2, w.y, acc[2][1]);
            acc[2][2] = fmaf(x2, w.z, acc[2][2]);
            acc[2][3] = fmaf(x2, w.w, acc[2][3]);
            acc[3][0] = fmaf(x3, w.x, acc[3][0]);
            acc[3][1] = fmaf(x3, w.y, acc[3][1]);
            acc[3][2] = fmaf(x3, w.z, acc[3][2]);
            acc[3][3] = fmaf(x3, w.w, acc[3][3]);
        }

        if (more) {
            const int nb = buf ^ 1;
            xs[nb][xm][xk + 0] = xa.x; xs[nb][xm][xk + 1] = xa.y;
            xs[nb][xm][xk + 2] = xa.z; xs[nb][xm][xk + 3] = xa.w;
            xs[nb][xm + 16][xk + 0] = xb.x; xs[nb][xm + 16][xk + 1] = xb.y;
            xs[nb][xm + 16][xk + 2] = xb.z; xs[nb][xm + 16][xk + 3] = xb.w;
            *(float4*)&WS(nb, wk +  0, wc4 * 4) = wv0;
            *(float4*)&WS(nb, wk +  8, wc4 * 4) = wv1;
            *(float4*)&WS(nb, wk + 16, wc4 * 4) = wv2;
            *(float4*)&WS(nb, wk + 24, wc4 * 4) = wv3;
            __syncthreads();
            buf = nb;
        }
    }

    // ---- epilogue: z exchange through SMEM (overlay ws), gates, state update ----
    __syncthreads();
    float* zt = ws_raw;               // zt[c][b], stride 33, c in [0,64)
#pragma unroll
    for (int cc = 0; cc < 4; cc++)
#pragma unroll
        for (int a = 0; a < 4; a++)
            zt[(n0t + cc) * 33 + (m0 + a)] = acc[a][cc];
    __syncthreads();

    const int uu = tid & 15;
    const int bq = tid >> 4;          // 0..7
    const int colu = u0 + uu;
    const float bi = U.bias[colu];
    const float bj = U.bias[256 + colu];
    const float bf = U.bias[512 + colu];
    const float bo = U.bias[768 + colu];

#pragma unroll
    for (int q = 0; q < 4; q++) {
        const int bl = bq + 8 * q;
        const int b = b0 + bl;
        const int gidx = b * Uc + colu;
        if (U.t < U.len[b]) {
            float g0 = zt[( 0 + uu) * 33 + bl] + bi;
            float g1 = zt[(16 + uu) * 33 + bl] + bj;
            float g2 = zt[(32 + uu) * 33 + bl] + bf;
            float g3 = zt[(48 + uu) * 33 + bl] + bo;
            if (U.zx) {
                const float* zr = U.zx + (size_t)b * U.zx_bs;
                g0 += zr[colu];
                g1 += zr[256 + colu];
                g2 += zr[512 + colu];
                g3 += zr[768 + colu];
            }
            const float cn = U.c[gidx] * sigm(g2 + 1.0f) + sigm(g0) * tanh_(g1);
            const float hn = tanh_(cn) * sigm(g3);
            U.c[gidx] = cn;
            U.h_out[gidx] = hn;
        } else {
            U.h_out[gidx] = U.h_in[gidx];
        }
    }
#undef WS
}

// ---------------- x-projection precompute: zx = X(rows x Din) @ W(Din x 1024) ----------------
struct XJob { const float* x; const int* ids; const float* tab;
              const float* W; float* zx; int rows, Din; };
struct XJobs { XJob j[3]; };

__global__ void xproj_kernel(XJobs jobs) {
    const XJob J = jobs.j[blockIdx.y];
    const int bm = blockIdx.x % 384;
    const int bn = blockIdx.x / 384;
    const int r0 = bm * 32;
    if (r0 >= J.rows) return;
    const int n0 = bn * 128;

    __shared__ float xs[32][33];
    __shared__ __align__(16) float ws[32][128];
    const int tid = threadIdx.x;
    const int mi = tid & 7, ni = tid >> 3;
    const int m0 = mi * 4, n0t = ni * 4;
    const int xm = tid >> 3, xk = (tid & 7) * 4;
    const int wc = (tid & 31) * 4, wk = tid >> 5;

    float acc[4][4];
#pragma unroll
    for (int a = 0; a < 4; a++)
#pragma unroll
        for (int b = 0; b < 4; b++) acc[a][b] = 0.0f;

    const int r = r0 + xm;
    const float* srow = J.ids ? (J.tab + (size_t)J.ids[r] * J.Din)
                              : (J.x + (size_t)r * J.Din);

    const int nk = (J.Din + 31) >> 5;
    for (int kt = 0; kt < nk; kt++) {
        const int k0 = kt * 32;
        __syncthreads();
#pragma unroll
        for (int j = 0; j < 4; j++) {
            const int k = k0 + xk + j;
            xs[xm][xk + j] = (k < J.Din) ? srow[k] : 0.0f;
        }
#pragma unroll
        for (int q = 0; q < 4; q++) {
            const int kk = wk + 8 * q, k = k0 + kk;
            float4 wv = make_float4(0.f, 0.f, 0.f, 0.f);
            if (k < J.Din)
                wv = *(const float4*)(J.W + (size_t)k * 1024 + n0 + wc);
            *(float4*)&ws[kk][wc] = wv;
        }
        __syncthreads();
#pragma unroll 8
        for (int kk = 0; kk < 32; kk++) {
            const float x0 = xs[m0 + 0][kk];
            const float x1 = xs[m0 + 1][kk];
            const float x2 = xs[m0 + 2][kk];
            const float x3 = xs[m0 + 3][kk];
            const float4 w = *(const float4*)&ws[kk][n0t];
            acc[0][0] = fmaf(x0, w.x, acc[0][0]);
            acc[0][1] = fmaf(x0, w.y, acc[0][1]);
            acc[0][2] = fmaf(x0, w.z, acc[0][2]);
            acc[0][3] = fmaf(x0, w.w, acc[0][3]);
            acc[1][0] = fmaf(x1, w.x, acc[1][0]);
            acc[1][1] = fmaf(x1, w.y, acc[1][1]);
            acc[1][2] = fmaf(x1, w.z, acc[1][2]);
            acc[1][3] = fmaf(x1, w.w, acc[1][3]);
            acc[2][0] = fmaf(x2, w.x, acc[2][0]);
            acc[2][1] = fmaf(x2, w.y, acc[2][1]);
            acc[2][2] = fmaf(x2, w.z, acc[2][2]);
            acc[2][3] = fmaf(x2, w.w, acc[2][3]);
            acc[3][0] = fmaf(x3, w.x, acc[3][0]);
            acc[3][1] = fmaf(x3, w.y, acc[3][1]);
            acc[3][2] = fmaf(x3, w.z, acc[3][2]);
            acc[3][3] = fmaf(x3, w.w, acc[3][3]);
        }
    }
#pragma unroll
    for (int a = 0; a < 4; a++) {
        *(float4*)(J.zx + (size_t)(r0 + m0 + a) * 1024 + n0 + n0t) =
            make_float4(acc[a][0], acc[a][1], acc[a][2], acc[a][3]);
    }
}

// ---------------- embedding: relu([w_emb[id], p_emb[pid]] @ emb_W + b) ----------------
__global__ void embed_kernel(const int* __restrict__ word_ids,
                             const int* __restrict__ pos_ids,
                             const float* __restrict__ w_emb,
                             const float* __restrict__ p_emb,
                             const float* __restrict__ W,
                             const float* __restrict__ bias,
                             float* __restrict__ out,
                             int nrows) {
    __shared__ float xs[8][EDINc];
    __shared__ int wid_s[8], pid_s[8];
    const int r0 = blockIdx.x * 8;
    const int tid = threadIdx.x;

    if (tid < 8) {
        int row = r0 + tid;
        wid_s[tid] = (row < nrows) ? word_ids[row] : 0;
        pid_s[tid] = (row < nrows) ? pos_ids[row] : 0;
    }
    __syncthreads();

    for (int idx = tid; idx < 8 * EDINc; idx += 128) {
        int r = idx / EDINc, k = idx - r * EDINc;
        float v;
        if (k < WDIMc) v = w_emb[wid_s[r] * WDIMc + k];
        else           v = p_emb[pid_s[r] * POSDc + (k - WDIMc)];
        xs[r][k] = v;
    }
    __syncthreads();

    float acc[8];
    const float bj = bias[tid];
#pragma unroll
    for (int r = 0; r < 8; r++) acc[r] = bj;

#pragma unroll 2
    for (int k = 0; k < EDINc; k++) {
        float w = W[k * FCc + tid];
#pragma unroll
        for (int r = 0; r < 8; r++) acc[r] = fmaf(xs[r][k], w, acc[r]);
    }
#pragma unroll
    for (int r = 0; r < 8; r++) {
        int row = r0 + r;
        if (row < nrows) out[row * FCc + tid] = fmaxf(acc[r], 0.0f);
    }
}

// ---------------- compose: recursive tree composition per (b, stk) ----------------
__global__ void compose_kernel(const int* __restrict__ comp_word_id,
                               const float* __restrict__ comp_emb,
                               const int* __restrict__ comp_action_id,
                               const int* __restrict__ comp_action_len,
                               const float* __restrict__ a_emb,
                               const float* __restrict__ rec_W,
                               const float* __restrict__ rec_b,
                               float* __restrict__ stack_emb) {
    const int seq = blockIdx.x;
    const int tid = threadIdx.x;
    __shared__ float vals[8][FCc];
    __shared__ float xbuf[RDINc];
    __shared__ int hid[8], did[8];

    if (tid < 8) {
        hid[tid] = comp_word_id[seq * 16 + 2 * tid];
        did[tid] = comp_word_id[seq * 16 + 2 * tid + 1];
    }
    __syncthreads();

    const float bj = rec_b[tid];
    for (int n = 0; n < 8; n++) {
        int ih = -1, idd = -1;
        for (int m = 0; m < n; m++) {
            if (hid[m] == hid[n]) ih = m;
            if (hid[m] == did[n]) idd = m;
        }
        float he = (ih  >= 0) ? vals[ih][tid]  : comp_emb[(seq * 16 + 2 * n) * FCc + tid];
        float de = (idd >= 0) ? vals[idd][tid] : comp_emb[(seq * 16 + 2 * n + 1) * FCc + tid];
        xbuf[tid] = he;
        xbuf[FCc + CADc + tid] = de;
        if (tid < CADc) xbuf[FCc + tid] = a_emb[comp_action_id[seq * 8 + n] * CADc + tid];
        __syncthreads();

        float acc = bj;
#pragma unroll 2
        for (int k = 0; k < RDINc; k++) acc = fmaf(xbuf[k], rec_W[k * FCc + tid], acc);
        vals[n][tid] = tanhf(acc);
        __syncthreads();
    }

    int al = comp_action_len[seq];
    float outv = (al == 0) ? comp_emb[(seq * 16) * FCc + tid] : vals[al - 1][tid];
    stack_emb[seq * FCc + tid] = outv;
}

// ---------------- output head ----------------
__global__ void final_kernel(const float* __restrict__ hs,
                             const float* __restrict__ hb,
                             const float* __restrict__ ha,
                             const float* __restrict__ fW,
                             const float* __restrict__ fb,
                             float* __restrict__ out) {
    const int b = blockIdx.x;
    const int tid = threadIdx.x;
    __shared__ float hcat[3 * Uc];
    for (int idx = tid; idx < 3 * Uc; idx += 128) {
        float v;
        if (idx < Uc)            v = hs[b * Uc + idx];
        else if (idx < 2 * Uc)   v = hb[b * Uc + idx - Uc];
        else                     v = ha[b * Uc + idx - 2 * Uc];
        hcat[idx] = v;
    }
    __syncthreads();
    if (tid < NOUTc) {
        float acc = fb[tid];
#pragma unroll 2
        for (int k = 0; k < 3 * Uc; k++) acc = fmaf(hcat[k], fW[k * NOUTc + tid], acc);
        out[b * NOUTc + tid] = acc;
    }
}

// ---------------- host driver ----------------
extern "C" void kernel_launch(void* const* d_in, const int* in_sizes, int n_in,
                              void* d_out, int out_size) {
    const int*   buff_word_id   = (const int*)d_in[0];
    const int*   buff_pos_id    = (const int*)d_in[1];
    const int*   comp_word_id   = (const int*)d_in[2];
    const int*   comp_pos_id    = (const int*)d_in[3];
    const int*   comp_action_id = (const int*)d_in[4];
    const int*   comp_action_len= (const int*)d_in[5];
    const int*   history_action_id = (const int*)d_in[6];
    const int*   stack_length   = (const int*)d_in[7];
    const int*   buff_length    = (const int*)d_in[8];
    const int*   history_action_length = (const int*)d_in[9];
    const float* p_emb      = (const float*)d_in[10];
    const float* comp_a_emb = (const float*)d_in[11];
    const float* hist_a_emb = (const float*)d_in[12];
    const float* w_emb      = (const float*)d_in[13];
    const float* emb_W      = (const float*)d_in[14];
    const float* emb_b      = (const float*)d_in[15];
    const float* rec_W      = (const float*)d_in[16];
    const float* rec_b      = (const float*)d_in[17];
    const float* W0s[3] = { (const float*)d_in[18], (const float*)d_in[22], (const float*)d_in[26] };
    const float* b0s[3] = { (const float*)d_in[19], (const float*)d_in[23], (const float*)d_in[27] };
    const float* W1s[3] = { (const float*)d_in[20], (const float*)d_in[24], (const float*)d_in[28] };
    const float* b1s[3] = { (const float*)d_in[21], (const float*)d_in[25], (const float*)d_in[29] };
    const float* fW  = (const float*)d_in[30];
    const float* fb  = (const float*)d_in[31];
    float* out = (float*)d_out;

    float *buff_emb_p, *comp_emb_p, *stack_emb_p;
    float *zx0_p, *zx1_p, *zx2_p;
    float *c0_p, *c1_p, *h0_p, *h1_p;
    cudaGetSymbolAddress((void**)&buff_emb_p,  g_buff_emb);
    cudaGetSymbolAddress((void**)&comp_emb_p,  g_comp_emb);
    cudaGetSymbolAddress((void**)&stack_emb_p, g_stack_emb);
    cudaGetSymbolAddress((void**)&zx0_p, g_zx0);
    cudaGetSymbolAddress((void**)&zx1_p, g_zx1);
    cudaGetSymbolAddress((void**)&zx2_p, g_zx2);
    cudaGetSymbolAddress((void**)&c0_p, g_c0);
    cudaGetSymbolAddress((void**)&c1_p, g_c1);
    cudaGetSymbolAddress((void**)&h0_p, g_h0);
    cudaGetSymbolAddress((void**)&h1_p, g_h1);

    const size_t SB = (size_t)Bc * Uc;

    cudaMemsetAsync(c0_p, 0, 3 * SB * sizeof(float));
    cudaMemsetAsync(c1_p, 0, 3 * SB * sizeof(float));
    cudaMemsetAsync(h0_p, 0, 3 * 2 * SB * sizeof(float));
    cudaMemsetAsync(h1_p, 0, 3 * 2 * SB * sizeof(float));

    // embeddings
    const int nbuff = Bc * BUFFc;
    embed_kernel<<<(nbuff + 7) / 8, 128>>>(buff_word_id, buff_pos_id, w_emb, p_emb,
                                           emb_W, emb_b, buff_emb_p, nbuff);
    const int ncomp = Bc * STKc * 16;
    embed_kernel<<<(ncomp + 7) / 8, 128>>>(comp_word_id, comp_pos_id, w_emb, p_emb,
                                           emb_W, emb_b, comp_emb_p, ncomp);

    // recursive compose -> stack_emb
    compose_kernel<<<Bc * STKc, 128>>>(comp_word_id, comp_emb_p, comp_action_id,
                                       comp_action_len, comp_a_emb, rec_W, rec_b,
                                       stack_emb_p);

    // precompute x-projections for layer0 of all three LSTMs
    {
        XJobs xj;
        xj.j[0] = XJob{ stack_emb_p, nullptr, nullptr, W0s[0], zx0_p, Bc * STKc,  FCc };
        xj.j[1] = XJob{ buff_emb_p,  nullptr, nullptr, W0s[1], zx1_p, Bc * BUFFc, FCc };
        xj.j[2] = XJob{ nullptr, history_action_id, hist_a_emb, W0s[2], zx2_p, Bc * HISTc, 50 };
        xproj_kernel<<<dim3(384 * 8, 3), 256>>>(xj);
    }

    // --- fused pipelined loop: layer0 at t=i, layer1 at t=i-1, one kernel/iter ---
    float* ZXs[3]  = { zx0_p, zx1_p, zx2_p };
    const int DIN0[3] = { FCc, FCc, 50 };
    const int Ts[3]   = { STKc, BUFFc, HISTc };
    const int* LEN[3] = { stack_length, buff_length, history_action_length };

    for (int i = 0; i <= HISTc; i++) {
        SUnits su;
        int n = 0;
        const int pin  = (i + 1) & 1;   // state t=i-1 parity
        const int pout = i & 1;         // state t=i parity
        for (int L = 0; L < 3; L++) {
            float* h0in  = h0_p + (L * 2 + pin)  * SB;
            float* h0out = h0_p + (L * 2 + pout) * SB;
            float* h1in  = h1_p + (L * 2 + pout) * SB;  // state t=i-2
            float* h1out = h1_p + (L * 2 + pin)  * SB;  // state t=i-1
            float* c0L = c0_p + L * SB;
            float* c1L = c1_p + L * SB;
            if (i < Ts[L]) {                  // layer0, t=i, K=256 (h-part only)
                su.u[n++] = SUnit{ h0in, h0in,
                                   W0s[L] + (size_t)DIN0[L] * 1024,
                                   ZXs[L] + (size_t)i * 1024, (long)Ts[L] * 1024,
                                   b0s[L], h0in, c0L, h0out, LEN[L], i, 8 };
            }
            if (i >= 1 && i <= Ts[L]) {       // layer1, t=i-1, K=512 ([h0(t), h1(t-1)])
                su.u[n++] = SUnit{ h0in, h1in,
                                   W1s[L],
                                   nullptr, 0,
                                   b1s[L], h1in, c1L, h1out, LEN[L], i - 1, 16 };
            }
        }
        if (n > 0)
            lstm_step_kernel<<<dim3(n, 64), 128>>>(su);
    }

    // output head: final h1 written at i=T (T even) with parity 1
    final_kernel<<<Bc, 128>>>(h1_p + (0 * 2 + 1) * SB,
                              h1_p + (1 * 2 + 1) * SB,
                              h1_p + (2 * 2 + 1) * SB,
                              fW, fb, out);
}

// round 7
// speedup vs baseline: 1.3615x; 1.2216x over previous
#include <cuda_runtime.h>
#include <math.h>

// ---------------- problem constants ----------------
#define Bc    128
#define BUFFc 64
#define STKc  48
#define HISTc 96
#define FCc   128
#define Uc    256
#define NOUTc 82
#define WDIMc 300
#define POSDc 50
#define EDINc 350
#define CADc  50
#define RDINc 306

// ---------------- device scratch ----------------
__device__ float g_buff_emb[Bc * BUFFc * FCc];
__device__ float g_comp_emb[Bc * STKc * 16 * FCc];
__device__ float g_stack_emb[Bc * STKc * FCc];

__device__ float g_zx0[Bc * STKc  * 1024];
__device__ float g_zx1[Bc * BUFFc * 1024];
__device__ float g_zx2[Bc * HISTc * 1024];

__device__ float g_p [3][2][Bc * 1024];      // layer1 h0-partials, double-buffered
__device__ float g_c0[3][Bc * Uc];
__device__ float g_c1[3][Bc * Uc];
__device__ float g_h0[3][2][Bc * Uc];
__device__ float g_h1[3][2][Bc * Uc];

__device__ __forceinline__ float sigm(float x) {
    return __fdividef(1.0f, 1.0f + __expf(-x));
}
__device__ __forceinline__ float tanh_(float x) {
    return __fdividef(2.0f, 1.0f + __expf(-2.0f * x)) - 1.0f;
}

// ---------------- uniform K=256 LSTM unit: GEMM (+ gates / or store partial) ----------------
// Block: 256 threads, tile 32b x 128 z-cols (gate-interleaved: 32 u x 4 gates).
// grid = (32, nunits). mode 0: store z to p_out. mode 1: gates + masked state update.
struct SUnit {
    const float* src;    // (128,256) h source
    const float* W;      // K=256 slab, row stride 1024
    const float* extra;  // zx (pre-offset by t) or p partial; null in mode 0
    long  extra_bs;      // batch stride of extra
    const float* bias;
    const float* h_in;
    float* c;
    float* h_out;
    float* p_out;        // mode 0 target
    const int* len;
    int t;
    int mode;
};
struct SUnits { SUnit u[9]; };

__global__ void __launch_bounds__(256, 2) lstm_unit_kernel(SUnits units) {
    const SUnit U = units.u[blockIdx.y];
    const int tid = threadIdx.x;
    const int bm = blockIdx.x & 3;     // 4 b-tiles of 32
    const int bu = blockIdx.x >> 2;    // 8 u-tiles of 32
    const int b0 = bm * 32;
    const int u0 = bu * 32;

    __shared__ float xs[2][32][33];
    __shared__ __align__(16) float ws_raw[2 * 32 * 128];
#define WS(bf,k,c) ws_raw[(bf) * 4096 + (k) * 128 + (c)]

    const int mi = tid & 7,  ni = tid >> 3;   // thread tile 4m x 4n
    const int m0 = mi * 4,   n0t = ni * 4;

    const int xm = tid >> 3;                  // x staging: row
    const int xk = (tid & 7) * 4;             // x staging: k float4
    const int wk = tid >> 5;                  // W staging: k rows {wk,+8,+16,+24}
    const int wc4 = tid & 31;                 // W staging: float4 col slot
    const int gcol = (wc4 >> 3) * 256 + u0 + (wc4 & 7) * 4;

    float acc[4][4];
#pragma unroll
    for (int a = 0; a < 4; a++)
#pragma unroll
        for (int b = 0; b < 4; b++) acc[a][b] = 0.0f;

    const float* srow = U.src + (b0 + xm) * Uc;

    // prologue: stage k-tile 0
    {
        float4 xv = *(const float4*)(srow + xk);
        xs[0][xm][xk + 0] = xv.x; xs[0][xm][xk + 1] = xv.y;
        xs[0][xm][xk + 2] = xv.z; xs[0][xm][xk + 3] = xv.w;
#pragma unroll
        for (int q = 0; q < 4; q++) {
            const int kk = wk + 8 * q;
            *(float4*)&WS(0, kk, wc4 * 4) =
                *(const float4*)(U.W + (size_t)kk * 1024 + gcol);
        }
    }
    __syncthreads();

    int buf = 0;
#pragma unroll 1
    for (int kt = 0; kt < 8; kt++) {
        float4 xv, wv0, wv1, wv2, wv3;
        const bool more = (kt < 7);
        if (more) {
            const int k0 = (kt + 1) * 32;
            xv = *(const float4*)(srow + k0 + xk);
            const float* wrow = U.W + (size_t)(k0 + wk) * 1024 + gcol;
            wv0 = *(const float4*)(wrow);
            wv1 = *(const float4*)(wrow +  8 * 1024);
            wv2 = *(const float4*)(wrow + 16 * 1024);
            wv3 = *(const float4*)(wrow + 24 * 1024);
        }

        const float (*xsb)[33] = xs[buf];
#pragma unroll
        for (int kk = 0; kk < 32; kk++) {
            const float x0 = xsb[m0 + 0][kk];
            const float x1 = xsb[m0 + 1][kk];
            const float x2 = xsb[m0 + 2][kk];
            const float x3 = xsb[m0 + 3][kk];
            const float4 w = *(const float4*)&WS(buf, kk, n0t);
            acc[0][0] = fmaf(x0, w.x, acc[0][0]);
            acc[0][1] = fmaf(x0, w.y, acc[0][1]);
            acc[0][2] = fmaf(x0, w.z, acc[0][2]);
            acc[0][3] = fmaf(x0, w.w, acc[0][3]);
            acc[1][0] = fmaf(x1, w.x, acc[1][0]);
            acc[1][1] = fmaf(x1, w.y, acc[1][1]);
            acc[1][2] = fmaf(x1, w.z, acc[1][2]);
            acc[1][3] = fmaf(x1, w.w, acc[1][3]);
            acc[2][0] = fmaf(x2, w.x, acc[2][0]);
            acc[2][1] = fmaf(x2, w.y, acc[2][1]);
            acc[2][2] = fmaf(x2, w.z, acc[2][2]);
            acc[2][3] = fmaf(x2, w.w, acc[2][3]);
            acc[3][0] = fmaf(x3, w.x, acc[3][0]);
            acc[3][1] = fmaf(x3, w.y, acc[3][1]);
            acc[3][2] = fmaf(x3, w.z, acc[3][2]);
            acc[3][3] = fmaf(x3, w.w, acc[3][3]);
        }

        if (more) {
            const int nb = buf ^ 1;
            xs[nb][xm][xk + 0] = xv.x; xs[nb][xm][xk + 1] = xv.y;
            xs[nb][xm][xk + 2] = xv.z; xs[nb][xm][xk + 3] = xv.w;
            *(float4*)&WS(nb, wk +  0, wc4 * 4) = wv0;
            *(float4*)&WS(nb, wk +  8, wc4 * 4) = wv1;
            *(float4*)&WS(nb, wk + 16, wc4 * 4) = wv2;
            *(float4*)&WS(nb, wk + 24, wc4 * 4) = wv3;
            __syncthreads();
            buf = nb;
        }
    }

    if (U.mode == 0) {
        // store partial z to p_out (gate-interleaved local cols -> global cols)
        const int gcolS = (n0t >> 5) * 256 + u0 + (n0t & 31);
#pragma unroll
        for (int a = 0; a < 4; a++) {
            *(float4*)(U.p_out + (size_t)(b0 + m0 + a) * 1024 + gcolS) =
                make_float4(acc[a][0], acc[a][1], acc[a][2], acc[a][3]);
        }
        return;
    }

    // gates epilogue: exchange z via SMEM overlay
    __syncthreads();
    float* zt = ws_raw;                 // zt[c][b], stride 33, c in [0,128)
#pragma unroll
    for (int cc = 0; cc < 4; cc++)
#pragma unroll
        for (int a = 0; a < 4; a++)
            zt[(n0t + cc) * 33 + (m0 + a)] = acc[a][cc];
    __syncthreads();

    const int uu = tid & 31;
    const int bq = tid >> 5;
    const int colu = u0 + uu;
    const float bi = U.bias[colu];
    const float bj = U.bias[256 + colu];
    const float bf = U.bias[512 + colu];
    const float bo = U.bias[768 + colu];

#pragma unroll
    for (int q = 0; q < 4; q++) {
        const int bl = bq + 8 * q;
        const int b = b0 + bl;
        const int gidx = b * Uc + colu;
        if (U.t < U.len[b]) {
            const float* er = U.extra + (size_t)b * U.extra_bs;
            float g0 = zt[(  0 + uu) * 33 + bl] + bi + er[colu];
            float g1 = zt[( 32 + uu) * 33 + bl] + bj + er[256 + colu];
            float g2 = zt[( 64 + uu) * 33 + bl] + bf + er[512 + colu];
            float g3 = zt[( 96 + uu) * 33 + bl] + bo + er[768 + colu];
            const float cn = U.c[gidx] * sigm(g2 + 1.0f) + sigm(g0) * tanh_(g1);
            const float hn = tanh_(cn) * sigm(g3);
            U.c[gidx] = cn;
            U.h_out[gidx] = hn;
        } else {
            U.h_out[gidx] = U.h_in[gidx];
        }
    }
#undef WS
}

// ---------------- x-projection precompute ----------------
struct XJob { const float* x; const int* ids; const float* tab;
              const float* W; float* zx; int rows, Din; };
struct XJobs { XJob j[3]; };

__global__ void xproj_kernel(XJobs jobs) {
    const XJob J = jobs.j[blockIdx.y];
    const int bm = blockIdx.x % 384;
    const int bn = blockIdx.x / 384;
    const int r0 = bm * 32;
    if (r0 >= J.rows) return;
    const int n0 = bn * 128;

    __shared__ float xs[32][33];
    __shared__ __align__(16) float ws[32][128];
    const int tid = threadIdx.x;
    const int mi = tid & 7, ni = tid >> 3;
    const int m0 = mi * 4, n0t = ni * 4;
    const int xm = tid >> 3, xk = (tid & 7) * 4;
    const int wc = (tid & 31) * 4, wk = tid >> 5;

    float acc[4][4];
#pragma unroll
    for (int a = 0; a < 4; a++)
#pragma unroll
        for (int b = 0; b < 4; b++) acc[a][b] = 0.0f;

    const int r = r0 + xm;
    const float* srow = J.ids ? (J.tab + (size_t)J.ids[r] * J.Din)
                              : (J.x + (size_t)r * J.Din);

    const int nk = (J.Din + 31) >> 5;
    for (int kt = 0; kt < nk; kt++) {
        const int k0 = kt * 32;
        __syncthreads();
#pragma unroll
        for (int j = 0; j < 4; j++) {
            const int k = k0 + xk + j;
            xs[xm][xk + j] = (k < J.Din) ? srow[k] : 0.0f;
        }
#pragma unroll
        for (int q = 0; q < 4; q++) {
            const int kk = wk + 8 * q, k = k0 + kk;
            float4 wv = make_float4(0.f, 0.f, 0.f, 0.f);
            if (k < J.Din)
                wv = *(const float4*)(J.W + (size_t)k * 1024 + n0 + wc);
            *(float4*)&ws[kk][wc] = wv;
        }
        __syncthreads();
#pragma unroll 8
        for (int kk = 0; kk < 32; kk++) {
            const float x0 = xs[m0 + 0][kk];
            const float x1 = xs[m0 + 1][kk];
            const float x2 = xs[m0 + 2][kk];
            const float x3 = xs[m0 + 3][kk];
            const float4 w = *(const float4*)&ws[kk][n0t];
            acc[0][0] = fmaf(x0, w.x, acc[0][0]);
            acc[0][1] = fmaf(x0, w.y, acc[0][1]);
            acc[0][2] = fmaf(x0, w.z, acc[0][2]);
            acc[0][3] = fmaf(x0, w.w, acc[0][3]);
            acc[1][0] = fmaf(x1, w.x, acc[1][0]);
            acc[1][1] = fmaf(x1, w.y, acc[1][1]);
            acc[1][2] = fmaf(x1, w.z, acc[1][2]);
            acc[1][3] = fmaf(x1, w.w, acc[1][3]);
            acc[2][0] = fmaf(x2, w.x, acc[2][0]);
            acc[2][1] = fmaf(x2, w.y, acc[2][1]);
            acc[2][2] = fmaf(x2, w.z, acc[2][2]);
            acc[2][3] = fmaf(x2, w.w, acc[2][3]);
            acc[3][0] = fmaf(x3, w.x, acc[3][0]);
            acc[3][1] = fmaf(x3, w.y, acc[3][1]);
            acc[3][2] = fmaf(x3, w.z, acc[3][2]);
            acc[3][3] = fmaf(x3, w.w, acc[3][3]);
        }
    }
#pragma unroll
    for (int a = 0; a < 4; a++) {
        *(float4*)(J.zx + (size_t)(r0 + m0 + a) * 1024 + n0 + n0t) =
            make_float4(acc[a][0], acc[a][1], acc[a][2], acc[a][3]);
    }
}

// ---------------- embedding ----------------
__global__ void embed_kernel(const int* __restrict__ word_ids,
                             const int* __restrict__ pos_ids,
                             const float* __restrict__ w_emb,
                             const float* __restrict__ p_emb,
                             const float* __restrict__ W,
                             const float* __restrict__ bias,
                             float* __restrict__ out,
                             int nrows) {
    __shared__ float xs[8][EDINc];
    __shared__ int wid_s[8], pid_s[8];
    const int r0 = blockIdx.x * 8;
    const int tid = threadIdx.x;

    if (tid < 8) {
        int row = r0 + tid;
        wid_s[tid] = (row < nrows) ? word_ids[row] : 0;
        pid_s[tid] = (row < nrows) ? pos_ids[row] : 0;
    }
    __syncthreads();

    for (int idx = tid; idx < 8 * EDINc; idx += 128) {
        int r = idx / EDINc, k = idx - r * EDINc;
        float v;
        if (k < WDIMc) v = w_emb[wid_s[r] * WDIMc + k];
        else           v = p_emb[pid_s[r] * POSDc + (k - WDIMc)];
        xs[r][k] = v;
    }
    __syncthreads();

    float acc[8];
    const float bj = bias[tid];
#pragma unroll
    for (int r = 0; r < 8; r++) acc[r] = bj;

#pragma unroll 2
    for (int k = 0; k < EDINc; k++) {
        float w = W[k * FCc + tid];
#pragma unroll
        for (int r = 0; r < 8; r++) acc[r] = fmaf(xs[r][k], w, acc[r]);
    }
#pragma unroll
    for (int r = 0; r < 8; r++) {
        int row = r0 + r;
        if (row < nrows) out[row * FCc + tid] = fmaxf(acc[r], 0.0f);
    }
}

// ---------------- compose ----------------
__global__ void compose_kernel(const int* __restrict__ comp_word_id,
                               const float* __restrict__ comp_emb,
                               const int* __restrict__ comp_action_id,
                               const int* __restrict__ comp_action_len,
                               const float* __restrict__ a_emb,
                               const float* __restrict__ rec_W,
                               const float* __restrict__ rec_b,
                               float* __restrict__ stack_emb) {
    const int seq = blockIdx.x;
    const int tid = threadIdx.x;
    __shared__ float vals[8][FCc];
    __shared__ float xbuf[RDINc];
    __shared__ int hid[8], did[8];

    if (tid < 8) {
        hid[tid] = comp_word_id[seq * 16 + 2 * tid];
        did[tid] = comp_word_id[seq * 16 + 2 * tid + 1];
    }
    __syncthreads();

    const float bj = rec_b[tid];
    for (int n = 0; n < 8; n++) {
        int ih = -1, idd = -1;
        for (int m = 0; m < n; m++) {
            if (hid[m] == hid[n]) ih = m;
            if (hid[m] == did[n]) idd = m;
        }
        float he = (ih  >= 0) ? vals[ih][tid]  : comp_emb[(seq * 16 + 2 * n) * FCc + tid];
        float de = (idd >= 0) ? vals[idd][tid] : comp_emb[(seq * 16 + 2 * n + 1) * FCc + tid];
        xbuf[tid] = he;
        xbuf[FCc + CADc + tid] = de;
        if (tid < CADc) xbuf[FCc + tid] = a_emb[comp_action_id[seq * 8 + n] * CADc + tid];
        __syncthreads();

        float acc = bj;
#pragma unroll 2
        for (int k = 0; k < RDINc; k++) acc = fmaf(xbuf[k], rec_W[k * FCc + tid], acc);
        vals[n][tid] = tanhf(acc);
        __syncthreads();
    }

    int al = comp_action_len[seq];
    float outv = (al == 0) ? comp_emb[(seq * 16) * FCc + tid] : vals[al - 1][tid];
    stack_emb[seq * FCc + tid] = outv;
}

// ---------------- output head ----------------
__global__ void final_kernel(const float* __restrict__ hs,
                             const float* __restrict__ hb,
                             const float* __restrict__ ha,
                             const float* __restrict__ fW,
                             const float* __restrict__ fb,
                             float* __restrict__ out) {
    const int b = blockIdx.x;
    const int tid = threadIdx.x;
    __shared__ float hcat[3 * Uc];
    for (int idx = tid; idx < 3 * Uc; idx += 128) {
        float v;
        if (idx < Uc)            v = hs[b * Uc + idx];
        else if (idx < 2 * Uc)   v = hb[b * Uc + idx - Uc];
        else                     v = ha[b * Uc + idx - 2 * Uc];
        hcat[idx] = v;
    }
    __syncthreads();
    if (tid < NOUTc) {
        float acc = fb[tid];
#pragma unroll 2
        for (int k = 0; k < 3 * Uc; k++) acc = fmaf(hcat[k], fW[k * NOUTc + tid], acc);
        out[b * NOUTc + tid] = acc;
    }
}

// ---------------- host driver ----------------
extern "C" void kernel_launch(void* const* d_in, const int* in_sizes, int n_in,
                              void* d_out, int out_size) {
    const int*   buff_word_id   = (const int*)d_in[0];
    const int*   buff_pos_id    = (const int*)d_in[1];
    const int*   comp_word_id   = (const int*)d_in[2];
    const int*   comp_pos_id    = (const int*)d_in[3];
    const int*   comp_action_id = (const int*)d_in[4];
    const int*   comp_action_len= (const int*)d_in[5];
    const int*   history_action_id = (const int*)d_in[6];
    const int*   stack_length   = (const int*)d_in[7];
    const int*   buff_length    = (const int*)d_in[8];
    const int*   history_action_length = (const int*)d_in[9];
    const float* p_emb      = (const float*)d_in[10];
    const float* comp_a_emb = (const float*)d_in[11];
    const float* hist_a_emb = (const float*)d_in[12];
    const float* w_emb      = (const float*)d_in[13];
    const float* emb_W      = (const float*)d_in[14];
    const float* emb_b      = (const float*)d_in[15];
    const float* rec_W      = (const float*)d_in[16];
    const float* rec_b      = (const float*)d_in[17];
    const float* W0s[3] = { (const float*)d_in[18], (const float*)d_in[22], (const float*)d_in[26] };
    const float* b0s[3] = { (const float*)d_in[19], (const float*)d_in[23], (const float*)d_in[27] };
    const float* W1s[3] = { (const float*)d_in[20], (const float*)d_in[24], (const float*)d_in[28] };
    const float* b1s[3] = { (const float*)d_in[21], (const float*)d_in[25], (const float*)d_in[29] };
    const float* fW  = (const float*)d_in[30];
    const float* fb  = (const float*)d_in[31];
    float* out = (float*)d_out;

    float *buff_emb_p, *comp_emb_p, *stack_emb_p;
    float *zx0_p, *zx1_p, *zx2_p, *pp_p;
    float *c0_p, *c1_p, *h0_p, *h1_p;
    cudaGetSymbolAddress((void**)&buff_emb_p,  g_buff_emb);
    cudaGetSymbolAddress((void**)&comp_emb_p,  g_comp_emb);
    cudaGetSymbolAddress((void**)&stack_emb_p, g_stack_emb);
    cudaGetSymbolAddress((void**)&zx0_p, g_zx0);
    cudaGetSymbolAddress((void**)&zx1_p, g_zx1);
    cudaGetSymbolAddress((void**)&zx2_p, g_zx2);
    cudaGetSymbolAddress((void**)&pp_p,  g_p);
    cudaGetSymbolAddress((void**)&c0_p, g_c0);
    cudaGetSymbolAddress((void**)&c1_p, g_c1);
    cudaGetSymbolAddress((void**)&h0_p, g_h0);
    cudaGetSymbolAddress((void**)&h1_p, g_h1);

    const size_t SB  = (size_t)Bc * Uc;
    const size_t ZPB = (size_t)Bc * 1024;

    cudaMemsetAsync(c0_p, 0, 3 * SB * sizeof(float));
    cudaMemsetAsync(c1_p, 0, 3 * SB * sizeof(float));
    cudaMemsetAsync(h0_p, 0, 3 * 2 * SB * sizeof(float));
    cudaMemsetAsync(h1_p, 0, 3 * 2 * SB * sizeof(float));

    // embeddings
    const int nbuff = Bc * BUFFc;
    embed_kernel<<<(nbuff + 7) / 8, 128>>>(buff_word_id, buff_pos_id, w_emb, p_emb,
                                           emb_W, emb_b, buff_emb_p, nbuff);
    const int ncomp = Bc * STKc * 16;
    embed_kernel<<<(ncomp + 7) / 8, 128>>>(comp_word_id, comp_pos_id, w_emb, p_emb,
                                           emb_W, emb_b, comp_emb_p, ncomp);

    // recursive compose
    compose_kernel<<<Bc * STKc, 128>>>(comp_word_id, comp_emb_p, comp_action_id,
                                       comp_action_len, comp_a_emb, rec_W, rec_b,
                                       stack_emb_p);

    // x-projections for layer0
    {
        XJobs xj;
        xj.j[0] = XJob{ stack_emb_p, nullptr, nullptr, W0s[0], zx0_p, Bc * STKc,  FCc };
        xj.j[1] = XJob{ buff_emb_p,  nullptr, nullptr, W0s[1], zx1_p, Bc * BUFFc, FCc };
        xj.j[2] = XJob{ nullptr, history_action_id, hist_a_emb, W0s[2], zx2_p, Bc * HISTc, 50 };
        xproj_kernel<<<dim3(384 * 8, 3), 256>>>(xj);
    }

    // --- deep-pipelined loop: one launch per iteration, all units K=256 ---
    // iter i: U_a = layer0 step i;  U_b = p(i-1) = h0(i-1)@W1a;  U_c = layer1 step i-2.
    float* ZXs[3]  = { zx0_p, zx1_p, zx2_p };
    const int DIN0[3] = { FCc, FCc, 50 };
    const int Ts[3]   = { STKc, BUFFc, HISTc };
    const int* LEN[3] = { stack_length, buff_length, history_action_length };

    for (int i = 0; i <= HISTc + 1; i++) {
        SUnits su;
        int n = 0;
        const int pr = (i + 1) & 1;   // parity of states i-1 / i-3; p write buffer
        const int pw = i & 1;         // parity of states i / i-2;   p read buffer
        for (int L = 0; L < 3; L++) {
            const int T = Ts[L];
            float* h0rd = h0_p + (L * 2 + pr) * SB;
            float* h0wr = h0_p + (L * 2 + pw) * SB;
            float* h1rd = h1_p + (L * 2 + pr) * SB;
            float* h1wr = h1_p + (L * 2 + pw) * SB;
            float* pwr  = pp_p + (L * 2 + pr) * ZPB;
            float* prd  = pp_p + (L * 2 + pw) * ZPB;
            float* c0L = c0_p + L * SB;
            float* c1L = c1_p + L * SB;
            if (i < T) {                       // layer0 step i
                su.u[n++] = SUnit{ h0rd, W0s[L] + (size_t)DIN0[L] * 1024,
                                   ZXs[L] + (size_t)i * 1024, (long)T * 1024,
                                   b0s[L], h0rd, c0L, h0wr, nullptr, LEN[L], i, 1 };
            }
            if (i >= 1 && i <= T) {            // p(i-1) = h0(i-1) @ W1a
                su.u[n++] = SUnit{ h0rd, W1s[L],
                                   nullptr, 0, nullptr, nullptr, nullptr, nullptr,
                                   pwr, nullptr, 0, 0 };
            }
            if (i >= 2 && i <= T + 1) {        // layer1 step i-2
                su.u[n++] = SUnit{ h1rd, W1s[L] + (size_t)256 * 1024,
                                   prd, 1024,
                                   b1s[L], h1rd, c1L, h1wr, nullptr, LEN[L], i - 2, 1 };
            }
        }
        if (n > 0)
            lstm_unit_kernel<<<dim3(32, n), 256>>>(su);
    }

    // output head: final h1 state T-1 lives at parity 1 (T even for all three)
    final_kernel<<<Bc, 128>>>(h1_p + (0 * 2 + 1) * SB,
                              h1_p + (1 * 2 + 1) * SB,
                              h1_p + (2 * 2 + 1) * SB,
                              fW, fb, out);
}

// round 8
// speedup vs baseline: 1.3628x; 1.0009x over previous
#include <cuda_runtime.h>
#include <math.h>

// ---------------- problem constants ----------------
#define Bc    128
#define BUFFc 64
#define STKc  48
#define HISTc 96
#define FCc   128
#define Uc    256
#define NOUTc 82
#define WDIMc 300
#define POSDc 50
#define EDINc 350
#define CADc  50
#define RDINc 306
#define NBLK  288
#define NITER 98

// ---------------- device scratch ----------------
__device__ float g_buff_emb[Bc * BUFFc * FCc];
__device__ float g_comp_emb[Bc * STKc * 16 * FCc];
__device__ float g_stack_emb[Bc * STKc * FCc];

__device__ float g_zx0[Bc * STKc  * 1024];
__device__ float g_zx1[Bc * BUFFc * 1024];
__device__ float g_zx2[Bc * HISTc * 1024];

__device__ float g_p [3][2][Bc * 1024];
__device__ float g_c0[3][Bc * Uc];
__device__ float g_c1[3][Bc * Uc];
__device__ float g_h0[3][2][Bc * Uc];
__device__ float g_h1[3][2][Bc * Uc];

__device__ unsigned g_bar;   // reset by cudaMemsetAsync before each persistent launch

__device__ __forceinline__ float sigm(float x) {
    return __fdividef(1.0f, 1.0f + __expf(-x));
}
__device__ __forceinline__ float tanh_(float x) {
    return __fdividef(2.0f, 1.0f + __expf(-2.0f * x)) - 1.0f;
}

// ---------------- persistent fused LSTM loop ----------------
// 9 slots x 32 tiles = 288 blocks, all resident (2/SM). One grid barrier per
// iteration. slot = L*3 + kind: kind0 = layer0 gates step i, kind1 = partial
// p(i-1)=h0(i-1)@W1a, kind2 = layer1 gates step i-2 (z = h1@W1b + p).
struct PParams {
    const float* W0h[3];
    const float* b0[3];
    const float* W1a[3];
    const float* W1b[3];
    const float* b1[3];
    const int*   len[3];
};

__global__ void __launch_bounds__(256, 2) lstm_loop_kernel(PParams P) {
    const int tid = threadIdx.x;
    const int bid = blockIdx.x;
    const int slot = bid >> 5;            // 0..8
    const int L = slot / 3;
    const int kind = slot - L * 3;
    const int tile = bid & 31;
    const int bm = tile & 3, bu = tile >> 2;
    const int b0r = bm * 32;
    const int u0 = bu * 32;

    __shared__ float xs[2][32][33];
    __shared__ __align__(16) float ws_raw[2 * 32 * 128];
#define WS(bf,k,c) ws_raw[(bf) * 4096 + (k) * 128 + (c)]

    const int mi = tid & 7,  ni = tid >> 3;
    const int m0 = mi * 4,   n0t = ni * 4;
    const int xm = tid >> 3;
    const int xk = (tid & 7) * 4;
    const int wk = tid >> 5;
    const int wc4 = tid & 31;
    const int gcol = (wc4 >> 3) * 256 + u0 + (wc4 & 7) * 4;

    const int T = (L == 0) ? STKc : (L == 1) ? BUFFc : HISTc;
    float* zxL = (L == 0) ? g_zx0 : (L == 1) ? g_zx1 : g_zx2;
    const int* lenL = P.len[L];

    for (int i = 0; i < NITER; i++) {
        const int pr = (i + 1) & 1;
        const int pw = i & 1;

        const float* src = nullptr;
        const float* W = nullptr;
        const float* extra = nullptr;
        long ebs = 0;
        const float* bias = nullptr;
        float* c = nullptr;
        float* h_out = nullptr;
        float* p_out = nullptr;
        int t = 0;
        bool gates = false, active = false;

        if (kind == 0) {
            if (i < T) {
                active = true; gates = true;
                src = &g_h0[L][pr][0];
                W = P.W0h[L];
                extra = zxL + (size_t)i * 1024;  ebs = (long)T * 1024;
                bias = P.b0[L];
                c = &g_c0[L][0];
                h_out = &g_h0[L][pw][0];
                t = i;
            }
        } else if (kind == 1) {
            if (i >= 1 && i <= T) {
                active = true;
                src = &g_h0[L][pr][0];
                W = P.W1a[L];
                p_out = &g_p[L][pr][0];
            }
        } else {
            if (i >= 2 && i <= T + 1) {
                active = true; gates = true;
                src = &g_h1[L][pr][0];
                W = P.W1b[L];
                extra = &g_p[L][pw][0];  ebs = 1024;
                bias = P.b1[L];
                c = &g_c1[L][0];
                h_out = &g_h1[L][pw][0];
                t = i - 2;
            }
        }

        if (active) {
            float acc[4][4];
#pragma unroll
            for (int a = 0; a < 4; a++)
#pragma unroll
                for (int b = 0; b < 4; b++) acc[a][b] = 0.0f;

            const float* srow = src + (b0r + xm) * Uc;

            // prologue: stage k-tile 0 (x via L2; W via L1 - persists across iters)
            {
                float4 xv = __ldcg((const float4*)(srow + xk));
                xs[0][xm][xk + 0] = xv.x; xs[0][xm][xk + 1] = xv.y;
                xs[0][xm][xk + 2] = xv.z; xs[0][xm][xk + 3] = xv.w;
#pragma unroll
                for (int q = 0; q < 4; q++) {
                    const int kk = wk + 8 * q;
                    *(float4*)&WS(0, kk, wc4 * 4) =
                        *(const float4*)(W + (size_t)kk * 1024 + gcol);
                }
            }
            __syncthreads();

            int buf = 0;
#pragma unroll 1
            for (int kt = 0; kt < 8; kt++) {
                float4 xv, wv0, wv1, wv2, wv3;
                const bool more = (kt < 7);
                if (more) {
                    const int k0 = (kt + 1) * 32;
                    xv = __ldcg((const float4*)(srow + k0 + xk));
                    const float* wrow = W + (size_t)(k0 + wk) * 1024 + gcol;
                    wv0 = *(const float4*)(wrow);
                    wv1 = *(const float4*)(wrow +  8 * 1024);
                    wv2 = *(const float4*)(wrow + 16 * 1024);
                    wv3 = *(const float4*)(wrow + 24 * 1024);
                }

                const float (*xsb)[33] = xs[buf];
#pragma unroll
                for (int kk = 0; kk < 32; kk++) {
                    const float x0 = xsb[m0 + 0][kk];
                    const float x1 = xsb[m0 + 1][kk];
                    const float x2 = xsb[m0 + 2][kk];
                    const float x3 = xsb[m0 + 3][kk];
                    const float4 w = *(const float4*)&WS(buf, kk, n0t);
                    acc[0][0] = fmaf(x0, w.x, acc[0][0]);
                    acc[0][1] = fmaf(x0, w.y, acc[0][1]);
                    acc[0][2] = fmaf(x0, w.z, acc[0][2]);
                    acc[0][3] = fmaf(x0, w.w, acc[0][3]);
                    acc[1][0] = fmaf(x1, w.x, acc[1][0]);
                    acc[1][1] = fmaf(x1, w.y, acc[1][1]);
                    acc[1][2] = fmaf(x1, w.z, acc[1][2]);
                    acc[1][3] = fmaf(x1, w.w, acc[1][3]);
                    acc[2][0] = fmaf(x2, w.x, acc[2][0]);
                    acc[2][1] = fmaf(x2, w.y, acc[2][1]);
                    acc[2][2] = fmaf(x2, w.z, acc[2][2]);
                    acc[2][3] = fmaf(x2, w.w, acc[2][3]);
                    acc[3][0] = fmaf(x3, w.x, acc[3][0]);
                    acc[3][1] = fmaf(x3, w.y, acc[3][1]);
                    acc[3][2] = fmaf(x3, w.z, acc[3][2]);
                    acc[3][3] = fmaf(x3, w.w, acc[3][3]);
                }

                if (more) {
                    const int nb = buf ^ 1;
                    xs[nb][xm][xk + 0] = xv.x; xs[nb][xm][xk + 1] = xv.y;
                    xs[nb][xm][xk + 2] = xv.z; xs[nb][xm][xk + 3] = xv.w;
                    *(float4*)&WS(nb, wk +  0, wc4 * 4) = wv0;
                    *(float4*)&WS(nb, wk +  8, wc4 * 4) = wv1;
                    *(float4*)&WS(nb, wk + 16, wc4 * 4) = wv2;
                    *(float4*)&WS(nb, wk + 24, wc4 * 4) = wv3;
                    __syncthreads();
                    buf = nb;
                }
            }

            if (!gates) {
                // store partial z (gate-interleaved local cols -> global cols)
                const int gcolS = (n0t >> 5) * 256 + u0 + (n0t & 31);
#pragma unroll
                for (int a = 0; a < 4; a++) {
                    __stcg((float4*)(p_out + (size_t)(b0r + m0 + a) * 1024 + gcolS),
                           make_float4(acc[a][0], acc[a][1], acc[a][2], acc[a][3]));
                }
            } else {
                // gates epilogue: exchange z via SMEM overlay
                __syncthreads();
                float* zt = ws_raw;      // zt[c][b], stride 33
#pragma unroll
                for (int cc = 0; cc < 4; cc++)
#pragma unroll
                    for (int a = 0; a < 4; a++)
                        zt[(n0t + cc) * 33 + (m0 + a)] = acc[a][cc];
                __syncthreads();

                const int uu = tid & 31;
                const int bq = tid >> 5;
                const int colu = u0 + uu;
                const float bi = bias[colu];
                const float bj = bias[256 + colu];
                const float bf = bias[512 + colu];
                const float bo = bias[768 + colu];

#pragma unroll
                for (int q = 0; q < 4; q++) {
                    const int bl = bq + 8 * q;
                    const int b = b0r + bl;
                    const int gidx = b * Uc + colu;
                    if (t < lenL[b]) {
                        const float* er = extra + (size_t)b * ebs;
                        float g0 = zt[(  0 + uu) * 33 + bl] + bi + __ldcg(&er[colu]);
                        float g1 = zt[( 32 + uu) * 33 + bl] + bj + __ldcg(&er[256 + colu]);
                        float g2 = zt[( 64 + uu) * 33 + bl] + bf + __ldcg(&er[512 + colu]);
                        float g3 = zt[( 96 + uu) * 33 + bl] + bo + __ldcg(&er[768 + colu]);
                        const float cn = __ldcg(&c[gidx]) * sigm(g2 + 1.0f)
                                       + sigm(g0) * tanh_(g1);
                        const float hn = tanh_(cn) * sigm(g3);
                        __stcg(&c[gidx], cn);
                        __stcg(&h_out[gidx], hn);
                    } else {
                        __stcg(&h_out[gidx], __ldcg(&src[gidx]));
                    }
                }
            }
        }

        // ---- grid barrier ----
        __syncthreads();
        __threadfence();
        if (tid == 0) {
            atomicAdd(&g_bar, 1u);
            const unsigned target = (unsigned)NBLK * (unsigned)(i + 1);
            volatile unsigned* vb = &g_bar;
            while (*vb < target) __nanosleep(32);
        }
        __syncthreads();
    }
#undef WS
}

// ---------------- x-projection precompute ----------------
struct XJob { const float* x; const int* ids; const float* tab;
              const float* W; float* zx; int rows, Din; };
struct XJobs { XJob j[3]; };

__global__ void xproj_kernel(XJobs jobs) {
    const XJob J = jobs.j[blockIdx.y];
    const int bm = blockIdx.x % 384;
    const int bn = blockIdx.x / 384;
    const int r0 = bm * 32;
    if (r0 >= J.rows) return;
    const int n0 = bn * 128;

    __shared__ float xs[32][33];
    __shared__ __align__(16) float ws[32][128];
    const int tid = threadIdx.x;
    const int mi = tid & 7, ni = tid >> 3;
    const int m0 = mi * 4, n0t = ni * 4;
    const int xm = tid >> 3, xk = (tid & 7) * 4;
    const int wc = (tid & 31) * 4, wk = tid >> 5;

    float acc[4][4];
#pragma unroll
    for (int a = 0; a < 4; a++)
#pragma unroll
        for (int b = 0; b < 4; b++) acc[a][b] = 0.0f;

    const int r = r0 + xm;
    const float* srow = J.ids ? (J.tab + (size_t)J.ids[r] * J.Din)
                              : (J.x + (size_t)r * J.Din);

    const int nk = (J.Din + 31) >> 5;
    for (int kt = 0; kt < nk; kt++) {
        const int k0 = kt * 32;
        __syncthreads();
#pragma unroll
        for (int j = 0; j < 4; j++) {
            const int k = k0 + xk + j;
            xs[xm][xk + j] = (k < J.Din) ? srow[k] : 0.0f;
        }
#pragma unroll
        for (int q = 0; q < 4; q++) {
            const int kk = wk + 8 * q, k = k0 + kk;
            float4 wv = make_float4(0.f, 0.f, 0.f, 0.f);
            if (k < J.Din)
                wv = *(const float4*)(J.W + (size_t)k * 1024 + n0 + wc);
            *(float4*)&ws[kk][wc] = wv;
        }
        __syncthreads();
#pragma unroll 8
        for (int kk = 0; kk < 32; kk++) {
            const float x0 = xs[m0 + 0][kk];
            const float x1 = xs[m0 + 1][kk];
            const float x2 = xs[m0 + 2][kk];
            const float x3 = xs[m0 + 3][kk];
            const float4 w = *(const float4*)&ws[kk][n0t];
            acc[0][0] = fmaf(x0, w.x, acc[0][0]);
            acc[0][1] = fmaf(x0, w.y, acc[0][1]);
            acc[0][2] = fmaf(x0, w.z, acc[0][2]);
            acc[0][3] = fmaf(x0, w.w, acc[0][3]);
            acc[1][0] = fmaf(x1, w.x, acc[1][0]);
            acc[1][1] = fmaf(x1, w.y, acc[1][1]);
            acc[1][2] = fmaf(x1, w.z, acc[1][2]);
            acc[1][3] = fmaf(x1, w.w, acc[1][3]);
            acc[2][0] = fmaf(x2, w.x, acc[2][0]);
            acc[2][1] = fmaf(x2, w.y, acc[2][1]);
            acc[2][2] = fmaf(x2, w.z, acc[2][2]);
            acc[2][3] = fmaf(x2, w.w, acc[2][3]);
            acc[3][0] = fmaf(x3, w.x, acc[3][0]);
            acc[3][1] = fmaf(x3, w.y, acc[3][1]);
            acc[3][2] = fmaf(x3, w.z, acc[3][2]);
            acc[3][3] = fmaf(x3, w.w, acc[3][3]);
        }
    }
#pragma unroll
    for (int a = 0; a < 4; a++) {
        *(float4*)(J.zx + (size_t)(r0 + m0 + a) * 1024 + n0 + n0t) =
            make_float4(acc[a][0], acc[a][1], acc[a][2], acc[a][3]);
    }
}

// ---------------- embedding ----------------
__global__ void embed_kernel(const int* __restrict__ word_ids,
                             const int* __restrict__ pos_ids,
                             const float* __restrict__ w_emb,
                             const float* __restrict__ p_emb,
                             const float* __restrict__ W,
                             const float* __restrict__ bias,
                             float* __restrict__ out,
                             int nrows) {
    __shared__ float xs[8][EDINc];
    __shared__ int wid_s[8], pid_s[8];
    const int r0 = blockIdx.x * 8;
    const int tid = threadIdx.x;

    if (tid < 8) {
        int row = r0 + tid;
        wid_s[tid] = (row < nrows) ? word_ids[row] : 0;
        pid_s[tid] = (row < nrows) ? pos_ids[row] : 0;
    }
    __syncthreads();

    for (int idx = tid; idx < 8 * EDINc; idx += 128) {
        int r = idx / EDINc, k = idx - r * EDINc;
        float v;
        if (k < WDIMc) v = w_emb[wid_s[r] * WDIMc + k];
        else           v = p_emb[pid_s[r] * POSDc + (k - WDIMc)];
        xs[r][k] = v;
    }
    __syncthreads();

    float acc[8];
    const float bj = bias[tid];
#pragma unroll
    for (int r = 0; r < 8; r++) acc[r] = bj;

#pragma unroll 2
    for (int k = 0; k < EDINc; k++) {
        float w = W[k * FCc + tid];
#pragma unroll
        for (int r = 0; r < 8; r++) acc[r] = fmaf(xs[r][k], w, acc[r]);
    }
#pragma unroll
    for (int r = 0; r < 8; r++) {
        int row = r0 + r;
        if (row < nrows) out[row * FCc + tid] = fmaxf(acc[r], 0.0f);
    }
}

// ---------------- compose ----------------
__global__ void compose_kernel(const int* __restrict__ comp_word_id,
                               const float* __restrict__ comp_emb,
                               const int* __restrict__ comp_action_id,
                               const int* __restrict__ comp_action_len,
                               const float* __restrict__ a_emb,
                               const float* __restrict__ rec_W,
                               const float* __restrict__ rec_b,
                               float* __restrict__ stack_emb) {
    const int seq = blockIdx.x;
    const int tid = threadIdx.x;
    __shared__ float vals[8][FCc];
    __shared__ float xbuf[RDINc];
    __shared__ int hid[8], did[8];

    if (tid < 8) {
        hid[tid] = comp_word_id[seq * 16 + 2 * tid];
        did[tid] = comp_word_id[seq * 16 + 2 * tid + 1];
    }
    __syncthreads();

    const float bj = rec_b[tid];
    for (int n = 0; n < 8; n++) {
        int ih = -1, idd = -1;
        for (int m = 0; m < n; m++) {
            if (hid[m] == hid[n]) ih = m;
            if (hid[m] == did[n]) idd = m;
        }
        float he = (ih  >= 0) ? vals[ih][tid]  : comp_emb[(seq * 16 + 2 * n) * FCc + tid];
        float de = (idd >= 0) ? vals[idd][tid] : comp_emb[(seq * 16 + 2 * n + 1) * FCc + tid];
        xbuf[tid] = he;
        xbuf[FCc + CADc + tid] = de;
        if (tid < CADc) xbuf[FCc + tid] = a_emb[comp_action_id[seq * 8 + n] * CADc + tid];
        __syncthreads();

        float acc = bj;
#pragma unroll 2
        for (int k = 0; k < RDINc; k++) acc = fmaf(xbuf[k], rec_W[k * FCc + tid], acc);
        vals[n][tid] = tanhf(acc);
        __syncthreads();
    }

    int al = comp_action_len[seq];
    float outv = (al == 0) ? comp_emb[(seq * 16) * FCc + tid] : vals[al - 1][tid];
    stack_emb[seq * FCc + tid] = outv;
}

// ---------------- output head ----------------
__global__ void final_kernel(const float* __restrict__ hs,
                             const float* __restrict__ hb,
                             const float* __restrict__ ha,
                             const float* __restrict__ fW,
                             const float* __restrict__ fb,
                             float* __restrict__ out) {
    const int b = blockIdx.x;
    const int tid = threadIdx.x;
    __shared__ float hcat[3 * Uc];
    for (int idx = tid; idx < 3 * Uc; idx += 128) {
        float v;
        if (idx < Uc)            v = hs[b * Uc + idx];
        else if (idx < 2 * Uc)   v = hb[b * Uc + idx - Uc];
        else                     v = ha[b * Uc + idx - 2 * Uc];
        hcat[idx] = v;
    }
    __syncthreads();
    if (tid < NOUTc) {
        float acc = fb[tid];
#pragma unroll 2
        for (int k = 0; k < 3 * Uc; k++) acc = fmaf(hcat[k], fW[k * NOUTc + tid], acc);
        out[b * NOUTc + tid] = acc;
    }
}

// ---------------- host driver ----------------
extern "C" void kernel_launch(void* const* d_in, const int* in_sizes, int n_in,
                              void* d_out, int out_size) {
    const int*   buff_word_id   = (const int*)d_in[0];
    const int*   buff_pos_id    = (const int*)d_in[1];
    const int*   comp_word_id   = (const int*)d_in[2];
    const int*   comp_pos_id    = (const int*)d_in[3];
    const int*   comp_action_id = (const int*)d_in[4];
    const int*   comp_action_len= (const int*)d_in[5];
    const int*   history_action_id = (const int*)d_in[6];
    const int*   stack_length   = (const int*)d_in[7];
    const int*   buff_length    = (const int*)d_in[8];
    const int*   history_action_length = (const int*)d_in[9];
    const float* p_emb      = (const float*)d_in[10];
    const float* comp_a_emb = (const float*)d_in[11];
    const float* hist_a_emb = (const float*)d_in[12];
    const float* w_emb      = (const float*)d_in[13];
    const float* emb_W      = (const float*)d_in[14];
    const float* emb_b      = (const float*)d_in[15];
    const float* rec_W      = (const float*)d_in[16];
    const float* rec_b      = (const float*)d_in[17];
    const float* W0s[3] = { (const float*)d_in[18], (const float*)d_in[22], (const float*)d_in[26] };
    const float* b0s[3] = { (const float*)d_in[19], (const float*)d_in[23], (const float*)d_in[27] };
    const float* W1s[3] = { (const float*)d_in[20], (const float*)d_in[24], (const float*)d_in[28] };
    const float* b1s[3] = { (const float*)d_in[21], (const float*)d_in[25], (const float*)d_in[29] };
    const float* fW  = (const float*)d_in[30];
    const float* fb  = (const float*)d_in[31];
    float* out = (float*)d_out;

    float *buff_emb_p, *comp_emb_p, *stack_emb_p;
    float *zx0_p, *zx1_p, *zx2_p;
    float *c0_p, *c1_p, *h0_p, *h1_p;
    unsigned* bar_p;
    cudaGetSymbolAddress((void**)&buff_emb_p,  g_buff_emb);
    cudaGetSymbolAddress((void**)&comp_emb_p,  g_comp_emb);
    cudaGetSymbolAddress((void**)&stack_emb_p, g_stack_emb);
    cudaGetSymbolAddress((void**)&zx0_p, g_zx0);
    cudaGetSymbolAddress((void**)&zx1_p, g_zx1);
    cudaGetSymbolAddress((void**)&zx2_p, g_zx2);
    cudaGetSymbolAddress((void**)&c0_p, g_c0);
    cudaGetSymbolAddress((void**)&c1_p, g_c1);
    cudaGetSymbolAddress((void**)&h0_p, g_h0);
    cudaGetSymbolAddress((void**)&h1_p, g_h1);
    cudaGetSymbolAddress((void**)&bar_p, g_bar);

    const size_t SB = (size_t)Bc * Uc;

    cudaMemsetAsync(bar_p, 0, sizeof(unsigned));
    cudaMemsetAsync(c0_p, 0, 3 * SB * sizeof(float));
    cudaMemsetAsync(c1_p, 0, 3 * SB * sizeof(float));
    cudaMemsetAsync(h0_p, 0, 3 * 2 * SB * sizeof(float));
    cudaMemsetAsync(h1_p, 0, 3 * 2 * SB * sizeof(float));

    // embeddings
    const int nbuff = Bc * BUFFc;
    embed_kernel<<<(nbuff + 7) / 8, 128>>>(buff_word_id, buff_pos_id, w_emb, p_emb,
                                           emb_W, emb_b, buff_emb_p, nbuff);
    const int ncomp = Bc * STKc * 16;
    embed_kernel<<<(ncomp + 7) / 8, 128>>>(comp_word_id, comp_pos_id, w_emb, p_emb,
                                           emb_W, emb_b, comp_emb_p, ncomp);

    // recursive compose
    compose_kernel<<<Bc * STKc, 128>>>(comp_word_id, comp_emb_p, comp_action_id,
                                       comp_action_len, comp_a_emb, rec_W, rec_b,
                                       stack_emb_p);

    // x-projections for layer0
    {
        XJobs xj;
        xj.j[0] = XJob{ stack_emb_p, nullptr, nullptr, W0s[0], zx0_p, Bc * STKc,  FCc };
        xj.j[1] = XJob{ buff_emb_p,  nullptr, nullptr, W0s[1], zx1_p, Bc * BUFFc, FCc };
        xj.j[2] = XJob{ nullptr, history_action_id, hist_a_emb, W0s[2], zx2_p, Bc * HISTc, 50 };
        xproj_kernel<<<dim3(384 * 8, 3), 256>>>(xj);
    }

    // persistent fused loop: all 98 iterations in ONE launch
    {
        PParams P;
        for (int L = 0; L < 3; L++) {
            const int din = (L == 2) ? 50 : FCc;
            P.W0h[L] = W0s[L] + (size_t)din * 1024;   // h-slab of layer0 W
            P.b0[L]  = b0s[L];
            P.W1a[L] = W1s[L];                        // x-slab (h0 input) of layer1 W
            P.W1b[L] = W1s[L] + (size_t)256 * 1024;   // h-slab of layer1 W
            P.b1[L]  = b1s[L];
        }
        P.len[0] = stack_length;
        P.len[1] = buff_length;
        P.len[2] = history_action_length;
        lstm_loop_kernel<<<NBLK, 256>>>(P);
    }

    // output head: final h1 state (t = T-1, T even) lives at parity 1
    final_kernel<<<Bc, 128>>>(h1_p + (0 * 2 + 1) * SB,
                              h1_p + (1 * 2 + 1) * SB,
                              h1_p + (2 * 2 + 1) * SB,
                              fW, fb, out);
}

// round 9
// speedup vs baseline: 1.4044x; 1.0305x over previous
#include <cuda_runtime.h>
#include <math.h>

// ---------------- problem constants ----------------
#define Bc    128
#define BUFFc 64
#define STKc  48
#define HISTc 96
#define FCc   128
#define Uc    256
#define NOUTc 82
#define WDIMc 300
#define POSDc 50
#define EDINc 350
#define CADc  50
#define RDINc 306
#define NBLK  288
#define NITER 98

// ---------------- device scratch ----------------
__device__ float g_buff_emb[Bc * BUFFc * FCc];
__device__ float g_comp_emb[Bc * STKc * 16 * FCc];
__device__ float g_stack_emb[Bc * STKc * FCc];

__device__ float g_zx0[Bc * STKc  * 1024];
__device__ float g_zx1[Bc * BUFFc * 1024];
__device__ float g_zx2[Bc * HISTc * 1024];

__device__ float g_p [3][2][Bc * 1024];      // sorted-order layer1 partials
__device__ float g_c0[3][Bc * Uc];           // sorted order
__device__ float g_c1[3][Bc * Uc];
__device__ float g_h0[3][2][Bc * Uc];        // sorted order, double-buffered
__device__ float g_h1[3][2][Bc * Uc];

__device__ int g_perm[3][Bc];    // sorted pos -> original batch
__device__ int g_inv [3][Bc];    // original batch -> sorted pos
__device__ int g_lens[3][Bc];    // lengths in sorted (descending) order
__device__ int g_cnt [3][HISTc]; // cnt[L][t] = #batches with len > t

__device__ unsigned g_bar;

__device__ __forceinline__ float sigm(float x) {
    return __fdividef(1.0f, 1.0f + __expf(-x));
}
__device__ __forceinline__ float tanh_(float x) {
    return __fdividef(2.0f, 1.0f + __expf(-2.0f * x)) - 1.0f;
}

// ---------------- per-LSTM length sort (stable, descending) ----------------
__global__ void sort_kernel(const int* len0, const int* len1, const int* len2) {
    const int L = blockIdx.x;
    const int* len = (L == 0) ? len0 : (L == 1) ? len1 : len2;
    const int T = (L == 0) ? STKc : (L == 1) ? BUFFc : HISTc;
    __shared__ int sl[Bc];
    const int tid = threadIdx.x;   // 128
    sl[tid] = len[tid];
    __syncthreads();
    const int myl = sl[tid];
    int rank = 0;
    for (int b = 0; b < Bc; b++) {
        const int lb = sl[b];
        rank += (lb > myl) || (lb == myl && b < tid);
    }
    g_perm[L][rank] = tid;
    g_inv[L][tid] = rank;
    g_lens[L][rank] = myl;
    if (tid < T) {
        int c = 0;
        for (int b = 0; b < Bc; b++) c += (sl[b] > tid);
        g_cnt[L][tid] = c;
    }
}

// ---------------- persistent fused LSTM loop with dynamic scheduling ----------------
// Work item = (unit s = L*3+kind, b-tile bm, u-tile bu). Units only cover the
// active (sorted) batch prefix: nb = ceil(cnt/32). Max items = 288 = NBLK.
struct PParams {
    const float* W0h[3];
    const float* b0[3];
    const float* W1a[3];
    const float* W1b[3];
    const float* b1[3];
};

__global__ void __launch_bounds__(256, 2) lstm_loop_kernel(PParams P) {
    const int tid = threadIdx.x;
    const int bid = blockIdx.x;

    __shared__ float xs[2][32][33];
    __shared__ __align__(16) float ws_raw[2 * 32 * 128];
#define WS(bf,k,c) ws_raw[(bf) * 4096 + (k) * 128 + (c)]

    const int mi = tid & 7,  ni = tid >> 3;
    const int m0 = mi * 4,   n0t = ni * 4;
    const int xm = tid >> 3;
    const int xk = (tid & 7) * 4;
    const int wk = tid >> 5;
    const int wc4 = tid & 31;

    for (int i = 0; i < NITER; i++) {
        const int pr = (i + 1) & 1;
        const int pw = i & 1;

        // ---- schedule: map bid -> (unit, tile) over active items ----
        int sfound = -1, local = 0, off = 0;
#pragma unroll
        for (int s = 0; s < 9; s++) {
            const int Ls = s / 3, kind = s - Ls * 3;
            const int Ts = (Ls == 0) ? STKc : (Ls == 1) ? BUFFc : HISTc;
            const int ts = i - kind;
            int nb = 0;
            if (ts >= 0 && ts < Ts) {
                const int cc = g_cnt[Ls][ts];
                nb = (cc + 31) >> 5;
            }
            const int items = nb * 8;
            if (sfound < 0 && bid >= off && bid < off + items) {
                sfound = s; local = bid - off;
            }
            off += items;
        }

        if (sfound >= 0) {
            const int L = sfound / 3, kind = sfound - L * 3;
            const int Ts = (L == 0) ? STKc : (L == 1) ? BUFFc : HISTc;
            const int t = i - kind;
            const int bm = local >> 3, bu = local & 7;
            const int b0r = bm * 32;
            const int u0 = bu * 32;
            const int gcol = (wc4 >> 3) * 256 + u0 + (wc4 & 7) * 4;

            const float* src;
            const float* W;
            const float* extra = nullptr;
            const float* bias = nullptr;
            float* c = nullptr;
            float* h_out = nullptr;
            float* p_out = nullptr;
            bool gates;
            if (kind == 0) {
                gates = true;
                src = &g_h0[L][pr][0];
                W = P.W0h[L];
                bias = P.b0[L];
                c = &g_c0[L][0];
                h_out = &g_h0[L][pw][0];
            } else if (kind == 1) {
                gates = false;
                src = &g_h0[L][pr][0];
                W = P.W1a[L];
                p_out = &g_p[L][pr][0];
            } else {
                gates = true;
                src = &g_h1[L][pr][0];
                W = P.W1b[L];
                extra = &g_p[L][pw][0];
                bias = P.b1[L];
                c = &g_c1[L][0];
                h_out = &g_h1[L][pw][0];
            }

            float acc[4][4];
#pragma unroll
            for (int a = 0; a < 4; a++)
#pragma unroll
                for (int b = 0; b < 4; b++) acc[a][b] = 0.0f;

            const float* srow = src + (b0r + xm) * Uc;

            // prologue: stage k-tile 0
            {
                float4 xv = __ldcg((const float4*)(srow + xk));
                xs[0][xm][xk + 0] = xv.x; xs[0][xm][xk + 1] = xv.y;
                xs[0][xm][xk + 2] = xv.z; xs[0][xm][xk + 3] = xv.w;
#pragma unroll
                for (int q = 0; q < 4; q++) {
                    const int kk = wk + 8 * q;
                    *(float4*)&WS(0, kk, wc4 * 4) =
                        *(const float4*)(W + (size_t)kk * 1024 + gcol);
                }
            }
            __syncthreads();

            int buf = 0;
#pragma unroll 1
            for (int kt = 0; kt < 8; kt++) {
                float4 xv, wv0, wv1, wv2, wv3;
                const bool more = (kt < 7);
                if (more) {
                    const int k0 = (kt + 1) * 32;
                    xv = __ldcg((const float4*)(srow + k0 + xk));
                    const float* wrow = W + (size_t)(k0 + wk) * 1024 + gcol;
                    wv0 = *(const float4*)(wrow);
                    wv1 = *(const float4*)(wrow +  8 * 1024);
                    wv2 = *(const float4*)(wrow + 16 * 1024);
                    wv3 = *(const float4*)(wrow + 24 * 1024);
                }

                const float (*xsb)[33] = xs[buf];
#pragma unroll
                for (int kk = 0; kk < 32; kk++) {
                    const float x0 = xsb[m0 + 0][kk];
                    const float x1 = xsb[m0 + 1][kk];
                    const float x2 = xsb[m0 + 2][kk];
                    const float x3 = xsb[m0 + 3][kk];
                    const float4 w = *(const float4*)&WS(buf, kk, n0t);
                    acc[0][0] = fmaf(x0, w.x, acc[0][0]);
                    acc[0][1] = fmaf(x0, w.y, acc[0][1]);
                    acc[0][2] = fmaf(x0, w.z, acc[0][2]);
                    acc[0][3] = fmaf(x0, w.w, acc[0][3]);
                    acc[1][0] = fmaf(x1, w.x, acc[1][0]);
                    acc[1][1] = fmaf(x1, w.y, acc[1][1]);
                    acc[1][2] = fmaf(x1, w.z, acc[1][2]);
                    acc[1][3] = fmaf(x1, w.w, acc[1][3]);
                    acc[2][0] = fmaf(x2, w.x, acc[2][0]);
                    acc[2][1] = fmaf(x2, w.y, acc[2][1]);
                    acc[2][2] = fmaf(x2, w.z, acc[2][2]);
                    acc[2][3] = fmaf(x2, w.w, acc[2][3]);
                    acc[3][0] = fmaf(x3, w.x, acc[3][0]);
                    acc[3][1] = fmaf(x3, w.y, acc[3][1]);
                    acc[3][2] = fmaf(x3, w.z, acc[3][2]);
                    acc[3][3] = fmaf(x3, w.w, acc[3][3]);
                }

                if (more) {
                    const int nb2 = buf ^ 1;
                    xs[nb2][xm][xk + 0] = xv.x; xs[nb2][xm][xk + 1] = xv.y;
                    xs[nb2][xm][xk + 2] = xv.z; xs[nb2][xm][xk + 3] = xv.w;
                    *(float4*)&WS(nb2, wk +  0, wc4 * 4) = wv0;
                    *(float4*)&WS(nb2, wk +  8, wc4 * 4) = wv1;
                    *(float4*)&WS(nb2, wk + 16, wc4 * 4) = wv2;
                    *(float4*)&WS(nb2, wk + 24, wc4 * 4) = wv3;
                    __syncthreads();
                    buf = nb2;
                }
            }

            if (!gates) {
                const int gcolS = (n0t >> 5) * 256 + u0 + (n0t & 31);
#pragma unroll
                for (int a = 0; a < 4; a++) {
                    __stcg((float4*)(p_out + (size_t)(b0r + m0 + a) * 1024 + gcolS),
                           make_float4(acc[a][0], acc[a][1], acc[a][2], acc[a][3]));
                }
            } else {
                __syncthreads();
                float* zt = ws_raw;
#pragma unroll
                for (int cc = 0; cc < 4; cc++)
#pragma unroll
                    for (int a = 0; a < 4; a++)
                        zt[(n0t + cc) * 33 + (m0 + a)] = acc[a][cc];
                __syncthreads();

                const int uu = tid & 31;
                const int bq = tid >> 5;
                const int colu = u0 + uu;
                const float bi = bias[colu];
                const float bj = bias[256 + colu];
                const float bf = bias[512 + colu];
                const float bo = bias[768 + colu];
                const float* zxbase = (L == 0) ? g_zx0 : (L == 1) ? g_zx1 : g_zx2;

#pragma unroll
                for (int q = 0; q < 4; q++) {
                    const int bl = bq + 8 * q;
                    const int j = b0r + bl;            // sorted batch index
                    if (t < g_lens[L][j]) {
                        const float* er;
                        if (kind == 0)
                            er = zxbase + ((size_t)g_perm[L][j] * Ts + t) * 1024;
                        else
                            er = extra + (size_t)j * 1024;
                        const int gidx = j * Uc + colu;
                        float g0 = zt[(  0 + uu) * 33 + bl] + bi + __ldcg(&er[colu]);
                        float g1 = zt[( 32 + uu) * 33 + bl] + bj + __ldcg(&er[256 + colu]);
                        float g2 = zt[( 64 + uu) * 33 + bl] + bf + __ldcg(&er[512 + colu]);
                        float g3 = zt[( 96 + uu) * 33 + bl] + bo + __ldcg(&er[768 + colu]);
                        const float cn = __ldcg(&c[gidx]) * sigm(g2 + 1.0f)
                                       + sigm(g0) * tanh_(g1);
                        const float hn = tanh_(cn) * sigm(g3);
                        __stcg(&c[gidx], cn);
                        __stcg(&h_out[gidx], hn);
                    }
                }
            }
        }

        // ---- grid barrier ----
        __syncthreads();
        __threadfence();
        if (tid == 0) {
            atomicAdd(&g_bar, 1u);
            const unsigned target = (unsigned)NBLK * (unsigned)(i + 1);
            volatile unsigned* vb = &g_bar;
            while (*vb < target) __nanosleep(32);
        }
        __syncthreads();
    }
#undef WS
}

// ---------------- x-projection precompute (skips fully-masked blocks) ----------------
struct XJob { const float* x; const int* ids; const float* tab;
              const float* W; float* zx; const int* len; int rows, Din, T; };
struct XJobs { XJob j[3]; };

__global__ void xproj_kernel(XJobs jobs) {
    const XJob J = jobs.j[blockIdx.y];
    const int bm = blockIdx.x % 384;
    const int bn = blockIdx.x / 384;
    const int r0 = bm * 32;
    if (r0 >= J.rows) return;
    const int tid = threadIdx.x;

    // whole-block skip when every (b,t) row is masked (t >= len[b])
    int pred = 0;
    if (tid < 32) {
        const int r = r0 + tid;
        const int bb = r / J.T;
        const int tt = r - bb * J.T;
        pred = (tt < J.len[bb]);
    }
    if (!__syncthreads_or(pred)) return;

    const int n0 = bn * 128;
    __shared__ float xs[32][33];
    __shared__ __align__(16) float ws[32][128];
    const int mi = tid & 7, ni = tid >> 3;
    const int m0 = mi * 4, n0t = ni * 4;
    const int xm = tid >> 3, xk = (tid & 7) * 4;
    const int wc = (tid & 31) * 4, wk = tid >> 5;

    float acc[4][4];
#pragma unroll
    for (int a = 0; a < 4; a++)
#pragma unroll
        for (int b = 0; b < 4; b++) acc[a][b] = 0.0f;

    const int r = r0 + xm;
    const float* srow = J.ids ? (J.tab + (size_t)J.ids[r] * J.Din)
                              : (J.x + (size_t)r * J.Din);

    const int nk = (J.Din + 31) >> 5;
    for (int kt = 0; kt < nk; kt++) {
        const int k0 = kt * 32;
        __syncthreads();
#pragma unroll
        for (int j = 0; j < 4; j++) {
            const int k = k0 + xk + j;
            xs[xm][xk + j] = (k < J.Din) ? srow[k] : 0.0f;
        }
#pragma unroll
        for (int q = 0; q < 4; q++) {
            const int kk = wk + 8 * q, k = k0 + kk;
            float4 wv = make_float4(0.f, 0.f, 0.f, 0.f);
            if (k < J.Din)
                wv = *(const float4*)(J.W + (size_t)k * 1024 + n0 + wc);
            *(float4*)&ws[kk][wc] = wv;
        }
        __syncthreads();
#pragma unroll 8
        for (int kk = 0; kk < 32; kk++) {
            const float x0 = xs[m0 + 0][kk];
            const float x1 = xs[m0 + 1][kk];
            const float x2 = xs[m0 + 2][kk];
            const float x3 = xs[m0 + 3][kk];
            const float4 w = *(const float4*)&ws[kk][n0t];
            acc[0][0] = fmaf(x0, w.x, acc[0][0]);
            acc[0][1] = fmaf(x0, w.y, acc[0][1]);
            acc[0][2] = fmaf(x0, w.z, acc[0][2]);
            acc[0][3] = fmaf(x0, w.w, acc[0][3]);
            acc[1][0] = fmaf(x1, w.x, acc[1][0]);
            acc[1][1] = fmaf(x1, w.y, acc[1][1]);
            acc[1][2] = fmaf(x1, w.z, acc[1][2]);
            acc[1][3] = fmaf(x1, w.w, acc[1][3]);
            acc[2][0] = fmaf(x2, w.x, acc[2][0]);
            acc[2][1] = fmaf(x2, w.y, acc[2][1]);
            acc[2][2] = fmaf(x2, w.z, acc[2][2]);
            acc[2][3] = fmaf(x2, w.w, acc[2][3]);
            acc[3][0] = fmaf(x3, w.x, acc[3][0]);
            acc[3][1] = fmaf(x3, w.y, acc[3][1]);
            acc[3][2] = fmaf(x3, w.z, acc[3][2]);
            acc[3][3] = fmaf(x3, w.w, acc[3][3]);
        }
    }
#pragma unroll
    for (int a = 0; a < 4; a++) {
        *(float4*)(J.zx + (size_t)(r0 + m0 + a) * 1024 + n0 + n0t) =
            make_float4(acc[a][0], acc[a][1], acc[a][2], acc[a][3]);
    }
}

// ---------------- embedding ----------------
__global__ void embed_kernel(const int* __restrict__ word_ids,
                             const int* __restrict__ pos_ids,
                             const float* __restrict__ w_emb,
                             const float* __restrict__ p_emb,
                             const float* __restrict__ W,
                             const float* __restrict__ bias,
                             float* __restrict__ out,
                             int nrows) {
    __shared__ float xs[8][EDINc];
    __shared__ int wid_s[8], pid_s[8];
    const int r0 = blockIdx.x * 8;
    const int tid = threadIdx.x;

    if (tid < 8) {
        int row = r0 + tid;
        wid_s[tid] = (row < nrows) ? word_ids[row] : 0;
        pid_s[tid] = (row < nrows) ? pos_ids[row] : 0;
    }
    __syncthreads();

    for (int idx = tid; idx < 8 * EDINc; idx += 128) {
        int r = idx / EDINc, k = idx - r * EDINc;
        float v;
        if (k < WDIMc) v = w_emb[wid_s[r] * WDIMc + k];
        else           v = p_emb[pid_s[r] * POSDc + (k - WDIMc)];
        xs[r][k] = v;
    }
    __syncthreads();

    float acc[8];
    const float bj = bias[tid];
#pragma unroll
    for (int r = 0; r < 8; r++) acc[r] = bj;

#pragma unroll 2
    for (int k = 0; k < EDINc; k++) {
        float w = W[k * FCc + tid];
#pragma unroll
        for (int r = 0; r < 8; r++) acc[r] = fmaf(xs[r][k], w, acc[r]);
    }
#pragma unroll
    for (int r = 0; r < 8; r++) {
        int row = r0 + r;
        if (row < nrows) out[row * FCc + tid] = fmaxf(acc[r], 0.0f);
    }
}

// ---------------- compose ----------------
__global__ void compose_kernel(const int* __restrict__ comp_word_id,
                               const float* __restrict__ comp_emb,
                               const int* __restrict__ comp_action_id,
                               const int* __restrict__ comp_action_len,
                               const float* __restrict__ a_emb,
                               const float* __restrict__ rec_W,
                               const float* __restrict__ rec_b,
                               float* __restrict__ stack_emb) {
    const int seq = blockIdx.x;
    const int tid = threadIdx.x;
    __shared__ float vals[8][FCc];
    __shared__ float xbuf[RDINc];
    __shared__ int hid[8], did[8];

    if (tid < 8) {
        hid[tid] = comp_word_id[seq * 16 + 2 * tid];
        did[tid] = comp_word_id[seq * 16 + 2 * tid + 1];
    }
    __syncthreads();

    const float bj = rec_b[tid];
    for (int n = 0; n < 8; n++) {
        int ih = -1, idd = -1;
        for (int m = 0; m < n; m++) {
            if (hid[m] == hid[n]) ih = m;
            if (hid[m] == did[n]) idd = m;
        }
        float he = (ih  >= 0) ? vals[ih][tid]  : comp_emb[(seq * 16 + 2 * n) * FCc + tid];
        float de = (idd >= 0) ? vals[idd][tid] : comp_emb[(seq * 16 + 2 * n + 1) * FCc + tid];
        xbuf[tid] = he;
        xbuf[FCc + CADc + tid] = de;
        if (tid < CADc) xbuf[FCc + tid] = a_emb[comp_action_id[seq * 8 + n] * CADc + tid];
        __syncthreads();

        float acc = bj;
#pragma unroll 2
        for (int k = 0; k < RDINc; k++) acc = fmaf(xbuf[k], rec_W[k * FCc + tid], acc);
        vals[n][tid] = tanhf(acc);
        __syncthreads();
    }

    int al = comp_action_len[seq];
    float outv = (al == 0) ? comp_emb[(seq * 16) * FCc + tid] : vals[al - 1][tid];
    stack_emb[seq * FCc + tid] = outv;
}

// ---------------- output head (per-batch parity + inverse-perm gather) ----------------
__global__ void final_kernel(const int* __restrict__ l0,
                             const int* __restrict__ l1,
                             const int* __restrict__ l2,
                             const float* __restrict__ fW,
                             const float* __restrict__ fb,
                             float* __restrict__ out) {
    const int b = blockIdx.x;
    const int tid = threadIdx.x;
    __shared__ float hcat[3 * Uc];
    for (int idx = tid; idx < 3 * Uc; idx += 128) {
        const int L = idx >> 8;
        const int col = idx & 255;
        const int len = ((L == 0) ? l0 : (L == 1) ? l1 : l2)[b];
        const int j = g_inv[L][b];
        hcat[idx] = g_h1[L][(len - 1) & 1][j * Uc + col];
    }
    __syncthreads();
    if (tid < NOUTc) {
        float acc = fb[tid];
#pragma unroll 2
        for (int k = 0; k < 3 * Uc; k++) acc = fmaf(hcat[k], fW[k * NOUTc + tid], acc);
        out[b * NOUTc + tid] = acc;
    }
}

// ---------------- host driver ----------------
extern "C" void kernel_launch(void* const* d_in, const int* in_sizes, int n_in,
                              void* d_out, int out_size) {
    const int*   buff_word_id   = (const int*)d_in[0];
    const int*   buff_pos_id    = (const int*)d_in[1];
    const int*   comp_word_id   = (const int*)d_in[2];
    const int*   comp_pos_id    = (const int*)d_in[3];
    const int*   comp_action_id = (const int*)d_in[4];
    const int*   comp_action_len= (const int*)d_in[5];
    const int*   history_action_id = (const int*)d_in[6];
    const int*   stack_length   = (const int*)d_in[7];
    const int*   buff_length    = (const int*)d_in[8];
    const int*   history_action_length = (const int*)d_in[9];
    const float* p_emb      = (const float*)d_in[10];
    const float* comp_a_emb = (const float*)d_in[11];
    const float* hist_a_emb = (const float*)d_in[12];
    const float* w_emb      = (const float*)d_in[13];
    const float* emb_W      = (const float*)d_in[14];
    const float* emb_b      = (const float*)d_in[15];
    const float* rec_W      = (const float*)d_in[16];
    const float* rec_b      = (const float*)d_in[17];
    const float* W0s[3] = { (const float*)d_in[18], (const float*)d_in[22], (const float*)d_in[26] };
    const float* b0s[3] = { (const float*)d_in[19], (const float*)d_in[23], (const float*)d_in[27] };
    const float* W1s[3] = { (const float*)d_in[20], (const float*)d_in[24], (const float*)d_in[28] };
    const float* b1s[3] = { (const float*)d_in[21], (const float*)d_in[25], (const float*)d_in[29] };
    const float* fW  = (const float*)d_in[30];
    const float* fb  = (const float*)d_in[31];
    float* out = (float*)d_out;

    float *buff_emb_p, *comp_emb_p, *stack_emb_p;
    float *zx0_p, *zx1_p, *zx2_p;
    float *c0_p, *c1_p, *h0_p, *h1_p;
    unsigned* bar_p;
    cudaGetSymbolAddress((void**)&buff_emb_p,  g_buff_emb);
    cudaGetSymbolAddress((void**)&comp_emb_p,  g_comp_emb);
    cudaGetSymbolAddress((void**)&stack_emb_p, g_stack_emb);
    cudaGetSymbolAddress((void**)&zx0_p, g_zx0);
    cudaGetSymbolAddress((void**)&zx1_p, g_zx1);
    cudaGetSymbolAddress((void**)&zx2_p, g_zx2);
    cudaGetSymbolAddress((void**)&c0_p, g_c0);
    cudaGetSymbolAddress((void**)&c1_p, g_c1);
    cudaGetSymbolAddress((void**)&h0_p, g_h0);
    cudaGetSymbolAddress((void**)&h1_p, g_h1);
    cudaGetSymbolAddress((void**)&bar_p, g_bar);

    const size_t SB = (size_t)Bc * Uc;

    cudaMemsetAsync(bar_p, 0, sizeof(unsigned));
    cudaMemsetAsync(c0_p, 0, 3 * SB * sizeof(float));
    cudaMemsetAsync(c1_p, 0, 3 * SB * sizeof(float));
    cudaMemsetAsync(h0_p, 0, 3 * 2 * SB * sizeof(float));
    cudaMemsetAsync(h1_p, 0, 3 * 2 * SB * sizeof(float));

    // length sort + per-step active counts
    sort_kernel<<<3, 128>>>(stack_length, buff_length, history_action_length);

    // embeddings
    const int nbuff = Bc * BUFFc;
    embed_kernel<<<(nbuff + 7) / 8, 128>>>(buff_word_id, buff_pos_id, w_emb, p_emb,
                                           emb_W, emb_b, buff_emb_p, nbuff);
    const int ncomp = Bc * STKc * 16;
    embed_kernel<<<(ncomp + 7) / 8, 128>>>(comp_word_id, comp_pos_id, w_emb, p_emb,
                                           emb_W, emb_b, comp_emb_p, ncomp);

    // recursive compose
    compose_kernel<<<Bc * STKc, 128>>>(comp_word_id, comp_emb_p, comp_action_id,
                                       comp_action_len, comp_a_emb, rec_W, rec_b,
                                       stack_emb_p);

    // x-projections for layer0 (masked-block skip)
    {
        XJobs xj;
        xj.j[0] = XJob{ stack_emb_p, nullptr, nullptr, W0s[0], zx0_p,
                        stack_length, Bc * STKc,  FCc, STKc };
        xj.j[1] = XJob{ buff_emb_p,  nullptr, nullptr, W0s[1], zx1_p,
                        buff_length, Bc * BUFFc, FCc, BUFFc };
        xj.j[2] = XJob{ nullptr, history_action_id, hist_a_emb, W0s[2], zx2_p,
                        history_action_length, Bc * HISTc, 50, HISTc };
        xproj_kernel<<<dim3(384 * 8, 3), 256>>>(xj);
    }

    // persistent fused loop (length-aware dynamic scheduling)
    {
        PParams P;
        for (int L = 0; L < 3; L++) {
            const int din = (L == 2) ? 50 : FCc;
            P.W0h[L] = W0s[L] + (size_t)din * 1024;
            P.b0[L]  = b0s[L];
            P.W1a[L] = W1s[L];
            P.W1b[L] = W1s[L] + (size_t)256 * 1024;
            P.b1[L]  = b1s[L];
        }
        lstm_loop_kernel<<<NBLK, 256>>>(P);
    }

    // output head
    final_kernel<<<Bc, 128>>>(stack_length, buff_length, history_action_length,
                              fW, fb, out);
}

// round 10
// speedup vs baseline: 1.7009x; 1.2111x over previous
#include <cuda_runtime.h>
#include <math.h>

// ---------------- problem constants ----------------
#define Bc    128
#define BUFFc 64
#define STKc  48
#define HISTc 96
#define FCc   128
#define Uc    256
#define NOUTc 82
#define WDIMc 300
#define POSDc 50
#define EDINc 350
#define CADc  50
#define RDINc 306
#define NBLK  288
#define NITER 98
#define CSEQ  8

// ---------------- device scratch ----------------
__device__ float g_buff_emb[Bc * BUFFc * FCc];
__device__ float g_comp_emb[Bc * STKc * 16 * FCc];
__device__ float g_stack_emb[Bc * STKc * FCc];

__device__ float g_zx0[Bc * STKc  * 1024];
__device__ float g_zx1[Bc * BUFFc * 1024];
__device__ float g_zx2[Bc * HISTc * 1024];

__device__ float g_p [3][2][Bc * 1024];
__device__ float g_c0[3][Bc * Uc];
__device__ float g_c1[3][Bc * Uc];
__device__ float g_h0[3][2][Bc * Uc];
__device__ float g_h1[3][2][Bc * Uc];

__device__ int g_perm[3][Bc];
__device__ int g_inv [3][Bc];
__device__ int g_lens[3][Bc];
__device__ int g_cnt [3][HISTc];

__device__ unsigned g_bar;

__device__ __forceinline__ float sigm(float x) {
    return __fdividef(1.0f, 1.0f + __expf(-x));
}
__device__ __forceinline__ float tanh_(float x) {
    return __fdividef(2.0f, 1.0f + __expf(-2.0f * x)) - 1.0f;
}

// ---------------- per-LSTM length sort (stable, descending) ----------------
__global__ void sort_kernel(const int* len0, const int* len1, const int* len2) {
    const int L = blockIdx.x;
    const int* len = (L == 0) ? len0 : (L == 1) ? len1 : len2;
    const int T = (L == 0) ? STKc : (L == 1) ? BUFFc : HISTc;
    __shared__ int sl[Bc];
    const int tid = threadIdx.x;
    sl[tid] = len[tid];
    __syncthreads();
    const int myl = sl[tid];
    int rank = 0;
    for (int b = 0; b < Bc; b++) {
        const int lb = sl[b];
        rank += (lb > myl) || (lb == myl && b < tid);
    }
    g_perm[L][rank] = tid;
    g_inv[L][tid] = rank;
    g_lens[L][rank] = myl;
    if (tid < T) {
        int c = 0;
        for (int b = 0; b < Bc; b++) c += (sl[b] > tid);
        g_cnt[L][tid] = c;
    }
}

// ---------------- persistent fused LSTM loop (unchanged from R8) ----------------
struct PParams {
    const float* W0h[3];
    const float* b0[3];
    const float* W1a[3];
    const float* W1b[3];
    const float* b1[3];
};

__global__ void __launch_bounds__(256, 2) lstm_loop_kernel(PParams P) {
    const int tid = threadIdx.x;
    const int bid = blockIdx.x;

    __shared__ float xs[2][32][33];
    __shared__ __align__(16) float ws_raw[2 * 32 * 128];
#define WS(bf,k,c) ws_raw[(bf) * 4096 + (k) * 128 + (c)]

    const int mi = tid & 7,  ni = tid >> 3;
    const int m0 = mi * 4,   n0t = ni * 4;
    const int xm = tid >> 3;
    const int xk = (tid & 7) * 4;
    const int wk = tid >> 5;
    const int wc4 = tid & 31;

    for (int i = 0; i < NITER; i++) {
        const int pr = (i + 1) & 1;
        const int pw = i & 1;

        int sfound = -1, local = 0, off = 0;
#pragma unroll
        for (int s = 0; s < 9; s++) {
            const int Ls = s / 3, kind = s - Ls * 3;
            const int Ts = (Ls == 0) ? STKc : (Ls == 1) ? BUFFc : HISTc;
            const int ts = i - kind;
            int nb = 0;
            if (ts >= 0 && ts < Ts) {
                const int cc = g_cnt[Ls][ts];
                nb = (cc + 31) >> 5;
            }
            const int items = nb * 8;
            if (sfound < 0 && bid >= off && bid < off + items) {
                sfound = s; local = bid - off;
            }
            off += items;
        }

        if (sfound >= 0) {
            const int L = sfound / 3, kind = sfound - L * 3;
            const int Ts = (L == 0) ? STKc : (L == 1) ? BUFFc : HISTc;
            const int t = i - kind;
            const int bm = local >> 3, bu = local & 7;
            const int b0r = bm * 32;
            const int u0 = bu * 32;
            const int gcol = (wc4 >> 3) * 256 + u0 + (wc4 & 7) * 4;

            const float* src;
            const float* W;
            const float* extra = nullptr;
            const float* bias = nullptr;
            float* c = nullptr;
            float* h_out = nullptr;
            float* p_out = nullptr;
            bool gates;
            if (kind == 0) {
                gates = true;
                src = &g_h0[L][pr][0];
                W = P.W0h[L];
                bias = P.b0[L];
                c = &g_c0[L][0];
                h_out = &g_h0[L][pw][0];
            } else if (kind == 1) {
                gates = false;
                src = &g_h0[L][pr][0];
                W = P.W1a[L];
                p_out = &g_p[L][pr][0];
            } else {
                gates = true;
                src = &g_h1[L][pr][0];
                W = P.W1b[L];
                extra = &g_p[L][pw][0];
                bias = P.b1[L];
                c = &g_c1[L][0];
                h_out = &g_h1[L][pw][0];
            }

            float acc[4][4];
#pragma unroll
            for (int a = 0; a < 4; a++)
#pragma unroll
                for (int b = 0; b < 4; b++) acc[a][b] = 0.0f;

            const float* srow = src + (b0r + xm) * Uc;

            {
                float4 xv = __ldcg((const float4*)(srow + xk));
                xs[0][xm][xk + 0] = xv.x; xs[0][xm][xk + 1] = xv.y;
                xs[0][xm][xk + 2] = xv.z; xs[0][xm][xk + 3] = xv.w;
#pragma unroll
                for (int q = 0; q < 4; q++) {
                    const int kk = wk + 8 * q;
                    *(float4*)&WS(0, kk, wc4 * 4) =
                        *(const float4*)(W + (size_t)kk * 1024 + gcol);
                }
            }
            __syncthreads();

            int buf = 0;
#pragma unroll 1
            for (int kt = 0; kt < 8; kt++) {
                float4 xv, wv0, wv1, wv2, wv3;
                const bool more = (kt < 7);
                if (more) {
                    const int k0 = (kt + 1) * 32;
                    xv = __ldcg((const float4*)(srow + k0 + xk));
                    const float* wrow = W + (size_t)(k0 + wk) * 1024 + gcol;
                    wv0 = *(const float4*)(wrow);
                    wv1 = *(const float4*)(wrow +  8 * 1024);
                    wv2 = *(const float4*)(wrow + 16 * 1024);
                    wv3 = *(const float4*)(wrow + 24 * 1024);
                }

                const float (*xsb)[33] = xs[buf];
#pragma unroll
                for (int kk = 0; kk < 32; kk++) {
                    const float x0 = xsb[m0 + 0][kk];
                    const float x1 = xsb[m0 + 1][kk];
                    const float x2 = xsb[m0 + 2][kk];
                    const float x3 = xsb[m0 + 3][kk];
                    const float4 w = *(const float4*)&WS(buf, kk, n0t);
                    acc[0][0] = fmaf(x0, w.x, acc[0][0]);
                    acc[0][1] = fmaf(x0, w.y, acc[0][1]);
                    acc[0][2] = fmaf(x0, w.z, acc[0][2]);
                    acc[0][3] = fmaf(x0, w.w, acc[0][3]);
                    acc[1][0] = fmaf(x1, w.x, acc[1][0]);
                    acc[1][1] = fmaf(x1, w.y, acc[1][1]);
                    acc[1][2] = fmaf(x1, w.z, acc[1][2]);
                    acc[1][3] = fmaf(x1, w.w, acc[1][3]);
                    acc[2][0] = fmaf(x2, w.x, acc[2][0]);
                    acc[2][1] = fmaf(x2, w.y, acc[2][1]);
                    acc[2][2] = fmaf(x2, w.z, acc[2][2]);
                    acc[2][3] = fmaf(x2, w.w, acc[2][3]);
                    acc[3][0] = fmaf(x3, w.x, acc[3][0]);
                    acc[3][1] = fmaf(x3, w.y, acc[3][1]);
                    acc[3][2] = fmaf(x3, w.z, acc[3][2]);
                    acc[3][3] = fmaf(x3, w.w, acc[3][3]);
                }

                if (more) {
                    const int nb2 = buf ^ 1;
                    xs[nb2][xm][xk + 0] = xv.x; xs[nb2][xm][xk + 1] = xv.y;
                    xs[nb2][xm][xk + 2] = xv.z; xs[nb2][xm][xk + 3] = xv.w;
                    *(float4*)&WS(nb2, wk +  0, wc4 * 4) = wv0;
                    *(float4*)&WS(nb2, wk +  8, wc4 * 4) = wv1;
                    *(float4*)&WS(nb2, wk + 16, wc4 * 4) = wv2;
                    *(float4*)&WS(nb2, wk + 24, wc4 * 4) = wv3;
                    __syncthreads();
                    buf = nb2;
                }
            }

            if (!gates) {
                const int gcolS = (n0t >> 5) * 256 + u0 + (n0t & 31);
#pragma unroll
                for (int a = 0; a < 4; a++) {
                    __stcg((float4*)(p_out + (size_t)(b0r + m0 + a) * 1024 + gcolS),
                           make_float4(acc[a][0], acc[a][1], acc[a][2], acc[a][3]));
                }
            } else {
                __syncthreads();
                float* zt = ws_raw;
#pragma unroll
                for (int cc = 0; cc < 4; cc++)
#pragma unroll
                    for (int a = 0; a < 4; a++)
                        zt[(n0t + cc) * 33 + (m0 + a)] = acc[a][cc];
                __syncthreads();

                const int uu = tid & 31;
                const int bq = tid >> 5;
                const int colu = u0 + uu;
                const float bi = bias[colu];
                const float bj = bias[256 + colu];
                const float bf = bias[512 + colu];
                const float bo = bias[768 + colu];
                const float* zxbase = (L == 0) ? g_zx0 : (L == 1) ? g_zx1 : g_zx2;

#pragma unroll
                for (int q = 0; q < 4; q++) {
                    const int bl = bq + 8 * q;
                    const int j = b0r + bl;
                    if (t < g_lens[L][j]) {
                        const float* er;
                        if (kind == 0)
                            er = zxbase + ((size_t)g_perm[L][j] * Ts + t) * 1024;
                        else
                            er = extra + (size_t)j * 1024;
                        const int gidx = j * Uc + colu;
                        float g0 = zt[(  0 + uu) * 33 + bl] + bi + __ldcg(&er[colu]);
                        float g1 = zt[( 32 + uu) * 33 + bl] + bj + __ldcg(&er[256 + colu]);
                        float g2 = zt[( 64 + uu) * 33 + bl] + bf + __ldcg(&er[512 + colu]);
                        float g3 = zt[( 96 + uu) * 33 + bl] + bo + __ldcg(&er[768 + colu]);
                        const float cn = __ldcg(&c[gidx]) * sigm(g2 + 1.0f)
                                       + sigm(g0) * tanh_(g1);
                        const float hn = tanh_(cn) * sigm(g3);
                        __stcg(&c[gidx], cn);
                        __stcg(&h_out[gidx], hn);
                    }
                }
            }
        }

        __syncthreads();
        __threadfence();
        if (tid == 0) {
            atomicAdd(&g_bar, 1u);
            const unsigned target = (unsigned)NBLK * (unsigned)(i + 1);
            volatile unsigned* vb = &g_bar;
            while (*vb < target) __nanosleep(32);
        }
        __syncthreads();
    }
#undef WS
}

// ---------------- x-projection precompute (masked-block skip) ----------------
struct XJob { const float* x; const int* ids; const float* tab;
              const float* W; float* zx; const int* len; int rows, Din, T; };
struct XJobs { XJob j[3]; };

__global__ void xproj_kernel(XJobs jobs) {
    const XJob J = jobs.j[blockIdx.y];
    const int bm = blockIdx.x % 384;
    const int bn = blockIdx.x / 384;
    const int r0 = bm * 32;
    if (r0 >= J.rows) return;
    const int tid = threadIdx.x;

    int pred = 0;
    if (tid < 32) {
        const int r = r0 + tid;
        const int bb = r / J.T;
        const int tt = r - bb * J.T;
        pred = (tt < J.len[bb]);
    }
    if (!__syncthreads_or(pred)) return;

    const int n0 = bn * 128;
    __shared__ float xs[32][33];
    __shared__ __align__(16) float ws[32][128];
    const int mi = tid & 7, ni = tid >> 3;
    const int m0 = mi * 4, n0t = ni * 4;
    const int xm = tid >> 3, xk = (tid & 7) * 4;
    const int wc = (tid & 31) * 4, wk = tid >> 5;

    float acc[4][4];
#pragma unroll
    for (int a = 0; a < 4; a++)
#pragma unroll
        for (int b = 0; b < 4; b++) acc[a][b] = 0.0f;

    const int r = r0 + xm;
    const float* srow = J.ids ? (J.tab + (size_t)J.ids[r] * J.Din)
                              : (J.x + (size_t)r * J.Din);

    const int nk = (J.Din + 31) >> 5;
    for (int kt = 0; kt < nk; kt++) {
        const int k0 = kt * 32;
        __syncthreads();
#pragma unroll
        for (int j = 0; j < 4; j++) {
            const int k = k0 + xk + j;
            xs[xm][xk + j] = (k < J.Din) ? srow[k] : 0.0f;
        }
#pragma unroll
        for (int q = 0; q < 4; q++) {
            const int kk = wk + 8 * q, k = k0 + kk;
            float4 wv = make_float4(0.f, 0.f, 0.f, 0.f);
            if (k < J.Din)
                wv = *(const float4*)(J.W + (size_t)k * 1024 + n0 + wc);
            *(float4*)&ws[kk][wc] = wv;
        }
        __syncthreads();
#pragma unroll 8
        for (int kk = 0; kk < 32; kk++) {
            const float x0 = xs[m0 + 0][kk];
            const float x1 = xs[m0 + 1][kk];
            const float x2 = xs[m0 + 2][kk];
            const float x3 = xs[m0 + 3][kk];
            const float4 w = *(const float4*)&ws[kk][n0t];
            acc[0][0] = fmaf(x0, w.x, acc[0][0]);
            acc[0][1] = fmaf(x0, w.y, acc[0][1]);
            acc[0][2] = fmaf(x0, w.z, acc[0][2]);
            acc[0][3] = fmaf(x0, w.w, acc[0][3]);
            acc[1][0] = fmaf(x1, w.x, acc[1][0]);
            acc[1][1] = fmaf(x1, w.y, acc[1][1]);
            acc[1][2] = fmaf(x1, w.z, acc[1][2]);
            acc[1][3] = fmaf(x1, w.w, acc[1][3]);
            acc[2][0] = fmaf(x2, w.x, acc[2][0]);
            acc[2][1] = fmaf(x2, w.y, acc[2][1]);
            acc[2][2] = fmaf(x2, w.z, acc[2][2]);
            acc[2][3] = fmaf(x2, w.w, acc[2][3]);
            acc[3][0] = fmaf(x3, w.x, acc[3][0]);
            acc[3][1] = fmaf(x3, w.y, acc[3][1]);
            acc[3][2] = fmaf(x3, w.z, acc[3][2]);
            acc[3][3] = fmaf(x3, w.w, acc[3][3]);
        }
    }
#pragma unroll
    for (int a = 0; a < 4; a++) {
        *(float4*)(J.zx + (size_t)(r0 + m0 + a) * 1024 + n0 + n0t) =
            make_float4(acc[a][0], acc[a][1], acc[a][2], acc[a][3]);
    }
}

// ---------------- embedding (dead-block skip via len/per_b/per_item) ----------------
__global__ void embed_kernel(const int* __restrict__ word_ids,
                             const int* __restrict__ pos_ids,
                             const float* __restrict__ w_emb,
                             const float* __restrict__ p_emb,
                             const float* __restrict__ W,
                             const float* __restrict__ bias,
                             float* __restrict__ out,
                             int nrows,
                             const int* __restrict__ len,
                             int per_b, int per_item) {
    const int r0 = blockIdx.x * 8;
    {
        const int b = r0 / per_b;
        const int item = (r0 - b * per_b) / per_item;
        if (item >= len[b]) return;    // all 8 rows dead (never read downstream)
    }
    __shared__ float xs[8][EDINc];
    __shared__ int wid_s[8], pid_s[8];
    const int tid = threadIdx.x;

    if (tid < 8) {
        int row = r0 + tid;
        wid_s[tid] = (row < nrows) ? word_ids[row] : 0;
        pid_s[tid] = (row < nrows) ? pos_ids[row] : 0;
    }
    __syncthreads();

    for (int idx = tid; idx < 8 * EDINc; idx += 128) {
        int r = idx / EDINc, k = idx - r * EDINc;
        float v;
        if (k < WDIMc) v = w_emb[wid_s[r] * WDIMc + k];
        else           v = p_emb[pid_s[r] * POSDc + (k - WDIMc)];
        xs[r][k] = v;
    }
    __syncthreads();

    float acc[8];
    const float bj = bias[tid];
#pragma unroll
    for (int r = 0; r < 8; r++) acc[r] = bj;

#pragma unroll 2
    for (int k = 0; k < EDINc; k++) {
        float w = W[k * FCc + tid];
#pragma unroll
        for (int r = 0; r < 8; r++) acc[r] = fmaf(xs[r][k], w, acc[r]);
    }
#pragma unroll
    for (int r = 0; r < 8; r++) {
        int row = r0 + r;
        if (row < nrows) out[row * FCc + tid] = fmaxf(acc[r], 0.0f);
    }
}

// ---------------- compose v2: 8 seqs/block mini-GEMM + dead-block skip ----------------
__global__ void __launch_bounds__(128) compose_kernel(
    const int* __restrict__ comp_word_id,
    const float* __restrict__ comp_emb,
    const int* __restrict__ comp_action_id,
    const int* __restrict__ comp_action_len,
    const float* __restrict__ a_emb,
    const float* __restrict__ rec_W,
    const float* __restrict__ rec_b,
    const int* __restrict__ stack_len,
    float* __restrict__ stack_emb)
{
    const int seq0 = blockIdx.x * CSEQ;
    {   // dead-block skip: all 8 seqs share b (48 % 8 == 0); stk ascending
        const int b = seq0 / STKc;
        const int stk0 = seq0 - b * STKc;
        if (stk0 >= stack_len[b]) return;
    }
    const int tid = threadIdx.x;

    __shared__ float vals[8][CSEQ][FCc];                  // 32 KB
    __shared__ __align__(16) float xs[RDINc][10];         // pad-10: 12.2 KB
    __shared__ int wid[CSEQ][16];
    __shared__ int act[CSEQ][8];
    __shared__ int alen[CSEQ];
    __shared__ signed char ihs[CSEQ][8], idds[CSEQ][8];

    {
        const int ss = tid >> 4, slot = tid & 15;
        wid[ss][slot] = comp_word_id[(seq0 + ss) * 16 + slot];
        if (tid < CSEQ * 8) {
            const int s2 = tid >> 3, n = tid & 7;
            act[s2][n] = comp_action_id[(seq0 + s2) * 8 + n];
        }
        if (tid < CSEQ) alen[tid] = comp_action_len[seq0 + tid];
    }
    __syncthreads();
    if (tid < CSEQ * 8) {
        const int ss = tid >> 3, n = tid & 7;
        const int hn = wid[ss][2 * n], dn = wid[ss][2 * n + 1];
        int ih = -1, idd = -1;
        for (int m = 0; m < n; m++) {
            const int hm = wid[ss][2 * m];
            if (hm == hn) ih = m;
            if (hm == dn) idd = m;
        }
        ihs[ss][n] = (signed char)ih;
        idds[ss][n] = (signed char)idd;
    }
    __syncthreads();

    const int mi = tid & 3,  ni = tid >> 2;    // thread tile: 2 seq x 4 col
    const int s0 = mi * 2,   n0 = ni * 4;
    const float4 bn = *(const float4*)(rec_b + n0);

    for (int n = 0; n < 8; n++) {
        // ---- stage X[k][s] for this step ----
#pragma unroll
        for (int ss = 0; ss < CSEQ; ss++) {
            const int ih = ihs[ss][n], idd = idds[ss][n];
            const int an = act[ss][n];
#pragma unroll
            for (int j = 0; j < 3; j++) {
                const int k = tid + j * 128;
                if (k < RDINc) {
                    float v;
                    if (k < FCc) {
                        v = (ih >= 0) ? vals[ih][ss][k]
                                      : comp_emb[((size_t)(seq0 + ss) * 16 + 2 * n) * FCc + k];
                    } else if (k < FCc + CADc) {
                        v = a_emb[an * CADc + (k - FCc)];
                    } else {
                        const int kk = k - (FCc + CADc);
                        v = (idd >= 0) ? vals[idd][ss][kk]
                                       : comp_emb[((size_t)(seq0 + ss) * 16 + 2 * n + 1) * FCc + kk];
                    }
                    xs[k][ss] = v;
                }
            }
        }
        __syncthreads();

        // ---- mini-GEMM: (8 x 306) @ (306 x 128), thread tile 2x4 ----
        float a00 = 0.f, a01 = 0.f, a02 = 0.f, a03 = 0.f;
        float a10 = 0.f, a11 = 0.f, a12 = 0.f, a13 = 0.f;
#pragma unroll 2
        for (int k = 0; k < RDINc; k++) {
            const float2 xv = *(const float2*)&xs[k][s0];
            const float4 wv = *(const float4*)(rec_W + (size_t)k * FCc + n0);
            a00 = fmaf(xv.x, wv.x, a00);
            a01 = fmaf(xv.x, wv.y, a01);
            a02 = fmaf(xv.x, wv.z, a02);
            a03 = fmaf(xv.x, wv.w, a03);
            a10 = fmaf(xv.y, wv.x, a10);
            a11 = fmaf(xv.y, wv.y, a11);
            a12 = fmaf(xv.y, wv.z, a12);
            a13 = fmaf(xv.y, wv.w, a13);
        }
        *(float4*)&vals[n][s0 + 0][n0] = make_float4(
            tanhf(a00 + bn.x), tanhf(a01 + bn.y), tanhf(a02 + bn.z), tanhf(a03 + bn.w));
        *(float4*)&vals[n][s0 + 1][n0] = make_float4(
            tanhf(a10 + bn.x), tanhf(a11 + bn.y), tanhf(a12 + bn.z), tanhf(a13 + bn.w));
        __syncthreads();
    }

    // ---- outputs ----
#pragma unroll
    for (int ss = 0; ss < CSEQ; ss++) {
        const int al = alen[ss];
        const float v = (al == 0)
            ? comp_emb[(size_t)(seq0 + ss) * 16 * FCc + tid]
            : vals[al - 1][ss][tid];
        stack_emb[(size_t)(seq0 + ss) * FCc + tid] = v;
    }
}

// ---------------- output head ----------------
__global__ void final_kernel(const int* __restrict__ l0,
                             const int* __restrict__ l1,
                             const int* __restrict__ l2,
                             const float* __restrict__ fW,
                             const float* __restrict__ fb,
                             float* __restrict__ out) {
    const int b = blockIdx.x;
    const int tid = threadIdx.x;
    __shared__ float hcat[3 * Uc];
    for (int idx = tid; idx < 3 * Uc; idx += 128) {
        const int L = idx >> 8;
        const int col = idx & 255;
        const int len = ((L == 0) ? l0 : (L == 1) ? l1 : l2)[b];
        const int j = g_inv[L][b];
        hcat[idx] = g_h1[L][(len - 1) & 1][j * Uc + col];
    }
    __syncthreads();
    if (tid < NOUTc) {
        float acc = fb[tid];
#pragma unroll 2
        for (int k = 0; k < 3 * Uc; k++) acc = fmaf(hcat[k], fW[k * NOUTc + tid], acc);
        out[b * NOUTc + tid] = acc;
    }
}

// ---------------- host driver ----------------
extern "C" void kernel_launch(void* const* d_in, const int* in_sizes, int n_in,
                              void* d_out, int out_size) {
    const int*   buff_word_id   = (const int*)d_in[0];
    const int*   buff_pos_id    = (const int*)d_in[1];
    const int*   comp_word_id   = (const int*)d_in[2];
    const int*   comp_pos_id    = (const int*)d_in[3];
    const int*   comp_action_id = (const int*)d_in[4];
    const int*   comp_action_len= (const int*)d_in[5];
    const int*   history_action_id = (const int*)d_in[6];
    const int*   stack_length   = (const int*)d_in[7];
    const int*   buff_length    = (const int*)d_in[8];
    const int*   history_action_length = (const int*)d_in[9];
    const float* p_emb      = (const float*)d_in[10];
    const float* comp_a_emb = (const float*)d_in[11];
    const float* hist_a_emb = (const float*)d_in[12];
    const float* w_emb      = (const float*)d_in[13];
    const float* emb_W      = (const float*)d_in[14];
    const float* emb_b      = (const float*)d_in[15];
    const float* rec_W      = (const float*)d_in[16];
    const float* rec_b      = (const float*)d_in[17];
    const float* W0s[3] = { (const float*)d_in[18], (const float*)d_in[22], (const float*)d_in[26] };
    const float* b0s[3] = { (const float*)d_in[19], (const float*)d_in[23], (const float*)d_in[27] };
    const float* W1s[3] = { (const float*)d_in[20], (const float*)d_in[24], (const float*)d_in[28] };
    const float* b1s[3] = { (const float*)d_in[21], (const float*)d_in[25], (const float*)d_in[29] };
    const float* fW  = (const float*)d_in[30];
    const float* fb  = (const float*)d_in[31];
    float* out = (float*)d_out;

    float *buff_emb_p, *comp_emb_p, *stack_emb_p;
    float *zx0_p, *zx1_p, *zx2_p;
    float *c0_p, *c1_p, *h0_p, *h1_p;
    unsigned* bar_p;
    cudaGetSymbolAddress((void**)&buff_emb_p,  g_buff_emb);
    cudaGetSymbolAddress((void**)&comp_emb_p,  g_comp_emb);
    cudaGetSymbolAddress((void**)&stack_emb_p, g_stack_emb);
    cudaGetSymbolAddress((void**)&zx0_p, g_zx0);
    cudaGetSymbolAddress((void**)&zx1_p, g_zx1);
    cudaGetSymbolAddress((void**)&zx2_p, g_zx2);
    cudaGetSymbolAddress((void**)&c0_p, g_c0);
    cudaGetSymbolAddress((void**)&c1_p, g_c1);
    cudaGetSymbolAddress((void**)&h0_p, g_h0);
    cudaGetSymbolAddress((void**)&h1_p, g_h1);
    cudaGetSymbolAddress((void**)&bar_p, g_bar);

    const size_t SB = (size_t)Bc * Uc;

    cudaMemsetAsync(bar_p, 0, sizeof(unsigned));
    cudaMemsetAsync(c0_p, 0, 3 * SB * sizeof(float));
    cudaMemsetAsync(c1_p, 0, 3 * SB * sizeof(float));
    cudaMemsetAsync(h0_p, 0, 3 * 2 * SB * sizeof(float));
    cudaMemsetAsync(h1_p, 0, 3 * 2 * SB * sizeof(float));

    // length sort + per-step active counts
    sort_kernel<<<3, 128>>>(stack_length, buff_length, history_action_length);

    // embeddings (dead-block skipping)
    const int nbuff = Bc * BUFFc;
    embed_kernel<<<(nbuff + 7) / 8, 128>>>(buff_word_id, buff_pos_id, w_emb, p_emb,
                                           emb_W, emb_b, buff_emb_p, nbuff,
                                           buff_length, BUFFc, 1);
    const int ncomp = Bc * STKc * 16;
    embed_kernel<<<(ncomp + 7) / 8, 128>>>(comp_word_id, comp_pos_id, w_emb, p_emb,
                                           emb_W, emb_b, comp_emb_p, ncomp,
                                           stack_length, STKc * 16, 16);

    // recursive compose (mini-GEMM, dead-block skip)
    compose_kernel<<<Bc * STKc / CSEQ, 128>>>(comp_word_id, comp_emb_p,
                                              comp_action_id, comp_action_len,
                                              comp_a_emb, rec_W, rec_b,
                                              stack_length, stack_emb_p);

    // x-projections for layer0 (masked-block skip)
    {
        XJobs xj;
        xj.j[0] = XJob{ stack_emb_p, nullptr, nullptr, W0s[0], zx0_p,
                        stack_length, Bc * STKc,  FCc, STKc };
        xj.j[1] = XJob{ buff_emb_p,  nullptr, nullptr, W0s[1], zx1_p,
                        buff_length, Bc * BUFFc, FCc, BUFFc };
        xj.j[2] = XJob{ nullptr, history_action_id, hist_a_emb, W0s[2], zx2_p,
                        history_action_length, Bc * HISTc, 50, HISTc };
        xproj_kernel<<<dim3(384 * 8, 3), 256>>>(xj);
    }

    // persistent fused loop
    {
        PParams P;
        for (int L = 0; L < 3; L++) {
            const int din = (L == 2) ? 50 : FCc;
            P.W0h[L] = W0s[L] + (size_t)din * 1024;
            P.b0[L]  = b0s[L];
            P.W1a[L] = W1s[L];
            P.W1b[L] = W1s[L] + (size_t)256 * 1024;
            P.b1[L]  = b1s[L];
        }
        lstm_loop_kernel<<<NBLK, 256>>>(P);
    }

    // output head
    final_kernel<<<Bc, 128>>>(stack_length, buff_length, history_action_length,
                              fW, fb, out);
}

// round 11
// speedup vs baseline: 1.7497x; 1.0287x over previous
#include <cuda_runtime.h>
#include <math.h>

// ---------------- problem constants ----------------
#define Bc    128
#define BUFFc 64
#define STKc  48
#define HISTc 96
#define FCc   128
#define Uc    256
#define NOUTc 82
#define WDIMc 300
#define POSDc 50
#define EDINc 350
#define CADc  50
#define RDINc 306
#define NBLK  288
#define NITER 98
#define CSEQ  8

// ---------------- device scratch ----------------
__device__ float g_buff_emb[Bc * BUFFc * FCc];
__device__ float g_comp_emb[Bc * STKc * 16 * FCc];
__device__ float g_stack_emb[Bc * STKc * FCc];

__device__ float g_zx0[Bc * STKc  * 1024];
__device__ float g_zx1[Bc * BUFFc * 1024];
__device__ float g_zx2[Bc * HISTc * 1024];

__device__ float g_p [3][2][Bc * 1024];
__device__ float g_c0[3][Bc * Uc];
__device__ float g_c1[3][Bc * Uc];
__device__ float g_h0[3][2][Bc * Uc];
__device__ float g_h1[3][2][Bc * Uc];

__device__ int g_perm[3][Bc];
__device__ int g_inv [3][Bc];
__device__ int g_lens[3][Bc];
__device__ int g_cnt [3][HISTc];

__device__ unsigned g_bar;

__device__ __forceinline__ float sigm(float x) {
    return __fdividef(1.0f, 1.0f + __expf(-x));
}
__device__ __forceinline__ float tanh_(float x) {
    return __fdividef(2.0f, 1.0f + __expf(-2.0f * x)) - 1.0f;
}

// ---------------- per-LSTM length sort (stable, descending) ----------------
__global__ void sort_kernel(const int* len0, const int* len1, const int* len2) {
    const int L = blockIdx.x;
    const int* len = (L == 0) ? len0 : (L == 1) ? len1 : len2;
    const int T = (L == 0) ? STKc : (L == 1) ? BUFFc : HISTc;
    __shared__ int sl[Bc];
    const int tid = threadIdx.x;
    sl[tid] = len[tid];
    __syncthreads();
    const int myl = sl[tid];
    int rank = 0;
    for (int b = 0; b < Bc; b++) {
        const int lb = sl[b];
        rank += (lb > myl) || (lb == myl && b < tid);
    }
    g_perm[L][rank] = tid;
    g_inv[L][tid] = rank;
    g_lens[L][rank] = myl;
    if (tid < T) {
        int c = 0;
        for (int b = 0; b < Bc; b++) c += (sl[b] > tid);
        g_cnt[L][tid] = c;
    }
}

// ---------------- persistent fused LSTM loop ----------------
// xs tile now [k][m] (pad 36): compute reads x as LDS.128 across m.
struct PParams {
    const float* W0h[3];
    const float* b0[3];
    const float* W1a[3];
    const float* W1b[3];
    const float* b1[3];
};

__global__ void __launch_bounds__(256, 2) lstm_loop_kernel(PParams P) {
    const int tid = threadIdx.x;
    const int bid = blockIdx.x;

    __shared__ __align__(16) float xs[2][32][36];         // [buf][k][m]
    __shared__ __align__(16) float ws_raw[2 * 32 * 128];
#define WS(bf,k,c) ws_raw[(bf) * 4096 + (k) * 128 + (c)]

    const int mi = tid & 7,  ni = tid >> 3;
    const int m0 = mi * 4,   n0t = ni * 4;
    const int xm = tid >> 3;
    const int xk = (tid & 7) * 4;
    const int wk = tid >> 5;
    const int wc4 = tid & 31;

    for (int i = 0; i < NITER; i++) {
        const int pr = (i + 1) & 1;
        const int pw = i & 1;

        int sfound = -1, local = 0, off = 0;
#pragma unroll
        for (int s = 0; s < 9; s++) {
            const int Ls = s / 3, kind = s - Ls * 3;
            const int Ts = (Ls == 0) ? STKc : (Ls == 1) ? BUFFc : HISTc;
            const int ts = i - kind;
            int nb = 0;
            if (ts >= 0 && ts < Ts) {
                const int cc = g_cnt[Ls][ts];
                nb = (cc + 31) >> 5;
            }
            const int items = nb * 8;
            if (sfound < 0 && bid >= off && bid < off + items) {
                sfound = s; local = bid - off;
            }
            off += items;
        }

        if (sfound >= 0) {
            const int L = sfound / 3, kind = sfound - L * 3;
            const int Ts = (L == 0) ? STKc : (L == 1) ? BUFFc : HISTc;
            const int t = i - kind;
            const int bm = local >> 3, bu = local & 7;
            const int b0r = bm * 32;
            const int u0 = bu * 32;
            const int gcol = (wc4 >> 3) * 256 + u0 + (wc4 & 7) * 4;

            const float* src;
            const float* W;
            const float* extra = nullptr;
            const float* bias = nullptr;
            float* c = nullptr;
            float* h_out = nullptr;
            float* p_out = nullptr;
            bool gates;
            if (kind == 0) {
                gates = true;
                src = &g_h0[L][pr][0];
                W = P.W0h[L];
                bias = P.b0[L];
                c = &g_c0[L][0];
                h_out = &g_h0[L][pw][0];
            } else if (kind == 1) {
                gates = false;
                src = &g_h0[L][pr][0];
                W = P.W1a[L];
                p_out = &g_p[L][pr][0];
            } else {
                gates = true;
                src = &g_h1[L][pr][0];
                W = P.W1b[L];
                extra = &g_p[L][pw][0];
                bias = P.b1[L];
                c = &g_c1[L][0];
                h_out = &g_h1[L][pw][0];
            }

            float acc[4][4];
#pragma unroll
            for (int a = 0; a < 4; a++)
#pragma unroll
                for (int b = 0; b < 4; b++) acc[a][b] = 0.0f;

            const float* srow = src + (b0r + xm) * Uc;

            {
                float4 xv = __ldcg((const float4*)(srow + xk));
                xs[0][xk + 0][xm] = xv.x; xs[0][xk + 1][xm] = xv.y;
                xs[0][xk + 2][xm] = xv.z; xs[0][xk + 3][xm] = xv.w;
#pragma unroll
                for (int q = 0; q < 4; q++) {
                    const int kk = wk + 8 * q;
                    *(float4*)&WS(0, kk, wc4 * 4) =
                        *(const float4*)(W + (size_t)kk * 1024 + gcol);
                }
            }
            __syncthreads();

            int buf = 0;
#pragma unroll 1
            for (int kt = 0; kt < 8; kt++) {
                float4 xv, wv0, wv1, wv2, wv3;
                const bool more = (kt < 7);
                if (more) {
                    const int k0 = (kt + 1) * 32;
                    xv = __ldcg((const float4*)(srow + k0 + xk));
                    const float* wrow = W + (size_t)(k0 + wk) * 1024 + gcol;
                    wv0 = *(const float4*)(wrow);
                    wv1 = *(const float4*)(wrow +  8 * 1024);
                    wv2 = *(const float4*)(wrow + 16 * 1024);
                    wv3 = *(const float4*)(wrow + 24 * 1024);
                }

                const float (*xsb)[36] = xs[buf];
#pragma unroll
                for (int kk = 0; kk < 32; kk++) {
                    const float4 x = *(const float4*)&xsb[kk][m0];
                    const float4 w = *(const float4*)&WS(buf, kk, n0t);
                    acc[0][0] = fmaf(x.x, w.x, acc[0][0]);
                    acc[0][1] = fmaf(x.x, w.y, acc[0][1]);
                    acc[0][2] = fmaf(x.x, w.z, acc[0][2]);
                    acc[0][3] = fmaf(x.x, w.w, acc[0][3]);
                    acc[1][0] = fmaf(x.y, w.x, acc[1][0]);
                    acc[1][1] = fmaf(x.y, w.y, acc[1][1]);
                    acc[1][2] = fmaf(x.y, w.z, acc[1][2]);
                    acc[1][3] = fmaf(x.y, w.w, acc[1][3]);
                    acc[2][0] = fmaf(x.z, w.x, acc[2][0]);
                    acc[2][1] = fmaf(x.z, w.y, acc[2][1]);
                    acc[2][2] = fmaf(x.z, w.z, acc[2][2]);
                    acc[2][3] = fmaf(x.z, w.w, acc[2][3]);
                    acc[3][0] = fmaf(x.w, w.x, acc[3][0]);
                    acc[3][1] = fmaf(x.w, w.y, acc[3][1]);
                    acc[3][2] = fmaf(x.w, w.z, acc[3][2]);
                    acc[3][3] = fmaf(x.w, w.w, acc[3][3]);
                }

                if (more) {
                    const int nb2 = buf ^ 1;
                    xs[nb2][xk + 0][xm] = xv.x; xs[nb2][xk + 1][xm] = xv.y;
                    xs[nb2][xk + 2][xm] = xv.z; xs[nb2][xk + 3][xm] = xv.w;
                    *(float4*)&WS(nb2, wk +  0, wc4 * 4) = wv0;
                    *(float4*)&WS(nb2, wk +  8, wc4 * 4) = wv1;
                    *(float4*)&WS(nb2, wk + 16, wc4 * 4) = wv2;
                    *(float4*)&WS(nb2, wk + 24, wc4 * 4) = wv3;
                    __syncthreads();
                    buf = nb2;
                }
            }

            if (!gates) {
                const int gcolS = (n0t >> 5) * 256 + u0 + (n0t & 31);
#pragma unroll
                for (int a = 0; a < 4; a++) {
                    __stcg((float4*)(p_out + (size_t)(b0r + m0 + a) * 1024 + gcolS),
                           make_float4(acc[a][0], acc[a][1], acc[a][2], acc[a][3]));
                }
            } else {
                __syncthreads();
                float* zt = ws_raw;
#pragma unroll
                for (int cc = 0; cc < 4; cc++)
#pragma unroll
                    for (int a = 0; a < 4; a++)
                        zt[(n0t + cc) * 33 + (m0 + a)] = acc[a][cc];
                __syncthreads();

                const int uu = tid & 31;
                const int bq = tid >> 5;
                const int colu = u0 + uu;
                const float bi = bias[colu];
                const float bj = bias[256 + colu];
                const float bf = bias[512 + colu];
                const float bo = bias[768 + colu];
                const float* zxbase = (L == 0) ? g_zx0 : (L == 1) ? g_zx1 : g_zx2;

#pragma unroll
                for (int q = 0; q < 4; q++) {
                    const int bl = bq + 8 * q;
                    const int j = b0r + bl;
                    if (t < g_lens[L][j]) {
                        const float* er;
                        if (kind == 0)
                            er = zxbase + ((size_t)g_perm[L][j] * Ts + t) * 1024;
                        else
                            er = extra + (size_t)j * 1024;
                        const int gidx = j * Uc + colu;
                        float g0 = zt[(  0 + uu) * 33 + bl] + bi + __ldcg(&er[colu]);
                        float g1 = zt[( 32 + uu) * 33 + bl] + bj + __ldcg(&er[256 + colu]);
                        float g2 = zt[( 64 + uu) * 33 + bl] + bf + __ldcg(&er[512 + colu]);
                        float g3 = zt[( 96 + uu) * 33 + bl] + bo + __ldcg(&er[768 + colu]);
                        const float cn = __ldcg(&c[gidx]) * sigm(g2 + 1.0f)
                                       + sigm(g0) * tanh_(g1);
                        const float hn = tanh_(cn) * sigm(g3);
                        __stcg(&c[gidx], cn);
                        __stcg(&h_out[gidx], hn);
                    }
                }
            }
        }

        __syncthreads();
        __threadfence();
        if (tid == 0) {
            atomicAdd(&g_bar, 1u);
            const unsigned target = (unsigned)NBLK * (unsigned)(i + 1);
            volatile unsigned* vb = &g_bar;
            while (*vb < target) __nanosleep(32);
        }
        __syncthreads();
    }
#undef WS
}

// ---------------- x-projection precompute ([k][m] x tile, masked-block skip) ----------------
struct XJob { const float* x; const int* ids; const float* tab;
              const float* W; float* zx; const int* len; int rows, Din, T; };
struct XJobs { XJob j[3]; };

__global__ void xproj_kernel(XJobs jobs) {
    const XJob J = jobs.j[blockIdx.y];
    const int bm = blockIdx.x % 384;
    const int bn = blockIdx.x / 384;
    const int r0 = bm * 32;
    if (r0 >= J.rows) return;
    const int tid = threadIdx.x;

    int pred = 0;
    if (tid < 32) {
        const int r = r0 + tid;
        const int bb = r / J.T;
        const int tt = r - bb * J.T;
        pred = (tt < J.len[bb]);
    }
    if (!__syncthreads_or(pred)) return;

    const int n0 = bn * 128;
    __shared__ __align__(16) float xs[32][36];     // [k][m]
    __shared__ __align__(16) float ws[32][128];
    const int mi = tid & 7, ni = tid >> 3;
    const int m0 = mi * 4, n0t = ni * 4;
    const int xm = tid >> 3, xk = (tid & 7) * 4;
    const int wc = (tid & 31) * 4, wk = tid >> 5;

    float acc[4][4];
#pragma unroll
    for (int a = 0; a < 4; a++)
#pragma unroll
        for (int b = 0; b < 4; b++) acc[a][b] = 0.0f;

    const int r = r0 + xm;
    const float* srow = J.ids ? (J.tab + (size_t)J.ids[r] * J.Din)
                              : (J.x + (size_t)r * J.Din);

    const int nk = (J.Din + 31) >> 5;
    for (int kt = 0; kt < nk; kt++) {
        const int k0 = kt * 32;
        __syncthreads();
#pragma unroll
        for (int j = 0; j < 4; j++) {
            const int k = k0 + xk + j;
            xs[xk + j][xm] = (k < J.Din) ? srow[k] : 0.0f;
        }
#pragma unroll
        for (int q = 0; q < 4; q++) {
            const int kk = wk + 8 * q, k = k0 + kk;
            float4 wv = make_float4(0.f, 0.f, 0.f, 0.f);
            if (k < J.Din)
                wv = *(const float4*)(J.W + (size_t)k * 1024 + n0 + wc);
            *(float4*)&ws[kk][wc] = wv;
        }
        __syncthreads();
#pragma unroll 8
        for (int kk = 0; kk < 32; kk++) {
            const float4 x = *(const float4*)&xs[kk][m0];
            const float4 w = *(const float4*)&ws[kk][n0t];
            acc[0][0] = fmaf(x.x, w.x, acc[0][0]);
            acc[0][1] = fmaf(x.x, w.y, acc[0][1]);
            acc[0][2] = fmaf(x.x, w.z, acc[0][2]);
            acc[0][3] = fmaf(x.x, w.w, acc[0][3]);
            acc[1][0] = fmaf(x.y, w.x, acc[1][0]);
            acc[1][1] = fmaf(x.y, w.y, acc[1][1]);
            acc[1][2] = fmaf(x.y, w.z, acc[1][2]);
            acc[1][3] = fmaf(x.y, w.w, acc[1][3]);
            acc[2][0] = fmaf(x.z, w.x, acc[2][0]);
            acc[2][1] = fmaf(x.z, w.y, acc[2][1]);
            acc[2][2] = fmaf(x.z, w.z, acc[2][2]);
            acc[2][3] = fmaf(x.z, w.w, acc[2][3]);
            acc[3][0] = fmaf(x.w, w.x, acc[3][0]);
            acc[3][1] = fmaf(x.w, w.y, acc[3][1]);
            acc[3][2] = fmaf(x.w, w.z, acc[3][2]);
            acc[3][3] = fmaf(x.w, w.w, acc[3][3]);
        }
    }
#pragma unroll
    for (int a = 0; a < 4; a++) {
        *(float4*)(J.zx + (size_t)(r0 + m0 + a) * 1024 + n0 + n0t) =
            make_float4(acc[a][0], acc[a][1], acc[a][2], acc[a][3]);
    }
}

// ---------------- embedding (dead-block skip) ----------------
__global__ void embed_kernel(const int* __restrict__ word_ids,
                             const int* __restrict__ pos_ids,
                             const float* __restrict__ w_emb,
                             const float* __restrict__ p_emb,
                             const float* __restrict__ W,
                             const float* __restrict__ bias,
                             float* __restrict__ out,
                             int nrows,
                             const int* __restrict__ len,
                             int per_b, int per_item) {
    const int r0 = blockIdx.x * 8;
    {
        const int b = r0 / per_b;
        const int item = (r0 - b * per_b) / per_item;
        if (item >= len[b]) return;
    }
    __shared__ float xs[8][EDINc];
    __shared__ int wid_s[8], pid_s[8];
    const int tid = threadIdx.x;

    if (tid < 8) {
        int row = r0 + tid;
        wid_s[tid] = (row < nrows) ? word_ids[row] : 0;
        pid_s[tid] = (row < nrows) ? pos_ids[row] : 0;
    }
    __syncthreads();

    for (int idx = tid; idx < 8 * EDINc; idx += 128) {
        int r = idx / EDINc, k = idx - r * EDINc;
        float v;
        if (k < WDIMc) v = w_emb[wid_s[r] * WDIMc + k];
        else           v = p_emb[pid_s[r] * POSDc + (k - WDIMc)];
        xs[r][k] = v;
    }
    __syncthreads();

    float acc[8];
    const float bj = bias[tid];
#pragma unroll
    for (int r = 0; r < 8; r++) acc[r] = bj;

#pragma unroll 2
    for (int k = 0; k < EDINc; k++) {
        float w = W[k * FCc + tid];
#pragma unroll
        for (int r = 0; r < 8; r++) acc[r] = fmaf(xs[r][k], w, acc[r]);
    }
#pragma unroll
    for (int r = 0; r < 8; r++) {
        int row = r0 + r;
        if (row < nrows) out[row * FCc + tid] = fmaxf(acc[r], 0.0f);
    }
}

// ---------------- compose v3: mini-GEMM with depth-4 W prefetch ----------------
__global__ void __launch_bounds__(128) compose_kernel(
    const int* __restrict__ comp_word_id,
    const float* __restrict__ comp_emb,
    const int* __restrict__ comp_action_id,
    const int* __restrict__ comp_action_len,
    const float* __restrict__ a_emb,
    const float* __restrict__ rec_W,
    const float* __restrict__ rec_b,
    const int* __restrict__ stack_len,
    float* __restrict__ stack_emb)
{
    const int seq0 = blockIdx.x * CSEQ;
    {
        const int b = seq0 / STKc;
        const int stk0 = seq0 - b * STKc;
        if (stk0 >= stack_len[b]) return;
    }
    const int tid = threadIdx.x;

    __shared__ float vals[8][CSEQ][FCc];
    __shared__ __align__(16) float xs[RDINc][10];
    __shared__ int wid[CSEQ][16];
    __shared__ int act[CSEQ][8];
    __shared__ int alen[CSEQ];
    __shared__ signed char ihs[CSEQ][8], idds[CSEQ][8];

    {
        const int ss = tid >> 4, slot = tid & 15;
        wid[ss][slot] = comp_word_id[(seq0 + ss) * 16 + slot];
        if (tid < CSEQ * 8) {
            const int s2 = tid >> 3, n = tid & 7;
            act[s2][n] = comp_action_id[(seq0 + s2) * 8 + n];
        }
        if (tid < CSEQ) alen[tid] = comp_action_len[seq0 + tid];
    }
    __syncthreads();
    if (tid < CSEQ * 8) {
        const int ss = tid >> 3, n = tid & 7;
        const int hn = wid[ss][2 * n], dn = wid[ss][2 * n + 1];
        int ih = -1, idd = -1;
        for (int m = 0; m < n; m++) {
            const int hm = wid[ss][2 * m];
            if (hm == hn) ih = m;
            if (hm == dn) idd = m;
        }
        ihs[ss][n] = (signed char)ih;
        idds[ss][n] = (signed char)idd;
    }
    __syncthreads();

    const int mi = tid & 3,  ni = tid >> 2;
    const int s0 = mi * 2,   n0 = ni * 4;
    const float4 bn = *(const float4*)(rec_b + n0);
    const float* Wn = rec_W + n0;

    for (int n = 0; n < 8; n++) {
        // ---- stage X[k][s] ----
#pragma unroll
        for (int ss = 0; ss < CSEQ; ss++) {
            const int ih = ihs[ss][n], idd = idds[ss][n];
            const int an = act[ss][n];
#pragma unroll
            for (int j = 0; j < 3; j++) {
                const int k = tid + j * 128;
                if (k < RDINc) {
                    float v;
                    if (k < FCc) {
                        v = (ih >= 0) ? vals[ih][ss][k]
                                      : comp_emb[((size_t)(seq0 + ss) * 16 + 2 * n) * FCc + k];
                    } else if (k < FCc + CADc) {
                        v = a_emb[an * CADc + (k - FCc)];
                    } else {
                        const int kk = k - (FCc + CADc);
                        v = (idd >= 0) ? vals[idd][ss][kk]
                                       : comp_emb[((size_t)(seq0 + ss) * 16 + 2 * n + 1) * FCc + kk];
                    }
                    xs[k][ss] = v;
                }
            }
        }
        __syncthreads();

        // ---- mini-GEMM with depth-4 W prefetch (MLP=4) ----
        float a00 = 0.f, a01 = 0.f, a02 = 0.f, a03 = 0.f;
        float a10 = 0.f, a11 = 0.f, a12 = 0.f, a13 = 0.f;

        float4 w0 = *(const float4*)(Wn + 0 * FCc);
        float4 w1 = *(const float4*)(Wn + 1 * FCc);
        float4 w2 = *(const float4*)(Wn + 2 * FCc);
        float4 w3 = *(const float4*)(Wn + 3 * FCc);
#pragma unroll 1
        for (int k = 0; k < 304; k += 4) {
            float4 p0, p1, p2, p3;
            if (k + 7 < RDINc) {
                p0 = *(const float4*)(Wn + (size_t)(k + 4) * FCc);
                p1 = *(const float4*)(Wn + (size_t)(k + 5) * FCc);
                p2 = *(const float4*)(Wn + (size_t)(k + 6) * FCc);
                p3 = *(const float4*)(Wn + (size_t)(k + 7) * FCc);
            } else {
                p0 = (k + 4 < RDINc) ? *(const float4*)(Wn + (size_t)(k + 4) * FCc) : w0;
                p1 = (k + 5 < RDINc) ? *(const float4*)(Wn + (size_t)(k + 5) * FCc) : w1;
                p2 = p2; p3 = p3;
                p2 = w2; p3 = w3;
            }
            const float2 x0 = *(const float2*)&xs[k + 0][s0];
            const float2 x1 = *(const float2*)&xs[k + 1][s0];
            const float2 x2 = *(const float2*)&xs[k + 2][s0];
            const float2 x3 = *(const float2*)&xs[k + 3][s0];
            a00 = fmaf(x0.x, w0.x, a00); a01 = fmaf(x0.x, w0.y, a01);
            a02 = fmaf(x0.x, w0.z, a02); a03 = fmaf(x0.x, w0.w, a03);
            a10 = fmaf(x0.y, w0.x, a10); a11 = fmaf(x0.y, w0.y, a11);
            a12 = fmaf(x0.y, w0.z, a12); a13 = fmaf(x0.y, w0.w, a13);
            a00 = fmaf(x1.x, w1.x, a00); a01 = fmaf(x1.x, w1.y, a01);
            a02 = fmaf(x1.x, w1.z, a02); a03 = fmaf(x1.x, w1.w, a03);
            a10 = fmaf(x1.y, w1.x, a10); a11 = fmaf(x1.y, w1.y, a11);
            a12 = fmaf(x1.y, w1.z, a12); a13 = fmaf(x1.y, w1.w, a13);
            a00 = fmaf(x2.x, w2.x, a00); a01 = fmaf(x2.x, w2.y, a01);
            a02 = fmaf(x2.x, w2.z, a02); a03 = fmaf(x2.x, w2.w, a03);
            a10 = fmaf(x2.y, w2.x, a10); a11 = fmaf(x2.y, w2.y, a11);
            a12 = fmaf(x2.y, w2.z, a12); a13 = fmaf(x2.y, w2.w, a13);
            a00 = fmaf(x3.x, w3.x, a00); a01 = fmaf(x3.x, w3.y, a01);
            a02 = fmaf(x3.x, w3.z, a02); a03 = fmaf(x3.x, w3.w, a03);
            a10 = fmaf(x3.y, w3.x, a10); a11 = fmaf(x3.y, w3.y, a11);
            a12 = fmaf(x3.y, w3.z, a12); a13 = fmaf(x3.y, w3.w, a13);
            w0 = p0; w1 = p1; w2 = p2; w3 = p3;
        }
        // tail: k = 304, 305 (w0, w1 hold their prefetched rows)
        {
            const float2 x0 = *(const float2*)&xs[304][s0];
            const float2 x1 = *(const float2*)&xs[305][s0];
            a00 = fmaf(x0.x, w0.x, a00); a01 = fmaf(x0.x, w0.y, a01);
            a02 = fmaf(x0.x, w0.z, a02); a03 = fmaf(x0.x, w0.w, a03);
            a10 = fmaf(x0.y, w0.x, a10); a11 = fmaf(x0.y, w0.y, a11);
            a12 = fmaf(x0.y, w0.z, a12); a13 = fmaf(x0.y, w0.w, a13);
            a00 = fmaf(x1.x, w1.x, a00); a01 = fmaf(x1.x, w1.y, a01);
            a02 = fmaf(x1.x, w1.z, a02); a03 = fmaf(x1.x, w1.w, a03);
            a10 = fmaf(x1.y, w1.x, a10); a11 = fmaf(x1.y, w1.y, a11);
            a12 = fmaf(x1.y, w1.z, a12); a13 = fmaf(x1.y, w1.w, a13);
        }

        *(float4*)&vals[n][s0 + 0][n0] = make_float4(
            tanhf(a00 + bn.x), tanhf(a01 + bn.y), tanhf(a02 + bn.z), tanhf(a03 + bn.w));
        *(float4*)&vals[n][s0 + 1][n0] = make_float4(
            tanhf(a10 + bn.x), tanhf(a11 + bn.y), tanhf(a12 + bn.z), tanhf(a13 + bn.w));
        __syncthreads();
    }

#pragma unroll
    for (int ss = 0; ss < CSEQ; ss++) {
        const int al = alen[ss];
        const float v = (al == 0)
            ? comp_emb[(size_t)(seq0 + ss) * 16 * FCc + tid]
            : vals[al - 1][ss][tid];
        stack_emb[(size_t)(seq0 + ss) * FCc + tid] = v;
    }
}

// ---------------- output head ----------------
__global__ void final_kernel(const int* __restrict__ l0,
                             const int* __restrict__ l1,
                             const int* __restrict__ l2,
                             const float* __restrict__ fW,
                             const float* __restrict__ fb,
                             float* __restrict__ out) {
    const int b = blockIdx.x;
    const int tid = threadIdx.x;
    __shared__ float hcat[3 * Uc];
    for (int idx = tid; idx < 3 * Uc; idx += 128) {
        const int L = idx >> 8;
        const int col = idx & 255;
        const int len = ((L == 0) ? l0 : (L == 1) ? l1 : l2)[b];
        const int j = g_inv[L][b];
        hcat[idx] = g_h1[L][(len - 1) & 1][j * Uc + col];
    }
    __syncthreads();
    if (tid < NOUTc) {
        float acc = fb[tid];
#pragma unroll 2
        for (int k = 0; k < 3 * Uc; k++) acc = fmaf(hcat[k], fW[k * NOUTc + tid], acc);
        out[b * NOUTc + tid] = acc;
    }
}

// ---------------- host driver ----------------
extern "C" void kernel_launch(void* const* d_in, const int* in_sizes, int n_in,
                              void* d_out, int out_size) {
    const int*   buff_word_id   = (const int*)d_in[0];
    const int*   buff_pos_id    = (const int*)d_in[1];
    const int*   comp_word_id   = (const int*)d_in[2];
    const int*   comp_pos_id    = (const int*)d_in[3];
    const int*   comp_action_id = (const int*)d_in[4];
    const int*   comp_action_len= (const int*)d_in[5];
    const int*   history_action_id = (const int*)d_in[6];
    const int*   stack_length   = (const int*)d_in[7];
    const int*   buff_length    = (const int*)d_in[8];
    const int*   history_action_length = (const int*)d_in[9];
    const float* p_emb      = (const float*)d_in[10];
    const float* comp_a_emb = (const float*)d_in[11];
    const float* hist_a_emb = (const float*)d_in[12];
    const float* w_emb      = (const float*)d_in[13];
    const float* emb_W      = (const float*)d_in[14];
    const float* emb_b      = (const float*)d_in[15];
    const float* rec_W      = (const float*)d_in[16];
    const float* rec_b      = (const float*)d_in[17];
    const float* W0s[3] = { (const float*)d_in[18], (const float*)d_in[22], (const float*)d_in[26] };
    const float* b0s[3] = { (const float*)d_in[19], (const float*)d_in[23], (const float*)d_in[27] };
    const float* W1s[3] = { (const float*)d_in[20], (const float*)d_in[24], (const float*)d_in[28] };
    const float* b1s[3] = { (const float*)d_in[21], (const float*)d_in[25], (const float*)d_in[29] };
    const float* fW  = (const float*)d_in[30];
    const float* fb  = (const float*)d_in[31];
    float* out = (float*)d_out;

    float *buff_emb_p, *comp_emb_p, *stack_emb_p;
    float *zx0_p, *zx1_p, *zx2_p;
    float *c0_p, *c1_p, *h0_p, *h1_p;
    unsigned* bar_p;
    cudaGetSymbolAddress((void**)&buff_emb_p,  g_buff_emb);
    cudaGetSymbolAddress((void**)&comp_emb_p,  g_comp_emb);
    cudaGetSymbolAddress((void**)&stack_emb_p, g_stack_emb);
    cudaGetSymbolAddress((void**)&zx0_p, g_zx0);
    cudaGetSymbolAddress((void**)&zx1_p, g_zx1);
    cudaGetSymbolAddress((void**)&zx2_p, g_zx2);
    cudaGetSymbolAddress((void**)&c0_p, g_c0);
    cudaGetSymbolAddress((void**)&c1_p, g_c1);
    cudaGetSymbolAddress((void**)&h0_p, g_h0);
    cudaGetSymbolAddress((void**)&h1_p, g_h1);
    cudaGetSymbolAddress((void**)&bar_p, g_bar);

    const size_t SB = (size_t)Bc * Uc;

    cudaMemsetAsync(bar_p, 0, sizeof(unsigned));
    cudaMemsetAsync(c0_p, 0, 3 * SB * sizeof(float));
    cudaMemsetAsync(c1_p, 0, 3 * SB * sizeof(float));
    cudaMemsetAsync(h0_p, 0, 3 * 2 * SB * sizeof(float));
    cudaMemsetAsync(h1_p, 0, 3 * 2 * SB * sizeof(float));

    // length sort + per-step active counts
    sort_kernel<<<3, 128>>>(stack_length, buff_length, history_action_length);

    // embeddings (dead-block skipping)
    const int nbuff = Bc * BUFFc;
    embed_kernel<<<(nbuff + 7) / 8, 128>>>(buff_word_id, buff_pos_id, w_emb, p_emb,
                                           emb_W, emb_b, buff_emb_p, nbuff,
                                           buff_length, BUFFc, 1);
    const int ncomp = Bc * STKc * 16;
    embed_kernel<<<(ncomp + 7) / 8, 128>>>(comp_word_id, comp_pos_id, w_emb, p_emb,
                                           emb_W, emb_b, comp_emb_p, ncomp,
                                           stack_length, STKc * 16, 16);

    // recursive compose
    compose_kernel<<<Bc * STKc / CSEQ, 128>>>(comp_word_id, comp_emb_p,
                                              comp_action_id, comp_action_len,
                                              comp_a_emb, rec_W, rec_b,
                                              stack_length, stack_emb_p);

    // x-projections for layer0
    {
        XJobs xj;
        xj.j[0] = XJob{ stack_emb_p, nullptr, nullptr, W0s[0], zx0_p,
                        stack_length, Bc * STKc,  FCc, STKc };
        xj.j[1] = XJob{ buff_emb_p,  nullptr, nullptr, W0s[1], zx1_p,
                        buff_length, Bc * BUFFc, FCc, BUFFc };
        xj.j[2] = XJob{ nullptr, history_action_id, hist_a_emb, W0s[2], zx2_p,
                        history_action_length, Bc * HISTc, 50, HISTc };
        xproj_kernel<<<dim3(384 * 8, 3), 256>>>(xj);
    }

    // persistent fused loop
    {
        PParams P;
        for (int L = 0; L < 3; L++) {
            const int din = (L == 2) ? 50 : FCc;
            P.W0h[L] = W0s[L] + (size_t)din * 1024;
            P.b0[L]  = b0s[L];
            P.W1a[L] = W1s[L];
            P.W1b[L] = W1s[L] + (size_t)256 * 1024;
            P.b1[L]  = b1s[L];
        }
        lstm_loop_kernel<<<NBLK, 256>>>(P);
    }

    // output head
    final_kernel<<<Bc, 128>>>(stack_length, buff_length, history_action_length,
                              fW, fb, out);
}

// round 12
// speedup vs baseline: 1.7981x; 1.0277x over previous
#include <cuda_runtime.h>
#include <math.h>

// ---------------- problem constants ----------------
#define Bc    128
#define BUFFc 64
#define STKc  48
#define HISTc 96
#define FCc   128
#define Uc    256
#define NOUTc 82
#define WDIMc 300
#define POSDc 50
#define EDINc 350
#define CADc  50
#define RDINc 306
#define NBLK  576
#define NITER 98
#define CSEQ  8
#define WST   68

// ---------------- device scratch ----------------
__device__ float g_buff_emb[Bc * BUFFc * FCc];
__device__ float g_comp_emb[Bc * STKc * 16 * FCc];
__device__ float g_stack_emb[Bc * STKc * FCc];

__device__ float g_zx0[Bc * STKc  * 1024];
__device__ float g_zx1[Bc * BUFFc * 1024];
__device__ float g_zx2[Bc * HISTc * 1024];

__device__ float g_p [3][2][Bc * 1024];
__device__ float g_c0[3][Bc * Uc];
__device__ float g_c1[3][Bc * Uc];
__device__ float g_h0[3][2][Bc * Uc];
__device__ float g_h1[3][2][Bc * Uc];

__device__ int g_perm[3][Bc];
__device__ int g_inv [3][Bc];
__device__ int g_lens[3][Bc];
__device__ int g_cnt [3][HISTc];

__device__ unsigned g_bar;

__device__ __forceinline__ float sigm(float x) {
    return __fdividef(1.0f, 1.0f + __expf(-x));
}
__device__ __forceinline__ float tanh_(float x) {
    return __fdividef(2.0f, 1.0f + __expf(-2.0f * x)) - 1.0f;
}

// ---------------- per-LSTM length sort (stable, descending) ----------------
__global__ void sort_kernel(const int* len0, const int* len1, const int* len2) {
    const int L = blockIdx.x;
    const int* len = (L == 0) ? len0 : (L == 1) ? len1 : len2;
    const int T = (L == 0) ? STKc : (L == 1) ? BUFFc : HISTc;
    __shared__ int sl[Bc];
    const int tid = threadIdx.x;
    sl[tid] = len[tid];
    __syncthreads();
    const int myl = sl[tid];
    int rank = 0;
    for (int b = 0; b < Bc; b++) {
        const int lb = sl[b];
        rank += (lb > myl) || (lb == myl && b < tid);
    }
    g_perm[L][rank] = tid;
    g_inv[L][tid] = rank;
    g_lens[L][rank] = myl;
    if (tid < T) {
        int c = 0;
        for (int b = 0; b < Bc; b++) c += (sl[b] > tid);
        g_cnt[L][tid] = c;
    }
}

// ---------------- persistent fused LSTM loop: fine-grained 128-thr blocks ----------------
// Work item = (unit, b-tile of 32, u-tile of 16). Block tile = 32b x 64 z-cols
// (16u x 4 gates). Max items = 9*4*16 = 576 = NBLK (all resident at 4/SM).
struct PParams {
    const float* W0h[3];
    const float* b0[3];
    const float* W1a[3];
    const float* W1b[3];
    const float* b1[3];
};

__global__ void __launch_bounds__(128, 4) lstm_loop_kernel(PParams P) {
    const int tid = threadIdx.x;
    const int bid = blockIdx.x;

    __shared__ __align__(16) float xs[2][32][36];          // [buf][k][m]
    __shared__ __align__(16) float ws_raw[2 * 32 * WST];   // [buf][k][c] (64 cols pad WST)
#define WS(bf,k,c) ws_raw[(bf) * (32 * WST) + (k) * WST + (c)]

    const int mi = tid & 7,  ni = tid >> 3;      // 8 m-tiles x 16 c-tiles
    const int m0 = mi * 4,   n0t = ni * 4;       // n0t in [0,64)
    const int xm = tid >> 2;                      // 0..31
    const int xk4 = (tid & 3) * 4;                // x float4 offsets: xk4, xk4+16
    const int wk = tid >> 4;                      // 0..7
    const int wc4 = tid & 15;                     // 16 float4 col slots

    for (int i = 0; i < NITER; i++) {
        const int pr = (i + 1) & 1;
        const int pw = i & 1;

        // ---- schedule: map bid -> (unit, tile) ----
        int sfound = -1, local = 0, off = 0;
#pragma unroll
        for (int s = 0; s < 9; s++) {
            const int Ls = s / 3, kind = s - Ls * 3;
            const int Ts = (Ls == 0) ? STKc : (Ls == 1) ? BUFFc : HISTc;
            const int ts = i - kind;
            int nb = 0;
            if (ts >= 0 && ts < Ts) {
                const int cc = g_cnt[Ls][ts];
                nb = (cc + 31) >> 5;
            }
            const int items = nb * 16;
            if (sfound < 0 && bid >= off && bid < off + items) {
                sfound = s; local = bid - off;
            }
            off += items;
        }

        if (sfound >= 0) {
            const int L = sfound / 3, kind = sfound - L * 3;
            const int Ts = (L == 0) ? STKc : (L == 1) ? BUFFc : HISTc;
            const int t = i - kind;
            const int bm = local >> 4, bu = local & 15;
            const int b0r = bm * 32;
            const int u0 = bu * 16;
            const int gcol = (wc4 >> 2) * 256 + u0 + (wc4 & 3) * 4;

            const float* src;
            const float* W;
            const float* extra = nullptr;
            const float* bias = nullptr;
            float* c = nullptr;
            float* h_out = nullptr;
            float* p_out = nullptr;
            bool gates;
            if (kind == 0) {
                gates = true;
                src = &g_h0[L][pr][0];
                W = P.W0h[L];
                bias = P.b0[L];
                c = &g_c0[L][0];
                h_out = &g_h0[L][pw][0];
            } else if (kind == 1) {
                gates = false;
                src = &g_h0[L][pr][0];
                W = P.W1a[L];
                p_out = &g_p[L][pr][0];
            } else {
                gates = true;
                src = &g_h1[L][pr][0];
                W = P.W1b[L];
                extra = &g_p[L][pw][0];
                bias = P.b1[L];
                c = &g_c1[L][0];
                h_out = &g_h1[L][pw][0];
            }

            float acc[4][4];
#pragma unroll
            for (int a = 0; a < 4; a++)
#pragma unroll
                for (int b = 0; b < 4; b++) acc[a][b] = 0.0f;

            const float* srow = src + (b0r + xm) * Uc;

            // prologue: stage k-tile 0
            {
                float4 xa = __ldcg((const float4*)(srow + xk4));
                float4 xb = __ldcg((const float4*)(srow + xk4 + 16));
                xs[0][xk4 + 0][xm] = xa.x; xs[0][xk4 + 1][xm] = xa.y;
                xs[0][xk4 + 2][xm] = xa.z; xs[0][xk4 + 3][xm] = xa.w;
                xs[0][xk4 + 16][xm] = xb.x; xs[0][xk4 + 17][xm] = xb.y;
                xs[0][xk4 + 18][xm] = xb.z; xs[0][xk4 + 19][xm] = xb.w;
#pragma unroll
                for (int q = 0; q < 4; q++) {
                    const int kk = wk + 8 * q;
                    *(float4*)&WS(0, kk, wc4 * 4) =
                        *(const float4*)(W + (size_t)kk * 1024 + gcol);
                }
            }
            __syncthreads();

            int buf = 0;
#pragma unroll 1
            for (int kt = 0; kt < 8; kt++) {
                float4 xa, xb, wv0, wv1, wv2, wv3;
                const bool more = (kt < 7);
                if (more) {
                    const int k0 = (kt + 1) * 32;
                    xa = __ldcg((const float4*)(srow + k0 + xk4));
                    xb = __ldcg((const float4*)(srow + k0 + xk4 + 16));
                    const float* wrow = W + (size_t)(k0 + wk) * 1024 + gcol;
                    wv0 = *(const float4*)(wrow);
                    wv1 = *(const float4*)(wrow +  8 * 1024);
                    wv2 = *(const float4*)(wrow + 16 * 1024);
                    wv3 = *(const float4*)(wrow + 24 * 1024);
                }

                const float (*xsb)[36] = xs[buf];
#pragma unroll
                for (int kk = 0; kk < 32; kk++) {
                    const float4 x = *(const float4*)&xsb[kk][m0];
                    const float4 w = *(const float4*)&WS(buf, kk, n0t);
                    acc[0][0] = fmaf(x.x, w.x, acc[0][0]);
                    acc[0][1] = fmaf(x.x, w.y, acc[0][1]);
                    acc[0][2] = fmaf(x.x, w.z, acc[0][2]);
                    acc[0][3] = fmaf(x.x, w.w, acc[0][3]);
                    acc[1][0] = fmaf(x.y, w.x, acc[1][0]);
                    acc[1][1] = fmaf(x.y, w.y, acc[1][1]);
                    acc[1][2] = fmaf(x.y, w.z, acc[1][2]);
                    acc[1][3] = fmaf(x.y, w.w, acc[1][3]);
                    acc[2][0] = fmaf(x.z, w.x, acc[2][0]);
                    acc[2][1] = fmaf(x.z, w.y, acc[2][1]);
                    acc[2][2] = fmaf(x.z, w.z, acc[2][2]);
                    acc[2][3] = fmaf(x.z, w.w, acc[2][3]);
                    acc[3][0] = fmaf(x.w, w.x, acc[3][0]);
                    acc[3][1] = fmaf(x.w, w.y, acc[3][1]);
                    acc[3][2] = fmaf(x.w, w.z, acc[3][2]);
                    acc[3][3] = fmaf(x.w, w.w, acc[3][3]);
                }

                if (more) {
                    const int nb2 = buf ^ 1;
                    xs[nb2][xk4 + 0][xm] = xa.x; xs[nb2][xk4 + 1][xm] = xa.y;
                    xs[nb2][xk4 + 2][xm] = xa.z; xs[nb2][xk4 + 3][xm] = xa.w;
                    xs[nb2][xk4 + 16][xm] = xb.x; xs[nb2][xk4 + 17][xm] = xb.y;
                    xs[nb2][xk4 + 18][xm] = xb.z; xs[nb2][xk4 + 19][xm] = xb.w;
                    *(float4*)&WS(nb2, wk +  0, wc4 * 4) = wv0;
                    *(float4*)&WS(nb2, wk +  8, wc4 * 4) = wv1;
                    *(float4*)&WS(nb2, wk + 16, wc4 * 4) = wv2;
                    *(float4*)&WS(nb2, wk + 24, wc4 * 4) = wv3;
                    __syncthreads();
                    buf = nb2;
                }
            }

            if (!gates) {
                // local col -> global col: gate = n0t>>4, offset = n0t&15
                const int gcolS = (n0t >> 4) * 256 + u0 + (n0t & 15);
#pragma unroll
                for (int a = 0; a < 4; a++) {
                    __stcg((float4*)(p_out + (size_t)(b0r + m0 + a) * 1024 + gcolS),
                           make_float4(acc[a][0], acc[a][1], acc[a][2], acc[a][3]));
                }
            } else {
                __syncthreads();
                float* zt = ws_raw;          // zt[c][b], stride 33, c in [0,64)
#pragma unroll
                for (int cc = 0; cc < 4; cc++)
#pragma unroll
                    for (int a = 0; a < 4; a++)
                        zt[(n0t + cc) * 33 + (m0 + a)] = acc[a][cc];
                __syncthreads();

                const int uu = tid & 15;
                const int bq = tid >> 4;     // 0..7
                const int colu = u0 + uu;
                const float bi = bias[colu];
                const float bj = bias[256 + colu];
                const float bf = bias[512 + colu];
                const float bo = bias[768 + colu];
                const float* zxbase = (L == 0) ? g_zx0 : (L == 1) ? g_zx1 : g_zx2;

#pragma unroll
                for (int q = 0; q < 4; q++) {
                    const int bl = bq + 8 * q;
                    const int j = b0r + bl;
                    if (t < g_lens[L][j]) {
                        const float* er;
                        if (kind == 0)
                            er = zxbase + ((size_t)g_perm[L][j] * Ts + t) * 1024;
                        else
                            er = extra + (size_t)j * 1024;
                        const int gidx = j * Uc + colu;
                        float g0 = zt[(  0 + uu) * 33 + bl] + bi + __ldcg(&er[colu]);
                        float g1 = zt[( 16 + uu) * 33 + bl] + bj + __ldcg(&er[256 + colu]);
                        float g2 = zt[( 32 + uu) * 33 + bl] + bf + __ldcg(&er[512 + colu]);
                        float g3 = zt[( 48 + uu) * 33 + bl] + bo + __ldcg(&er[768 + colu]);
                        const float cn = __ldcg(&c[gidx]) * sigm(g2 + 1.0f)
                                       + sigm(g0) * tanh_(g1);
                        const float hn = tanh_(cn) * sigm(g3);
                        __stcg(&c[gidx], cn);
                        __stcg(&h_out[gidx], hn);
                    }
                }
            }
        }

        // ---- grid barrier ----
        __syncthreads();
        __threadfence();
        if (tid == 0) {
            atomicAdd(&g_bar, 1u);
            const unsigned target = (unsigned)NBLK * (unsigned)(i + 1);
            volatile unsigned* vb = &g_bar;
            while (*vb < target) __nanosleep(32);
        }
        __syncthreads();
    }
#undef WS
}

// ---------------- x-projection precompute ([k][m] x tile, masked-block skip) ----------------
struct XJob { const float* x; const int* ids; const float* tab;
              const float* W; float* zx; const int* len; int rows, Din, T; };
struct XJobs { XJob j[3]; };

__global__ void xproj_kernel(XJobs jobs) {
    const XJob J = jobs.j[blockIdx.y];
    const int bm = blockIdx.x % 384;
    const int bn = blockIdx.x / 384;
    const int r0 = bm * 32;
    if (r0 >= J.rows) return;
    const int tid = threadIdx.x;

    int pred = 0;
    if (tid < 32) {
        const int r = r0 + tid;
        const int bb = r / J.T;
        const int tt = r - bb * J.T;
        pred = (tt < J.len[bb]);
    }
    if (!__syncthreads_or(pred)) return;

    const int n0 = bn * 128;
    __shared__ __align__(16) float xs[32][36];
    __shared__ __align__(16) float ws[32][128];
    const int mi = tid & 7, ni = tid >> 3;
    const int m0 = mi * 4, n0t = ni * 4;
    const int xm = tid >> 3, xk = (tid & 7) * 4;
    const int wc = (tid & 31) * 4, wk = tid >> 5;

    float acc[4][4];
#pragma unroll
    for (int a = 0; a < 4; a++)
#pragma unroll
        for (int b = 0; b < 4; b++) acc[a][b] = 0.0f;

    const int r = r0 + xm;
    const float* srow = J.ids ? (J.tab + (size_t)J.ids[r] * J.Din)
                              : (J.x + (size_t)r * J.Din);

    const int nk = (J.Din + 31) >> 5;
    for (int kt = 0; kt < nk; kt++) {
        const int k0 = kt * 32;
        __syncthreads();
#pragma unroll
        for (int j = 0; j < 4; j++) {
            const int k = k0 + xk + j;
            xs[xk + j][xm] = (k < J.Din) ? srow[k] : 0.0f;
        }
#pragma unroll
        for (int q = 0; q < 4; q++) {
            const int kk = wk + 8 * q, k = k0 + kk;
            float4 wv = make_float4(0.f, 0.f, 0.f, 0.f);
            if (k < J.Din)
                wv = *(const float4*)(J.W + (size_t)k * 1024 + n0 + wc);
            *(float4*)&ws[kk][wc] = wv;
        }
        __syncthreads();
#pragma unroll 8
        for (int kk = 0; kk < 32; kk++) {
            const float4 x = *(const float4*)&xs[kk][m0];
            const float4 w = *(const float4*)&ws[kk][n0t];
            acc[0][0] = fmaf(x.x, w.x, acc[0][0]);
            acc[0][1] = fmaf(x.x, w.y, acc[0][1]);
            acc[0][2] = fmaf(x.x, w.z, acc[0][2]);
            acc[0][3] = fmaf(x.x, w.w, acc[0][3]);
            acc[1][0] = fmaf(x.y, w.x, acc[1][0]);
            acc[1][1] = fmaf(x.y, w.y, acc[1][1]);
            acc[1][2] = fmaf(x.y, w.z, acc[1][2]);
            acc[1][3] = fmaf(x.y, w.w, acc[1][3]);
            acc[2][0] = fmaf(x.z, w.x, acc[2][0]);
            acc[2][1] = fmaf(x.z, w.y, acc[2][1]);
            acc[2][2] = fmaf(x.z, w.z, acc[2][2]);
            acc[2][3] = fmaf(x.z, w.w, acc[2][3]);
            acc[3][0] = fmaf(x.w, w.x, acc[3][0]);
            acc[3][1] = fmaf(x.w, w.y, acc[3][1]);
            acc[3][2] = fmaf(x.w, w.z, acc[3][2]);
            acc[3][3] = fmaf(x.w, w.w, acc[3][3]);
        }
    }
#pragma unroll
    for (int a = 0; a < 4; a++) {
        *(float4*)(J.zx + (size_t)(r0 + m0 + a) * 1024 + n0 + n0t) =
            make_float4(acc[a][0], acc[a][1], acc[a][2], acc[a][3]);
    }
}

// ---------------- embedding (dead-block skip) ----------------
__global__ void embed_kernel(const int* __restrict__ word_ids,
                             const int* __restrict__ pos_ids,
                             const float* __restrict__ w_emb,
                             const float* __restrict__ p_emb,
                             const float* __restrict__ W,
                             const float* __restrict__ bias,
                             float* __restrict__ out,
                             int nrows,
                             const int* __restrict__ len,
                             int per_b, int per_item) {
    const int r0 = blockIdx.x * 8;
    {
        const int b = r0 / per_b;
        const int item = (r0 - b * per_b) / per_item;
        if (item >= len[b]) return;
    }
    __shared__ float xs[8][EDINc];
    __shared__ int wid_s[8], pid_s[8];
    const int tid = threadIdx.x;

    if (tid < 8) {
        int row = r0 + tid;
        wid_s[tid] = (row < nrows) ? word_ids[row] : 0;
        pid_s[tid] = (row < nrows) ? pos_ids[row] : 0;
    }
    __syncthreads();

    for (int idx = tid; idx < 8 * EDINc; idx += 128) {
        int r = idx / EDINc, k = idx - r * EDINc;
        float v;
        if (k < WDIMc) v = w_emb[wid_s[r] * WDIMc + k];
        else           v = p_emb[pid_s[r] * POSDc + (k - WDIMc)];
        xs[r][k] = v;
    }
    __syncthreads();

    float acc[8];
    const float bj = bias[tid];
#pragma unroll
    for (int r = 0; r < 8; r++) acc[r] = bj;

#pragma unroll 2
    for (int k = 0; k < EDINc; k++) {
        float w = W[k * FCc + tid];
#pragma unroll
        for (int r = 0; r < 8; r++) acc[r] = fmaf(xs[r][k], w, acc[r]);
    }
#pragma unroll
    for (int r = 0; r < 8; r++) {
        int row = r0 + r;
        if (row < nrows) out[row * FCc + tid] = fmaxf(acc[r], 0.0f);
    }
}

// ---------------- compose v3: mini-GEMM with depth-4 W prefetch ----------------
__global__ void __launch_bounds__(128) compose_kernel(
    const int* __restrict__ comp_word_id,
    const float* __restrict__ comp_emb,
    const int* __restrict__ comp_action_id,
    const int* __restrict__ comp_action_len,
    const float* __restrict__ a_emb,
    const float* __restrict__ rec_W,
    const float* __restrict__ rec_b,
    const int* __restrict__ stack_len,
    float* __restrict__ stack_emb)
{
    const int seq0 = blockIdx.x * CSEQ;
    {
        const int b = seq0 / STKc;
        const int stk0 = seq0 - b * STKc;
        if (stk0 >= stack_len[b]) return;
    }
    const int tid = threadIdx.x;

    __shared__ float vals[8][CSEQ][FCc];
    __shared__ __align__(16) float xs[RDINc][10];
    __shared__ int wid[CSEQ][16];
    __shared__ int act[CSEQ][8];
    __shared__ int alen[CSEQ];
    __shared__ signed char ihs[CSEQ][8], idds[CSEQ][8];

    {
        const int ss = tid >> 4, slot = tid & 15;
        wid[ss][slot] = comp_word_id[(seq0 + ss) * 16 + slot];
        if (tid < CSEQ * 8) {
            const int s2 = tid >> 3, n = tid & 7;
            act[s2][n] = comp_action_id[(seq0 + s2) * 8 + n];
        }
        if (tid < CSEQ) alen[tid] = comp_action_len[seq0 + tid];
    }
    __syncthreads();
    if (tid < CSEQ * 8) {
        const int ss = tid >> 3, n = tid & 7;
        const int hn = wid[ss][2 * n], dn = wid[ss][2 * n + 1];
        int ih = -1, idd = -1;
        for (int m = 0; m < n; m++) {
            const int hm = wid[ss][2 * m];
            if (hm == hn) ih = m;
            if (hm == dn) idd = m;
        }
        ihs[ss][n] = (signed char)ih;
        idds[ss][n] = (signed char)idd;
    }
    __syncthreads();

    const int mi = tid & 3,  ni = tid >> 2;
    const int s0 = mi * 2,   n0 = ni * 4;
    const float4 bn = *(const float4*)(rec_b + n0);
    const float* Wn = rec_W + n0;

    for (int n = 0; n < 8; n++) {
#pragma unroll
        for (int ss = 0; ss < CSEQ; ss++) {
            const int ih = ihs[ss][n], idd = idds[ss][n];
            const int an = act[ss][n];
#pragma unroll
            for (int j = 0; j < 3; j++) {
                const int k = tid + j * 128;
                if (k < RDINc) {
                    float v;
                    if (k < FCc) {
                        v = (ih >= 0) ? vals[ih][ss][k]
                                      : comp_emb[((size_t)(seq0 + ss) * 16 + 2 * n) * FCc + k];
                    } else if (k < FCc + CADc) {
                        v = a_emb[an * CADc + (k - FCc)];
                    } else {
                        const int kk = k - (FCc + CADc);
                        v = (idd >= 0) ? vals[idd][ss][kk]
                                       : comp_emb[((size_t)(seq0 + ss) * 16 + 2 * n + 1) * FCc + kk];
                    }
                    xs[k][ss] = v;
                }
            }
        }
        __syncthreads();

        float a00 = 0.f, a01 = 0.f, a02 = 0.f, a03 = 0.f;
        float a10 = 0.f, a11 = 0.f, a12 = 0.f, a13 = 0.f;

        float4 w0 = *(const float4*)(Wn + 0 * FCc);
        float4 w1 = *(const float4*)(Wn + 1 * FCc);
        float4 w2 = *(const float4*)(Wn + 2 * FCc);
        float4 w3 = *(const float4*)(Wn + 3 * FCc);
#pragma unroll 1
        for (int k = 0; k < 304; k += 4) {
            float4 p0, p1, p2, p3;
            if (k + 7 < RDINc) {
                p0 = *(const float4*)(Wn + (size_t)(k + 4) * FCc);
                p1 = *(const float4*)(Wn + (size_t)(k + 5) * FCc);
                p2 = *(const float4*)(Wn + (size_t)(k + 6) * FCc);
                p3 = *(const float4*)(Wn + (size_t)(k + 7) * FCc);
            } else {
                p0 = (k + 4 < RDINc) ? *(const float4*)(Wn + (size_t)(k + 4) * FCc) : w0;
                p1 = (k + 5 < RDINc) ? *(const float4*)(Wn + (size_t)(k + 5) * FCc) : w1;
                p2 = w2; p3 = w3;
            }
            const float2 x0 = *(const float2*)&xs[k + 0][s0];
            const float2 x1 = *(const float2*)&xs[k + 1][s0];
            const float2 x2 = *(const float2*)&xs[k + 2][s0];
            const float2 x3 = *(const float2*)&xs[k + 3][s0];
            a00 = fmaf(x0.x, w0.x, a00); a01 = fmaf(x0.x, w0.y, a01);
            a02 = fmaf(x0.x, w0.z, a02); a03 = fmaf(x0.x, w0.w, a03);
            a10 = fmaf(x0.y, w0.x, a10); a11 = fmaf(x0.y, w0.y, a11);
            a12 = fmaf(x0.y, w0.z, a12); a13 = fmaf(x0.y, w0.w, a13);
            a00 = fmaf(x1.x, w1.x, a00); a01 = fmaf(x1.x, w1.y, a01);
            a02 = fmaf(x1.x, w1.z, a02); a03 = fmaf(x1.x, w1.w, a03);
            a10 = fmaf(x1.y, w1.x, a10); a11 = fmaf(x1.y, w1.y, a11);
            a12 = fmaf(x1.y, w1.z, a12); a13 = fmaf(x1.y, w1.w, a13);
            a00 = fmaf(x2.x, w2.x, a00); a01 = fmaf(x2.x, w2.y, a01);
            a02 = fmaf(x2.x, w2.z, a02); a03 = fmaf(x2.x, w2.w, a03);
            a10 = fmaf(x2.y, w2.x, a10); a11 = fmaf(x2.y, w2.y, a11);
            a12 = fmaf(x2.y, w2.z, a12); a13 = fmaf(x2.y, w2.w, a13);
            a00 = fmaf(x3.x, w3.x, a00); a01 = fmaf(x3.x, w3.y, a01);
            a02 = fmaf(x3.x, w3.z, a02); a03 = fmaf(x3.x, w3.w, a03);
            a10 = fmaf(x3.y, w3.x, a10); a11 = fmaf(x3.y, w3.y, a11);
            a12 = fmaf(x3.y, w3.z, a12); a13 = fmaf(x3.y, w3.w, a13);
            w0 = p0; w1 = p1; w2 = p2; w3 = p3;
        }
        {
            const float2 x0 = *(const float2*)&xs[304][s0];
            const float2 x1 = *(const float2*)&xs[305][s0];
            a00 = fmaf(x0.x, w0.x, a00); a01 = fmaf(x0.x, w0.y, a01);
            a02 = fmaf(x0.x, w0.z, a02); a03 = fmaf(x0.x, w0.w, a03);
            a10 = fmaf(x0.y, w0.x, a10); a11 = fmaf(x0.y, w0.y, a11);
            a12 = fmaf(x0.y, w0.z, a12); a13 = fmaf(x0.y, w0.w, a13);
            a00 = fmaf(x1.x, w1.x, a00); a01 = fmaf(x1.x, w1.y, a01);
            a02 = fmaf(x1.x, w1.z, a02); a03 = fmaf(x1.x, w1.w, a03);
            a10 = fmaf(x1.y, w1.x, a10); a11 = fmaf(x1.y, w1.y, a11);
            a12 = fmaf(x1.y, w1.z, a12); a13 = fmaf(x1.y, w1.w, a13);
        }

        *(float4*)&vals[n][s0 + 0][n0] = make_float4(
            tanhf(a00 + bn.x), tanhf(a01 + bn.y), tanhf(a02 + bn.z), tanhf(a03 + bn.w));
        *(float4*)&vals[n][s0 + 1][n0] = make_float4(
            tanhf(a10 + bn.x), tanhf(a11 + bn.y), tanhf(a12 + bn.z), tanhf(a13 + bn.w));
        __syncthreads();
    }

#pragma unroll
    for (int ss = 0; ss < CSEQ; ss++) {
        const int al = alen[ss];
        const float v = (al == 0)
            ? comp_emb[(size_t)(seq0 + ss) * 16 * FCc + tid]
            : vals[al - 1][ss][tid];
        stack_emb[(size_t)(seq0 + ss) * FCc + tid] = v;
    }
}

// ---------------- output head ----------------
__global__ void final_kernel(const int* __restrict__ l0,
                             const int* __restrict__ l1,
                             const int* __restrict__ l2,
                             const float* __restrict__ fW,
                             const float* __restrict__ fb,
                             float* __restrict__ out) {
    const int b = blockIdx.x;
    const int tid = threadIdx.x;
    __shared__ float hcat[3 * Uc];
    for (int idx = tid; idx < 3 * Uc; idx += 128) {
        const int L = idx >> 8;
        const int col = idx & 255;
        const int len = ((L == 0) ? l0 : (L == 1) ? l1 : l2)[b];
        const int j = g_inv[L][b];
        hcat[idx] = g_h1[L][(len - 1) & 1][j * Uc + col];
    }
    __syncthreads();
    if (tid < NOUTc) {
        float acc = fb[tid];
#pragma unroll 2
        for (int k = 0; k < 3 * Uc; k++) acc = fmaf(hcat[k], fW[k * NOUTc + tid], acc);
        out[b * NOUTc + tid] = acc;
    }
}

// ---------------- host driver ----------------
extern "C" void kernel_launch(void* const* d_in, const int* in_sizes, int n_in,
                              void* d_out, int out_size) {
    const int*   buff_word_id   = (const int*)d_in[0];
    const int*   buff_pos_id    = (const int*)d_in[1];
    const int*   comp_word_id   = (const int*)d_in[2];
    const int*   comp_pos_id    = (const int*)d_in[3];
    const int*   comp_action_id = (const int*)d_in[4];
    const int*   comp_action_len= (const int*)d_in[5];
    const int*   history_action_id = (const int*)d_in[6];
    const int*   stack_length   = (const int*)d_in[7];
    const int*   buff_length    = (const int*)d_in[8];
    const int*   history_action_length = (const int*)d_in[9];
    const float* p_emb      = (const float*)d_in[10];
    const float* comp_a_emb = (const float*)d_in[11];
    const float* hist_a_emb = (const float*)d_in[12];
    const float* w_emb      = (const float*)d_in[13];
    const float* emb_W      = (const float*)d_in[14];
    const float* emb_b      = (const float*)d_in[15];
    const float* rec_W      = (const float*)d_in[16];
    const float* rec_b      = (const float*)d_in[17];
    const float* W0s[3] = { (const float*)d_in[18], (const float*)d_in[22], (const float*)d_in[26] };
    const float* b0s[3] = { (const float*)d_in[19], (const float*)d_in[23], (const float*)d_in[27] };
    const float* W1s[3] = { (const float*)d_in[20], (const float*)d_in[24], (const float*)d_in[28] };
    const float* b1s[3] = { (const float*)d_in[21], (const float*)d_in[25], (const float*)d_in[29] };
    const float* fW  = (const float*)d_in[30];
    const float* fb  = (const float*)d_in[31];
    float* out = (float*)d_out;

    float *buff_emb_p, *comp_emb_p, *stack_emb_p;
    float *zx0_p, *zx1_p, *zx2_p;
    float *c0_p, *c1_p, *h0_p, *h1_p;
    unsigned* bar_p;
    cudaGetSymbolAddress((void**)&buff_emb_p,  g_buff_emb);
    cudaGetSymbolAddress((void**)&comp_emb_p,  g_comp_emb);
    cudaGetSymbolAddress((void**)&stack_emb_p, g_stack_emb);
    cudaGetSymbolAddress((void**)&zx0_p, g_zx0);
    cudaGetSymbolAddress((void**)&zx1_p, g_zx1);
    cudaGetSymbolAddress((void**)&zx2_p, g_zx2);
    cudaGetSymbolAddress((void**)&c0_p, g_c0);
    cudaGetSymbolAddress((void**)&c1_p, g_c1);
    cudaGetSymbolAddress((void**)&h0_p, g_h0);
    cudaGetSymbolAddress((void**)&h1_p, g_h1);
    cudaGetSymbolAddress((void**)&bar_p, g_bar);

    const size_t SB = (size_t)Bc * Uc;

    cudaMemsetAsync(bar_p, 0, sizeof(unsigned));
    cudaMemsetAsync(c0_p, 0, 3 * SB * sizeof(float));
    cudaMemsetAsync(c1_p, 0, 3 * SB * sizeof(float));
    cudaMemsetAsync(h0_p, 0, 3 * 2 * SB * sizeof(float));
    cudaMemsetAsync(h1_p, 0, 3 * 2 * SB * sizeof(float));

    // length sort + per-step active counts
    sort_kernel<<<3, 128>>>(stack_length, buff_length, history_action_length);

    // embeddings (dead-block skipping)
    const int nbuff = Bc * BUFFc;
    embed_kernel<<<(nbuff + 7) / 8, 128>>>(buff_word_id, buff_pos_id, w_emb, p_emb,
                                           emb_W, emb_b, buff_emb_p, nbuff,
                                           buff_length, BUFFc, 1);
    const int ncomp = Bc * STKc * 16;
    embed_kernel<<<(ncomp + 7) / 8, 128>>>(comp_word_id, comp_pos_id, w_emb, p_emb,
                                           emb_W, emb_b, comp_emb_p, ncomp,
                                           stack_length, STKc * 16, 16);

    // recursive compose
    compose_kernel<<<Bc * STKc / CSEQ, 128>>>(comp_word_id, comp_emb_p,
                                              comp_action_id, comp_action_len,
                                              comp_a_emb, rec_W, rec_b,
                                              stack_length, stack_emb_p);

    // x-projections for layer0
    {
        XJobs xj;
        xj.j[0] = XJob{ stack_emb_p, nullptr, nullptr, W0s[0], zx0_p,
                        stack_length, Bc * STKc,  FCc, STKc };
        xj.j[1] = XJob{ buff_emb_p,  nullptr, nullptr, W0s[1], zx1_p,
                        buff_length, Bc * BUFFc, FCc, BUFFc };
        xj.j[2] = XJob{ nullptr, history_action_id, hist_a_emb, W0s[2], zx2_p,
                        history_action_length, Bc * HISTc, 50, HISTc };
        xproj_kernel<<<dim3(384 * 8, 3), 256>>>(xj);
    }

    // persistent fused loop (fine-grained blocks)
    {
        PParams P;
        for (int L = 0; L < 3; L++) {
            const int din = (L == 2) ? 50 : FCc;
            P.W0h[L] = W0s[L] + (size_t)din * 1024;
            P.b0[L]  = b0s[L];
            P.W1a[L] = W1s[L];
            P.W1b[L] = W1s[L] + (size_t)256 * 1024;
            P.b1[L]  = b1s[L];
        }
        lstm_loop_kernel<<<NBLK, 128>>>(P);
    }

    // output head
    final_kernel<<<Bc, 128>>>(stack_length, buff_length, history_action_length,
                              fW, fb, out);
}

// round 13
// speedup vs baseline: 1.8562x; 1.0323x over previous
#include <cuda_runtime.h>
#include <math.h>

// ---------------- problem constants ----------------
#define Bc    128
#define BUFFc 64
#define STKc  48
#define HISTc 96
#define FCc   128
#define Uc    256
#define NOUTc 82
#define WDIMc 300
#define POSDc 50
#define EDINc 350
#define CADc  50
#define RDINc 306
#define NBLK  576
#define NITER 98
#define CSEQ  8
#define WST   68

// ---------------- device scratch ----------------
__device__ float g_buff_emb[Bc * BUFFc * FCc];
__device__ float g_comp_emb[Bc * STKc * 16 * FCc];
__device__ float g_stack_emb[Bc * STKc * FCc];

__device__ float g_zx0[Bc * STKc  * 1024];
__device__ float g_zx1[Bc * BUFFc * 1024];
__device__ float g_zx2[Bc * HISTc * 1024];

__device__ float g_p [3][2][Bc * 1024];
__device__ float g_c0[3][Bc * Uc];
__device__ float g_c1[3][Bc * Uc];
__device__ float g_h0[3][2][Bc * Uc];
__device__ float g_h1[3][2][Bc * Uc];

__device__ int g_perm[3][Bc];
__device__ int g_inv [3][Bc];
__device__ int g_lens[3][Bc];
__device__ int g_cnt [3][HISTc];

__device__ unsigned g_bar;

__device__ __forceinline__ float sigm(float x) {
    return __fdividef(1.0f, 1.0f + __expf(-x));
}
__device__ __forceinline__ float tanh_(float x) {
    return __fdividef(2.0f, 1.0f + __expf(-2.0f * x)) - 1.0f;
}

// ---------------- per-LSTM length sort (stable, descending) ----------------
__global__ void sort_kernel(const int* len0, const int* len1, const int* len2) {
    const int L = blockIdx.x;
    const int* len = (L == 0) ? len0 : (L == 1) ? len1 : len2;
    const int T = (L == 0) ? STKc : (L == 1) ? BUFFc : HISTc;
    __shared__ int sl[Bc];
    const int tid = threadIdx.x;
    sl[tid] = len[tid];
    __syncthreads();
    const int myl = sl[tid];
    int rank = 0;
    for (int b = 0; b < Bc; b++) {
        const int lb = sl[b];
        rank += (lb > myl) || (lb == myl && b < tid);
    }
    g_perm[L][rank] = tid;
    g_inv[L][tid] = rank;
    g_lens[L][rank] = myl;
    if (tid < T) {
        int c = 0;
        for (int b = 0; b < Bc; b++) c += (sl[b] > tid);
        g_cnt[L][tid] = c;
    }
}

// ---------------- persistent fused LSTM loop (unchanged from R11) ----------------
struct PParams {
    const float* W0h[3];
    const float* b0[3];
    const float* W1a[3];
    const float* W1b[3];
    const float* b1[3];
};

__global__ void __launch_bounds__(128, 4) lstm_loop_kernel(PParams P) {
    const int tid = threadIdx.x;
    const int bid = blockIdx.x;

    __shared__ __align__(16) float xs[2][32][36];
    __shared__ __align__(16) float ws_raw[2 * 32 * WST];
#define WS(bf,k,c) ws_raw[(bf) * (32 * WST) + (k) * WST + (c)]

    const int mi = tid & 7,  ni = tid >> 3;
    const int m0 = mi * 4,   n0t = ni * 4;
    const int xm = tid >> 2;
    const int xk4 = (tid & 3) * 4;
    const int wk = tid >> 4;
    const int wc4 = tid & 15;

    for (int i = 0; i < NITER; i++) {
        const int pr = (i + 1) & 1;
        const int pw = i & 1;

        int sfound = -1, local = 0, off = 0;
#pragma unroll
        for (int s = 0; s < 9; s++) {
            const int Ls = s / 3, kind = s - Ls * 3;
            const int Ts = (Ls == 0) ? STKc : (Ls == 1) ? BUFFc : HISTc;
            const int ts = i - kind;
            int nb = 0;
            if (ts >= 0 && ts < Ts) {
                const int cc = g_cnt[Ls][ts];
                nb = (cc + 31) >> 5;
            }
            const int items = nb * 16;
            if (sfound < 0 && bid >= off && bid < off + items) {
                sfound = s; local = bid - off;
            }
            off += items;
        }

        if (sfound >= 0) {
            const int L = sfound / 3, kind = sfound - L * 3;
            const int Ts = (L == 0) ? STKc : (L == 1) ? BUFFc : HISTc;
            const int t = i - kind;
            const int bm = local >> 4, bu = local & 15;
            const int b0r = bm * 32;
            const int u0 = bu * 16;
            const int gcol = (wc4 >> 2) * 256 + u0 + (wc4 & 3) * 4;

            const float* src;
            const float* W;
            const float* extra = nullptr;
            const float* bias = nullptr;
            float* c = nullptr;
            float* h_out = nullptr;
            float* p_out = nullptr;
            bool gates;
            if (kind == 0) {
                gates = true;
                src = &g_h0[L][pr][0];
                W = P.W0h[L];
                bias = P.b0[L];
                c = &g_c0[L][0];
                h_out = &g_h0[L][pw][0];
            } else if (kind == 1) {
                gates = false;
                src = &g_h0[L][pr][0];
                W = P.W1a[L];
                p_out = &g_p[L][pr][0];
            } else {
                gates = true;
                src = &g_h1[L][pr][0];
                W = P.W1b[L];
                extra = &g_p[L][pw][0];
                bias = P.b1[L];
                c = &g_c1[L][0];
                h_out = &g_h1[L][pw][0];
            }

            float acc[4][4];
#pragma unroll
            for (int a = 0; a < 4; a++)
#pragma unroll
                for (int b = 0; b < 4; b++) acc[a][b] = 0.0f;

            const float* srow = src + (b0r + xm) * Uc;

            {
                float4 xa = __ldcg((const float4*)(srow + xk4));
                float4 xb = __ldcg((const float4*)(srow + xk4 + 16));
                xs[0][xk4 + 0][xm] = xa.x; xs[0][xk4 + 1][xm] = xa.y;
                xs[0][xk4 + 2][xm] = xa.z; xs[0][xk4 + 3][xm] = xa.w;
                xs[0][xk4 + 16][xm] = xb.x; xs[0][xk4 + 17][xm] = xb.y;
                xs[0][xk4 + 18][xm] = xb.z; xs[0][xk4 + 19][xm] = xb.w;
#pragma unroll
                for (int q = 0; q < 4; q++) {
                    const int kk = wk + 8 * q;
                    *(float4*)&WS(0, kk, wc4 * 4) =
                        *(const float4*)(W + (size_t)kk * 1024 + gcol);
                }
            }
            __syncthreads();

            int buf = 0;
#pragma unroll 1
            for (int kt = 0; kt < 8; kt++) {
                float4 xa, xb, wv0, wv1, wv2, wv3;
                const bool more = (kt < 7);
                if (more) {
                    const int k0 = (kt + 1) * 32;
                    xa = __ldcg((const float4*)(srow + k0 + xk4));
                    xb = __ldcg((const float4*)(srow + k0 + xk4 + 16));
                    const float* wrow = W + (size_t)(k0 + wk) * 1024 + gcol;
                    wv0 = *(const float4*)(wrow);
                    wv1 = *(const float4*)(wrow +  8 * 1024);
                    wv2 = *(const float4*)(wrow + 16 * 1024);
                    wv3 = *(const float4*)(wrow + 24 * 1024);
                }

                const float (*xsb)[36] = xs[buf];
#pragma unroll
                for (int kk = 0; kk < 32; kk++) {
                    const float4 x = *(const float4*)&xsb[kk][m0];
                    const float4 w = *(const float4*)&WS(buf, kk, n0t);
                    acc[0][0] = fmaf(x.x, w.x, acc[0][0]);
                    acc[0][1] = fmaf(x.x, w.y, acc[0][1]);
                    acc[0][2] = fmaf(x.x, w.z, acc[0][2]);
                    acc[0][3] = fmaf(x.x, w.w, acc[0][3]);
                    acc[1][0] = fmaf(x.y, w.x, acc[1][0]);
                    acc[1][1] = fmaf(x.y, w.y, acc[1][1]);
                    acc[1][2] = fmaf(x.y, w.z, acc[1][2]);
                    acc[1][3] = fmaf(x.y, w.w, acc[1][3]);
                    acc[2][0] = fmaf(x.z, w.x, acc[2][0]);
                    acc[2][1] = fmaf(x.z, w.y, acc[2][1]);
                    acc[2][2] = fmaf(x.z, w.z, acc[2][2]);
                    acc[2][3] = fmaf(x.z, w.w, acc[2][3]);
                    acc[3][0] = fmaf(x.w, w.x, acc[3][0]);
                    acc[3][1] = fmaf(x.w, w.y, acc[3][1]);
                    acc[3][2] = fmaf(x.w, w.z, acc[3][2]);
                    acc[3][3] = fmaf(x.w, w.w, acc[3][3]);
                }

                if (more) {
                    const int nb2 = buf ^ 1;
                    xs[nb2][xk4 + 0][xm] = xa.x; xs[nb2][xk4 + 1][xm] = xa.y;
                    xs[nb2][xk4 + 2][xm] = xa.z; xs[nb2][xk4 + 3][xm] = xa.w;
                    xs[nb2][xk4 + 16][xm] = xb.x; xs[nb2][xk4 + 17][xm] = xb.y;
                    xs[nb2][xk4 + 18][xm] = xb.z; xs[nb2][xk4 + 19][xm] = xb.w;
                    *(float4*)&WS(nb2, wk +  0, wc4 * 4) = wv0;
                    *(float4*)&WS(nb2, wk +  8, wc4 * 4) = wv1;
                    *(float4*)&WS(nb2, wk + 16, wc4 * 4) = wv2;
                    *(float4*)&WS(nb2, wk + 24, wc4 * 4) = wv3;
                    __syncthreads();
                    buf = nb2;
                }
            }

            if (!gates) {
                const int gcolS = (n0t >> 4) * 256 + u0 + (n0t & 15);
#pragma unroll
                for (int a = 0; a < 4; a++) {
                    __stcg((float4*)(p_out + (size_t)(b0r + m0 + a) * 1024 + gcolS),
                           make_float4(acc[a][0], acc[a][1], acc[a][2], acc[a][3]));
                }
            } else {
                __syncthreads();
                float* zt = ws_raw;
#pragma unroll
                for (int cc = 0; cc < 4; cc++)
#pragma unroll
                    for (int a = 0; a < 4; a++)
                        zt[(n0t + cc) * 33 + (m0 + a)] = acc[a][cc];
                __syncthreads();

                const int uu = tid & 15;
                const int bq = tid >> 4;
                const int colu = u0 + uu;
                const float bi = bias[colu];
                const float bj = bias[256 + colu];
                const float bf = bias[512 + colu];
                const float bo = bias[768 + colu];
                const float* zxbase = (L == 0) ? g_zx0 : (L == 1) ? g_zx1 : g_zx2;

#pragma unroll
                for (int q = 0; q < 4; q++) {
                    const int bl = bq + 8 * q;
                    const int j = b0r + bl;
                    if (t < g_lens[L][j]) {
                        const float* er;
                        if (kind == 0)
                            er = zxbase + ((size_t)g_perm[L][j] * Ts + t) * 1024;
                        else
                            er = extra + (size_t)j * 1024;
                        const int gidx = j * Uc + colu;
                        float g0 = zt[(  0 + uu) * 33 + bl] + bi + __ldcg(&er[colu]);
                        float g1 = zt[( 16 + uu) * 33 + bl] + bj + __ldcg(&er[256 + colu]);
                        float g2 = zt[( 32 + uu) * 33 + bl] + bf + __ldcg(&er[512 + colu]);
                        float g3 = zt[( 48 + uu) * 33 + bl] + bo + __ldcg(&er[768 + colu]);
                        const float cn = __ldcg(&c[gidx]) * sigm(g2 + 1.0f)
                                       + sigm(g0) * tanh_(g1);
                        const float hn = tanh_(cn) * sigm(g3);
                        __stcg(&c[gidx], cn);
                        __stcg(&h_out[gidx], hn);
                    }
                }
            }
        }

        __syncthreads();
        __threadfence();
        if (tid == 0) {
            atomicAdd(&g_bar, 1u);
            const unsigned target = (unsigned)NBLK * (unsigned)(i + 1);
            volatile unsigned* vb = &g_bar;
            while (*vb < target) __nanosleep(32);
        }
        __syncthreads();
    }
#undef WS
}

// ---------------- x-projection precompute ([k][m] x tile, masked-block skip) ----------------
struct XJob { const float* x; const int* ids; const float* tab;
              const float* W; float* zx; const int* len; int rows, Din, T; };
struct XJobs { XJob j[3]; };

__global__ void xproj_kernel(XJobs jobs) {
    const XJob J = jobs.j[blockIdx.y];
    const int bm = blockIdx.x % 384;
    const int bn = blockIdx.x / 384;
    const int r0 = bm * 32;
    if (r0 >= J.rows) return;
    const int tid = threadIdx.x;

    int pred = 0;
    if (tid < 32) {
        const int r = r0 + tid;
        const int bb = r / J.T;
        const int tt = r - bb * J.T;
        pred = (tt < J.len[bb]);
    }
    if (!__syncthreads_or(pred)) return;

    const int n0 = bn * 128;
    __shared__ __align__(16) float xs[32][36];
    __shared__ __align__(16) float ws[32][128];
    const int mi = tid & 7, ni = tid >> 3;
    const int m0 = mi * 4, n0t = ni * 4;
    const int xm = tid >> 3, xk = (tid & 7) * 4;
    const int wc = (tid & 31) * 4, wk = tid >> 5;

    float acc[4][4];
#pragma unroll
    for (int a = 0; a < 4; a++)
#pragma unroll
        for (int b = 0; b < 4; b++) acc[a][b] = 0.0f;

    const int r = r0 + xm;
    const float* srow = J.ids ? (J.tab + (size_t)J.ids[r] * J.Din)
                              : (J.x + (size_t)r * J.Din);

    const int nk = (J.Din + 31) >> 5;
    for (int kt = 0; kt < nk; kt++) {
        const int k0 = kt * 32;
        __syncthreads();
#pragma unroll
        for (int j = 0; j < 4; j++) {
            const int k = k0 + xk + j;
            xs[xk + j][xm] = (k < J.Din) ? srow[k] : 0.0f;
        }
#pragma unroll
        for (int q = 0; q < 4; q++) {
            const int kk = wk + 8 * q, k = k0 + kk;
            float4 wv = make_float4(0.f, 0.f, 0.f, 0.f);
            if (k < J.Din)
                wv = *(const float4*)(J.W + (size_t)k * 1024 + n0 + wc);
            *(float4*)&ws[kk][wc] = wv;
        }
        __syncthreads();
#pragma unroll 8
        for (int kk = 0; kk < 32; kk++) {
            const float4 x = *(const float4*)&xs[kk][m0];
            const float4 w = *(const float4*)&ws[kk][n0t];
            acc[0][0] = fmaf(x.x, w.x, acc[0][0]);
            acc[0][1] = fmaf(x.x, w.y, acc[0][1]);
            acc[0][2] = fmaf(x.x, w.z, acc[0][2]);
            acc[0][3] = fmaf(x.x, w.w, acc[0][3]);
            acc[1][0] = fmaf(x.y, w.x, acc[1][0]);
            acc[1][1] = fmaf(x.y, w.y, acc[1][1]);
            acc[1][2] = fmaf(x.y, w.z, acc[1][2]);
            acc[1][3] = fmaf(x.y, w.w, acc[1][3]);
            acc[2][0] = fmaf(x.z, w.x, acc[2][0]);
            acc[2][1] = fmaf(x.z, w.y, acc[2][1]);
            acc[2][2] = fmaf(x.z, w.z, acc[2][2]);
            acc[2][3] = fmaf(x.z, w.w, acc[2][3]);
            acc[3][0] = fmaf(x.w, w.x, acc[3][0]);
            acc[3][1] = fmaf(x.w, w.y, acc[3][1]);
            acc[3][2] = fmaf(x.w, w.z, acc[3][2]);
            acc[3][3] = fmaf(x.w, w.w, acc[3][3]);
        }
    }
#pragma unroll
    for (int a = 0; a < 4; a++) {
        *(float4*)(J.zx + (size_t)(r0 + m0 + a) * 1024 + n0 + n0t) =
            make_float4(acc[a][0], acc[a][1], acc[a][2], acc[a][3]);
    }
}

// ---------------- embedding v3: transposed x, warp-uniform rows, W prefetch ----------------
// 8 rows/block, 128 threads. Warp w handles rows {2w, 2w+1}; lane = 4 cols.
__global__ void __launch_bounds__(128) embed_kernel(
    const int* __restrict__ word_ids,
    const int* __restrict__ pos_ids,
    const float* __restrict__ w_emb,
    const float* __restrict__ p_emb,
    const float* __restrict__ W,
    const float* __restrict__ bias,
    float* __restrict__ out,
    int nrows,
    const int* __restrict__ len,
    int per_b, int per_item)
{
    const int r0 = blockIdx.x * 8;
    {
        const int b = r0 / per_b;
        const int item = (r0 - b * per_b) / per_item;
        if (item >= len[b]) return;
    }
    __shared__ __align__(16) float xs[EDINc][10];   // [k][r] transposed
    __shared__ int wid_s[8], pid_s[8];
    const int tid = threadIdx.x;

    if (tid < 8) {
        int row = r0 + tid;
        wid_s[tid] = (row < nrows) ? word_ids[row] : 0;
        pid_s[tid] = (row < nrows) ? pos_ids[row] : 0;
    }
    __syncthreads();

    for (int idx = tid; idx < 8 * EDINc; idx += 128) {
        int r = idx / EDINc, k = idx - r * EDINc;
        float v;
        if (k < WDIMc) v = w_emb[wid_s[r] * WDIMc + k];
        else           v = p_emb[pid_s[r] * POSDc + (k - WDIMc)];
        xs[k][r] = v;
    }
    __syncthreads();

    const int ri = tid >> 5;           // warp id -> rows 2ri, 2ri+1
    const int s0 = 2 * ri;
    const int n0 = (tid & 31) * 4;     // 4 cols
    const float4 bv = *(const float4*)(bias + n0);
    const float* Wn = W + n0;

    float a00 = 0.f, a01 = 0.f, a02 = 0.f, a03 = 0.f;
    float a10 = 0.f, a11 = 0.f, a12 = 0.f, a13 = 0.f;

    float4 w0 = *(const float4*)(Wn + 0 * FCc);
    float4 w1 = *(const float4*)(Wn + 1 * FCc);
    float4 w2 = *(const float4*)(Wn + 2 * FCc);
    float4 w3 = *(const float4*)(Wn + 3 * FCc);
#pragma unroll 1
    for (int k = 0; k < 348; k += 4) {
        float4 p0, p1, p2, p3;
        p0 = (k + 4 < EDINc) ? *(const float4*)(Wn + (size_t)(k + 4) * FCc) : w0;
        p1 = (k + 5 < EDINc) ? *(const float4*)(Wn + (size_t)(k + 5) * FCc) : w1;
        p2 = (k + 6 < EDINc) ? *(const float4*)(Wn + (size_t)(k + 6) * FCc) : w2;
        p3 = (k + 7 < EDINc) ? *(const float4*)(Wn + (size_t)(k + 7) * FCc) : w3;
        const float2 x0 = *(const float2*)&xs[k + 0][s0];
        const float2 x1 = *(const float2*)&xs[k + 1][s0];
        const float2 x2 = *(const float2*)&xs[k + 2][s0];
        const float2 x3 = *(const float2*)&xs[k + 3][s0];
        a00 = fmaf(x0.x, w0.x, a00); a01 = fmaf(x0.x, w0.y, a01);
        a02 = fmaf(x0.x, w0.z, a02); a03 = fmaf(x0.x, w0.w, a03);
        a10 = fmaf(x0.y, w0.x, a10); a11 = fmaf(x0.y, w0.y, a11);
        a12 = fmaf(x0.y, w0.z, a12); a13 = fmaf(x0.y, w0.w, a13);
        a00 = fmaf(x1.x, w1.x, a00); a01 = fmaf(x1.x, w1.y, a01);
        a02 = fmaf(x1.x, w1.z, a02); a03 = fmaf(x1.x, w1.w, a03);
        a10 = fmaf(x1.y, w1.x, a10); a11 = fmaf(x1.y, w1.y, a11);
        a12 = fmaf(x1.y, w1.z, a12); a13 = fmaf(x1.y, w1.w, a13);
        a00 = fmaf(x2.x, w2.x, a00); a01 = fmaf(x2.x, w2.y, a01);
        a02 = fmaf(x2.x, w2.z, a02); a03 = fmaf(x2.x, w2.w, a03);
        a10 = fmaf(x2.y, w2.x, a10); a11 = fmaf(x2.y, w2.y, a11);
        a12 = fmaf(x2.y, w2.z, a12); a13 = fmaf(x2.y, w2.w, a13);
        a00 = fmaf(x3.x, w3.x, a00); a01 = fmaf(x3.x, w3.y, a01);
        a02 = fmaf(x3.x, w3.z, a02); a03 = fmaf(x3.x, w3.w, a03);
        a10 = fmaf(x3.y, w3.x, a10); a11 = fmaf(x3.y, w3.y, a11);
        a12 = fmaf(x3.y, w3.z, a12); a13 = fmaf(x3.y, w3.w, a13);
        w0 = p0; w1 = p1; w2 = p2; w3 = p3;
    }
    {   // tail k = 348, 349 (in w0, w1)
        const float2 x0 = *(const float2*)&xs[348][s0];
        const float2 x1 = *(const float2*)&xs[349][s0];
        a00 = fmaf(x0.x, w0.x, a00); a01 = fmaf(x0.x, w0.y, a01);
        a02 = fmaf(x0.x, w0.z, a02); a03 = fmaf(x0.x, w0.w, a03);
        a10 = fmaf(x0.y, w0.x, a10); a11 = fmaf(x0.y, w0.y, a11);
        a12 = fmaf(x0.y, w0.z, a12); a13 = fmaf(x0.y, w0.w, a13);
        a00 = fmaf(x1.x, w1.x, a00); a01 = fmaf(x1.x, w1.y, a01);
        a02 = fmaf(x1.x, w1.z, a02); a03 = fmaf(x1.x, w1.w, a03);
        a10 = fmaf(x1.y, w1.x, a10); a11 = fmaf(x1.y, w1.y, a11);
        a12 = fmaf(x1.y, w1.z, a12); a13 = fmaf(x1.y, w1.w, a13);
    }

    const int rowA = r0 + s0, rowB = r0 + s0 + 1;
    if (rowA < nrows)
        *(float4*)(out + (size_t)rowA * FCc + n0) = make_float4(
            fmaxf(a00 + bv.x, 0.f), fmaxf(a01 + bv.y, 0.f),
            fmaxf(a02 + bv.z, 0.f), fmaxf(a03 + bv.w, 0.f));
    if (rowB < nrows)
        *(float4*)(out + (size_t)rowB * FCc + n0) = make_float4(
            fmaxf(a10 + bv.x, 0.f), fmaxf(a11 + bv.y, 0.f),
            fmaxf(a12 + bv.z, 0.f), fmaxf(a13 + bv.w, 0.f));
}

// ---------------- compose v4: mini-GEMM with depth-8 W prefetch (no guards) ----------------
__global__ void __launch_bounds__(128) compose_kernel(
    const int* __restrict__ comp_word_id,
    const float* __restrict__ comp_emb,
    const int* __restrict__ comp_action_id,
    const int* __restrict__ comp_action_len,
    const float* __restrict__ a_emb,
    const float* __restrict__ rec_W,
    const float* __restrict__ rec_b,
    const int* __restrict__ stack_len,
    float* __restrict__ stack_emb)
{
    const int seq0 = blockIdx.x * CSEQ;
    {
        const int b = seq0 / STKc;
        const int stk0 = seq0 - b * STKc;
        if (stk0 >= stack_len[b]) return;
    }
    const int tid = threadIdx.x;

    __shared__ float vals[8][CSEQ][FCc];
    __shared__ __align__(16) float xs[RDINc][10];
    __shared__ int wid[CSEQ][16];
    __shared__ int act[CSEQ][8];
    __shared__ int alen[CSEQ];
    __shared__ signed char ihs[CSEQ][8], idds[CSEQ][8];

    {
        const int ss = tid >> 4, slot = tid & 15;
        wid[ss][slot] = comp_word_id[(seq0 + ss) * 16 + slot];
        if (tid < CSEQ * 8) {
            const int s2 = tid >> 3, n = tid & 7;
            act[s2][n] = comp_action_id[(seq0 + s2) * 8 + n];
        }
        if (tid < CSEQ) alen[tid] = comp_action_len[seq0 + tid];
    }
    __syncthreads();
    if (tid < CSEQ * 8) {
        const int ss = tid >> 3, n = tid & 7;
        const int hn = wid[ss][2 * n], dn = wid[ss][2 * n + 1];
        int ih = -1, idd = -1;
        for (int m = 0; m < n; m++) {
            const int hm = wid[ss][2 * m];
            if (hm == hn) ih = m;
            if (hm == dn) idd = m;
        }
        ihs[ss][n] = (signed char)ih;
        idds[ss][n] = (signed char)idd;
    }
    __syncthreads();

    const int mi = tid & 3,  ni = tid >> 2;
    const int s0 = mi * 2,   n0 = ni * 4;
    const float4 bn = *(const float4*)(rec_b + n0);
    const float* Wn = rec_W + n0;

    for (int n = 0; n < 8; n++) {
#pragma unroll
        for (int ss = 0; ss < CSEQ; ss++) {
            const int ih = ihs[ss][n], idd = idds[ss][n];
            const int an = act[ss][n];
#pragma unroll
            for (int j = 0; j < 3; j++) {
                const int k = tid + j * 128;
                if (k < RDINc) {
                    float v;
                    if (k < FCc) {
                        v = (ih >= 0) ? vals[ih][ss][k]
                                      : comp_emb[((size_t)(seq0 + ss) * 16 + 2 * n) * FCc + k];
                    } else if (k < FCc + CADc) {
                        v = a_emb[an * CADc + (k - FCc)];
                    } else {
                        const int kk = k - (FCc + CADc);
                        v = (idd >= 0) ? vals[idd][ss][kk]
                                       : comp_emb[((size_t)(seq0 + ss) * 16 + 2 * n + 1) * FCc + kk];
                    }
                    xs[k][ss] = v;
                }
            }
        }
        __syncthreads();

        float a00 = 0.f, a01 = 0.f, a02 = 0.f, a03 = 0.f;
        float a10 = 0.f, a11 = 0.f, a12 = 0.f, a13 = 0.f;

        // depth-8 prefetch; 306 = 8*38 + 2; prefetch max row = 303 (always valid)
        float4 w[8];
#pragma unroll
        for (int j = 0; j < 8; j++)
            w[j] = *(const float4*)(Wn + (size_t)j * FCc);

#pragma unroll 1
        for (int k = 0; k < 296; k += 8) {
            float4 p[8];
#pragma unroll
            for (int j = 0; j < 8; j++)
                p[j] = *(const float4*)(Wn + (size_t)(k + 8 + j) * FCc);
#pragma unroll
            for (int j = 0; j < 8; j++) {
                const float2 x = *(const float2*)&xs[k + j][s0];
                a00 = fmaf(x.x, w[j].x, a00); a01 = fmaf(x.x, w[j].y, a01);
                a02 = fmaf(x.x, w[j].z, a02); a03 = fmaf(x.x, w[j].w, a03);
                a10 = fmaf(x.y, w[j].x, a10); a11 = fmaf(x.y, w[j].y, a11);
                a12 = fmaf(x.y, w[j].z, a12); a13 = fmaf(x.y, w[j].w, a13);
            }
#pragma unroll
            for (int j = 0; j < 8; j++) w[j] = p[j];
        }
        // rows 296..303 (in w), then tail 304, 305
#pragma unroll
        for (int j = 0; j < 8; j++) {
            const float2 x = *(const float2*)&xs[296 + j][s0];
            a00 = fmaf(x.x, w[j].x, a00); a01 = fmaf(x.x, w[j].y, a01);
            a02 = fmaf(x.x, w[j].z, a02); a03 = fmaf(x.x, w[j].w, a03);
            a10 = fmaf(x.y, w[j].x, a10); a11 = fmaf(x.y, w[j].y, a11);
            a12 = fmaf(x.y, w[j].z, a12); a13 = fmaf(x.y, w[j].w, a13);
        }
#pragma unroll
        for (int j = 0; j < 2; j++) {
            const float4 wt = *(const float4*)(Wn + (size_t)(304 + j) * FCc);
            const float2 x = *(const float2*)&xs[304 + j][s0];
            a00 = fmaf(x.x, wt.x, a00); a01 = fmaf(x.x, wt.y, a01);
            a02 = fmaf(x.x, wt.z, a02); a03 = fmaf(x.x, wt.w, a03);
            a10 = fmaf(x.y, wt.x, a10); a11 = fmaf(x.y, wt.y, a11);
            a12 = fmaf(x.y, wt.z, a12); a13 = fmaf(x.y, wt.w, a13);
        }

        *(float4*)&vals[n][s0 + 0][n0] = make_float4(
            tanhf(a00 + bn.x), tanhf(a01 + bn.y), tanhf(a02 + bn.z), tanhf(a03 + bn.w));
        *(float4*)&vals[n][s0 + 1][n0] = make_float4(
            tanhf(a10 + bn.x), tanhf(a11 + bn.y), tanhf(a12 + bn.z), tanhf(a13 + bn.w));
        __syncthreads();
    }

#pragma unroll
    for (int ss = 0; ss < CSEQ; ss++) {
        const int al = alen[ss];
        const float v = (al == 0)
            ? comp_emb[(size_t)(seq0 + ss) * 16 * FCc + tid]
            : vals[al - 1][ss][tid];
        stack_emb[(size_t)(seq0 + ss) * FCc + tid] = v;
    }
}

// ---------------- output head ----------------
__global__ void final_kernel(const int* __restrict__ l0,
                             const int* __restrict__ l1,
                             const int* __restrict__ l2,
                             const float* __restrict__ fW,
                             const float* __restrict__ fb,
                             float* __restrict__ out) {
    const int b = blockIdx.x;
    const int tid = threadIdx.x;
    __shared__ float hcat[3 * Uc];
    for (int idx = tid; idx < 3 * Uc; idx += 128) {
        const int L = idx >> 8;
        const int col = idx & 255;
        const int len = ((L == 0) ? l0 : (L == 1) ? l1 : l2)[b];
        const int j = g_inv[L][b];
        hcat[idx] = g_h1[L][(len - 1) & 1][j * Uc + col];
    }
    __syncthreads();
    if (tid < NOUTc) {
        float acc = fb[tid];
#pragma unroll 2
        for (int k = 0; k < 3 * Uc; k++) acc = fmaf(hcat[k], fW[k * NOUTc + tid], acc);
        out[b * NOUTc + tid] = acc;
    }
}

// ---------------- host driver ----------------
extern "C" void kernel_launch(void* const* d_in, const int* in_sizes, int n_in,
                              void* d_out, int out_size) {
    const int*   buff_word_id   = (const int*)d_in[0];
    const int*   buff_pos_id    = (const int*)d_in[1];
    const int*   comp_word_id   = (const int*)d_in[2];
    const int*   comp_pos_id    = (const int*)d_in[3];
    const int*   comp_action_id = (const int*)d_in[4];
    const int*   comp_action_len= (const int*)d_in[5];
    const int*   history_action_id = (const int*)d_in[6];
    const int*   stack_length   = (const int*)d_in[7];
    const int*   buff_length    = (const int*)d_in[8];
    const int*   history_action_length = (const int*)d_in[9];
    const float* p_emb      = (const float*)d_in[10];
    const float* comp_a_emb = (const float*)d_in[11];
    const float* hist_a_emb = (const float*)d_in[12];
    const float* w_emb      = (const float*)d_in[13];
    const float* emb_W      = (const float*)d_in[14];
    const float* emb_b      = (const float*)d_in[15];
    const float* rec_W      = (const float*)d_in[16];
    const float* rec_b      = (const float*)d_in[17];
    const float* W0s[3] = { (const float*)d_in[18], (const float*)d_in[22], (const float*)d_in[26] };
    const float* b0s[3] = { (const float*)d_in[19], (const float*)d_in[23], (const float*)d_in[27] };
    const float* W1s[3] = { (const float*)d_in[20], (const float*)d_in[24], (const float*)d_in[28] };
    const float* b1s[3] = { (const float*)d_in[21], (const float*)d_in[25], (const float*)d_in[29] };
    const float* fW  = (const float*)d_in[30];
    const float* fb  = (const float*)d_in[31];
    float* out = (float*)d_out;

    float *buff_emb_p, *comp_emb_p, *stack_emb_p;
    float *zx0_p, *zx1_p, *zx2_p;
    float *c0_p, *c1_p, *h0_p, *h1_p;
    unsigned* bar_p;
    cudaGetSymbolAddress((void**)&buff_emb_p,  g_buff_emb);
    cudaGetSymbolAddress((void**)&comp_emb_p,  g_comp_emb);
    cudaGetSymbolAddress((void**)&stack_emb_p, g_stack_emb);
    cudaGetSymbolAddress((void**)&zx0_p, g_zx0);
    cudaGetSymbolAddress((void**)&zx1_p, g_zx1);
    cudaGetSymbolAddress((void**)&zx2_p, g_zx2);
    cudaGetSymbolAddress((void**)&c0_p, g_c0);
    cudaGetSymbolAddress((void**)&c1_p, g_c1);
    cudaGetSymbolAddress((void**)&h0_p, g_h0);
    cudaGetSymbolAddress((void**)&h1_p, g_h1);
    cudaGetSymbolAddress((void**)&bar_p, g_bar);

    const size_t SB = (size_t)Bc * Uc;

    cudaMemsetAsync(bar_p, 0, sizeof(unsigned));
    cudaMemsetAsync(c0_p, 0, 3 * SB * sizeof(float));
    cudaMemsetAsync(c1_p, 0, 3 * SB * sizeof(float));
    cudaMemsetAsync(h0_p, 0, 3 * 2 * SB * sizeof(float));
    cudaMemsetAsync(h1_p, 0, 3 * 2 * SB * sizeof(float));

    // length sort + per-step active counts
    sort_kernel<<<3, 128>>>(stack_length, buff_length, history_action_length);

    // embeddings (dead-block skipping, v3 tiled)
    const int nbuff = Bc * BUFFc;
    embed_kernel<<<(nbuff + 7) / 8, 128>>>(buff_word_id, buff_pos_id, w_emb, p_emb,
                                           emb_W, emb_b, buff_emb_p, nbuff,
                                           buff_length, BUFFc, 1);
    const int ncomp = Bc * STKc * 16;
    embed_kernel<<<(ncomp + 7) / 8, 128>>>(comp_word_id, comp_pos_id, w_emb, p_emb,
                                           emb_W, emb_b, comp_emb_p, ncomp,
                                           stack_length, STKc * 16, 16);

    // recursive compose
    compose_kernel<<<Bc * STKc / CSEQ, 128>>>(comp_word_id, comp_emb_p,
                                              comp_action_id, comp_action_len,
                                              comp_a_emb, rec_W, rec_b,
                                              stack_length, stack_emb_p);

    // x-projections for layer0
    {
        XJobs xj;
        xj.j[0] = XJob{ stack_emb_p, nullptr, nullptr, W0s[0], zx0_p,
                        stack_length, Bc * STKc,  FCc, STKc };
        xj.j[1] = XJob{ buff_emb_p,  nullptr, nullptr, W0s[1], zx1_p,
                        buff_length, Bc * BUFFc, FCc, BUFFc };
        xj.j[2] = XJob{ nullptr, history_action_id, hist_a_emb, W0s[2], zx2_p,
                        history_action_length, Bc * HISTc, 50, HISTc };
        xproj_kernel<<<dim3(384 * 8, 3), 256>>>(xj);
    }

    // persistent fused loop
    {
        PParams P;
        for (int L = 0; L < 3; L++) {
            const int din = (L == 2) ? 50 : FCc;
            P.W0h[L] = W0s[L] + (size_t)din * 1024;
            P.b0[L]  = b0s[L];
            P.W1a[L] = W1s[L];
            P.W1b[L] = W1s[L] + (size_t)256 * 1024;
            P.b1[L]  = b1s[L];
        }
        lstm_loop_kernel<<<NBLK, 128>>>(P);
    }

    // output head
    final_kernel<<<Bc, 128>>>(stack_length, buff_length, history_action_length,
                              fW, fb, out);
}

// round 15
// speedup vs baseline: 1.9000x; 1.0236x over previous
#include <cuda_runtime.h>
#include <math.h>

// ---------------- problem constants ----------------
#define Bc    128
#define BUFFc 64
#define STKc  48
#define HISTc 96
#define FCc   128
#define Uc    256
#define NOUTc 82
#define WDIMc 300
#define POSDc 50
#define EDINc 350
#define CADc  50
#define RDINc 306
#define NBLK  576
#define NITER 98
#define CSEQ  8
#define WST   68

// ---------------- device scratch ----------------
__device__ float g_buff_emb[Bc * BUFFc * FCc];
__device__ float g_comp_emb[Bc * STKc * 16 * FCc];
__device__ float g_stack_emb[Bc * STKc * FCc];

__device__ float g_zx0[Bc * STKc  * 1024];
__device__ float g_zx1[Bc * BUFFc * 1024];
__device__ float g_zx2[Bc * HISTc * 1024];

__device__ float g_p [3][2][Bc * 1024];
__device__ float g_c0[3][Bc * Uc];
__device__ float g_c1[3][Bc * Uc];
__device__ float g_h0[3][2][Bc * Uc];
__device__ float g_h1[3][2][Bc * Uc];

__device__ int g_perm[3][Bc];
__device__ int g_inv [3][Bc];
__device__ int g_lens[3][Bc];
__device__ int g_cnt [3][HISTc];

__device__ unsigned g_bar;

__device__ __forceinline__ float sigm(float x) {
    return __fdividef(1.0f, 1.0f + __expf(-x));
}
__device__ __forceinline__ float tanh_(float x) {
    return __fdividef(2.0f, 1.0f + __expf(-2.0f * x)) - 1.0f;
}

// ---------------- per-LSTM length sort (stable, descending) ----------------
__global__ void sort_kernel(const int* len0, const int* len1, const int* len2) {
    const int L = blockIdx.x;
    const int* len = (L == 0) ? len0 : (L == 1) ? len1 : len2;
    const int T = (L == 0) ? STKc : (L == 1) ? BUFFc : HISTc;
    __shared__ int sl[Bc];
    const int tid = threadIdx.x;
    sl[tid] = len[tid];
    __syncthreads();
    const int myl = sl[tid];
    int rank = 0;
    for (int b = 0; b < Bc; b++) {
        const int lb = sl[b];
        rank += (lb > myl) || (lb == myl && b < tid);
    }
    g_perm[L][rank] = tid;
    g_inv[L][tid] = rank;
    g_lens[L][rank] = myl;
    if (tid < T) {
        int c = 0;
        for (int b = 0; b < Bc; b++) c += (sl[b] > tid);
        g_cnt[L][tid] = c;
    }
}

// ---------------- persistent fused LSTM loop (smem-cached schedule tables) ----------------
struct PParams {
    const float* W0h[3];
    const float* b0[3];
    const float* W1a[3];
    const float* W1b[3];
    const float* b1[3];
};

__global__ void __launch_bounds__(128, 4) lstm_loop_kernel(PParams P) {
    const int tid = threadIdx.x;
    const int bid = blockIdx.x;

    __shared__ __align__(16) float xs[2][32][36];
    __shared__ __align__(16) float ws_raw[2 * 32 * WST];
    __shared__ int cnt_s [3 * HISTc];
    __shared__ int lens_s[3 * Bc];
    __shared__ int perm_s[3 * Bc];
#define WS(bf,k,c) ws_raw[(bf) * (32 * WST) + (k) * WST + (c)]

    // cache invariant schedule tables once
    for (int idx = tid; idx < 3 * HISTc; idx += 128) cnt_s[idx]  = ((const int*)g_cnt)[idx];
    for (int idx = tid; idx < 3 * Bc;    idx += 128) lens_s[idx] = ((const int*)g_lens)[idx];
    for (int idx = tid; idx < 3 * Bc;    idx += 128) perm_s[idx] = ((const int*)g_perm)[idx];
    __syncthreads();

    const int mi = tid & 7,  ni = tid >> 3;
    const int m0 = mi * 4,   n0t = ni * 4;
    const int xm = tid >> 2;
    const int xk4 = (tid & 3) * 4;
    const int wk = tid >> 4;
    const int wc4 = tid & 15;

    for (int i = 0; i < NITER; i++) {
        const int pr = (i + 1) & 1;
        const int pw = i & 1;

        int sfound = -1, local = 0, off = 0;
#pragma unroll
        for (int s = 0; s < 9; s++) {
            const int Ls = s / 3, kind = s - Ls * 3;
            const int Ts = (Ls == 0) ? STKc : (Ls == 1) ? BUFFc : HISTc;
            const int ts = i - kind;
            int nb = 0;
            if (ts >= 0 && ts < Ts) {
                const int cc = cnt_s[Ls * HISTc + ts];
                nb = (cc + 31) >> 5;
            }
            const int items = nb * 16;
            if (sfound < 0 && bid >= off && bid < off + items) {
                sfound = s; local = bid - off;
            }
            off += items;
        }

        if (sfound >= 0) {
            const int L = sfound / 3, kind = sfound - L * 3;
            const int Ts = (L == 0) ? STKc : (L == 1) ? BUFFc : HISTc;
            const int t = i - kind;
            const int bm = local >> 4, bu = local & 15;
            const int b0r = bm * 32;
            const int u0 = bu * 16;
            const int gcol = (wc4 >> 2) * 256 + u0 + (wc4 & 3) * 4;

            const float* src;
            const float* W;
            const float* extra = nullptr;
            const float* bias = nullptr;
            float* c = nullptr;
            float* h_out = nullptr;
            float* p_out = nullptr;
            bool gates;
            if (kind == 0) {
                gates = true;
                src = &g_h0[L][pr][0];
                W = P.W0h[L];
                bias = P.b0[L];
                c = &g_c0[L][0];
                h_out = &g_h0[L][pw][0];
            } else if (kind == 1) {
                gates = false;
                src = &g_h0[L][pr][0];
                W = P.W1a[L];
                p_out = &g_p[L][pr][0];
            } else {
                gates = true;
                src = &g_h1[L][pr][0];
                W = P.W1b[L];
                extra = &g_p[L][pw][0];
                bias = P.b1[L];
                c = &g_c1[L][0];
                h_out = &g_h1[L][pw][0];
            }

            float acc[4][4];
#pragma unroll
            for (int a = 0; a < 4; a++)
#pragma unroll
                for (int b = 0; b < 4; b++) acc[a][b] = 0.0f;

            const float* srow = src + (b0r + xm) * Uc;

            {
                float4 xa = __ldcg((const float4*)(srow + xk4));
                float4 xb = __ldcg((const float4*)(srow + xk4 + 16));
                xs[0][xk4 + 0][xm] = xa.x; xs[0][xk4 + 1][xm] = xa.y;
                xs[0][xk4 + 2][xm] = xa.z; xs[0][xk4 + 3][xm] = xa.w;
                xs[0][xk4 + 16][xm] = xb.x; xs[0][xk4 + 17][xm] = xb.y;
                xs[0][xk4 + 18][xm] = xb.z; xs[0][xk4 + 19][xm] = xb.w;
#pragma unroll
                for (int q = 0; q < 4; q++) {
                    const int kk = wk + 8 * q;
                    *(float4*)&WS(0, kk, wc4 * 4) =
                        *(const float4*)(W + (size_t)kk * 1024 + gcol);
                }
            }
            __syncthreads();

            int buf = 0;
#pragma unroll 1
            for (int kt = 0; kt < 8; kt++) {
                float4 xa, xb, wv0, wv1, wv2, wv3;
                const bool more = (kt < 7);
                if (more) {
                    const int k0 = (kt + 1) * 32;
                    xa = __ldcg((const float4*)(srow + k0 + xk4));
                    xb = __ldcg((const float4*)(srow + k0 + xk4 + 16));
                    const float* wrow = W + (size_t)(k0 + wk) * 1024 + gcol;
                    wv0 = *(const float4*)(wrow);
                    wv1 = *(const float4*)(wrow +  8 * 1024);
                    wv2 = *(const float4*)(wrow + 16 * 1024);
                    wv3 = *(const float4*)(wrow + 24 * 1024);
                }

                const float (*xsb)[36] = xs[buf];
#pragma unroll
                for (int kk = 0; kk < 32; kk++) {
                    const float4 x = *(const float4*)&xsb[kk][m0];
                    const float4 w = *(const float4*)&WS(buf, kk, n0t);
                    acc[0][0] = fmaf(x.x, w.x, acc[0][0]);
                    acc[0][1] = fmaf(x.x, w.y, acc[0][1]);
                    acc[0][2] = fmaf(x.x, w.z, acc[0][2]);
                    acc[0][3] = fmaf(x.x, w.w, acc[0][3]);
                    acc[1][0] = fmaf(x.y, w.x, acc[1][0]);
                    acc[1][1] = fmaf(x.y, w.y, acc[1][1]);
                    acc[1][2] = fmaf(x.y, w.z, acc[1][2]);
                    acc[1][3] = fmaf(x.y, w.w, acc[1][3]);
                    acc[2][0] = fmaf(x.z, w.x, acc[2][0]);
                    acc[2][1] = fmaf(x.z, w.y, acc[2][1]);
                    acc[2][2] = fmaf(x.z, w.z, acc[2][2]);
                    acc[2][3] = fmaf(x.z, w.w, acc[2][3]);
                    acc[3][0] = fmaf(x.w, w.x, acc[3][0]);
                    acc[3][1] = fmaf(x.w, w.y, acc[3][1]);
                    acc[3][2] = fmaf(x.w, w.z, acc[3][2]);
                    acc[3][3] = fmaf(x.w, w.w, acc[3][3]);
                }

                if (more) {
                    const int nb2 = buf ^ 1;
                    xs[nb2][xk4 + 0][xm] = xa.x; xs[nb2][xk4 + 1][xm] = xa.y;
                    xs[nb2][xk4 + 2][xm] = xa.z; xs[nb2][xk4 + 3][xm] = xa.w;
                    xs[nb2][xk4 + 16][xm] = xb.x; xs[nb2][xk4 + 17][xm] = xb.y;
                    xs[nb2][xk4 + 18][xm] = xb.z; xs[nb2][xk4 + 19][xm] = xb.w;
                    *(float4*)&WS(nb2, wk +  0, wc4 * 4) = wv0;
                    *(float4*)&WS(nb2, wk +  8, wc4 * 4) = wv1;
                    *(float4*)&WS(nb2, wk + 16, wc4 * 4) = wv2;
                    *(float4*)&WS(nb2, wk + 24, wc4 * 4) = wv3;
                    __syncthreads();
                    buf = nb2;
                }
            }

            if (!gates) {
                const int gcolS = (n0t >> 4) * 256 + u0 + (n0t & 15);
#pragma unroll
                for (int a = 0; a < 4; a++) {
                    __stcg((float4*)(p_out + (size_t)(b0r + m0 + a) * 1024 + gcolS),
                           make_float4(acc[a][0], acc[a][1], acc[a][2], acc[a][3]));
                }
            } else {
                __syncthreads();
                float* zt = ws_raw;
#pragma unroll
                for (int cc = 0; cc < 4; cc++)
#pragma unroll
                    for (int a = 0; a < 4; a++)
                        zt[(n0t + cc) * 33 + (m0 + a)] = acc[a][cc];
                __syncthreads();

                const int uu = tid & 15;
                const int bq = tid >> 4;
                const int colu = u0 + uu;
                const float bi = bias[colu];
                const float bj = bias[256 + colu];
                const float bf = bias[512 + colu];
                const float bo = bias[768 + colu];
                const float* zxbase = (L == 0) ? g_zx0 : (L == 1) ? g_zx1 : g_zx2;

#pragma unroll
                for (int q = 0; q < 4; q++) {
                    const int bl = bq + 8 * q;
                    const int j = b0r + bl;
                    if (t < lens_s[L * Bc + j]) {
                        const float* er;
                        if (kind == 0)
                            er = zxbase + ((size_t)perm_s[L * Bc + j] * Ts + t) * 1024;
                        else
                            er = extra + (size_t)j * 1024;
                        const int gidx = j * Uc + colu;
                        float g0 = zt[(  0 + uu) * 33 + bl] + bi + __ldcg(&er[colu]);
                        float g1 = zt[( 16 + uu) * 33 + bl] + bj + __ldcg(&er[256 + colu]);
                        float g2 = zt[( 32 + uu) * 33 + bl] + bf + __ldcg(&er[512 + colu]);
                        float g3 = zt[( 48 + uu) * 33 + bl] + bo + __ldcg(&er[768 + colu]);
                        const float cn = __ldcg(&c[gidx]) * sigm(g2 + 1.0f)
                                       + sigm(g0) * tanh_(g1);
                        const float hn = tanh_(cn) * sigm(g3);
                        __stcg(&c[gidx], cn);
                        __stcg(&h_out[gidx], hn);
                    }
                }
            }
        }

        __syncthreads();
        __threadfence();
        if (tid == 0) {
            atomicAdd(&g_bar, 1u);
            const unsigned target = (unsigned)NBLK * (unsigned)(i + 1);
            volatile unsigned* vb = &g_bar;
            while (*vb < target) __nanosleep(32);
        }
        __syncthreads();
    }
#undef WS
}

// ---------------- x-projection precompute (3-job batched, masked-block skip) ----------------
struct XJob { const float* x; const int* ids; const float* tab;
              const float* W; float* zx; const int* len; int rows, Din, T; };
struct XJobs { XJob j[3]; };

__global__ void xproj_kernel(XJobs jobs) {
    const XJob J = jobs.j[blockIdx.y];
    const int bm = blockIdx.x % 384;
    const int bn = blockIdx.x / 384;
    const int r0 = bm * 32;
    if (r0 >= J.rows) return;
    const int tid = threadIdx.x;

    int pred = 0;
    if (tid < 32) {
        const int r = r0 + tid;
        const int bb = r / J.T;
        const int tt = r - bb * J.T;
        pred = (tt < J.len[bb]);
    }
    if (!__syncthreads_or(pred)) return;

    const int n0 = bn * 128;
    __shared__ __align__(16) float xs[32][36];
    __shared__ __align__(16) float ws[32][128];
    const int mi = tid & 7, ni = tid >> 3;
    const int m0 = mi * 4, n0t = ni * 4;
    const int xm = tid >> 3, xk = (tid & 7) * 4;
    const int wc = (tid & 31) * 4, wk = tid >> 5;

    float acc[4][4];
#pragma unroll
    for (int a = 0; a < 4; a++)
#pragma unroll
        for (int b = 0; b < 4; b++) acc[a][b] = 0.0f;

    const int r = r0 + xm;
    const float* srow = J.ids ? (J.tab + (size_t)J.ids[r] * J.Din)
                              : (J.x + (size_t)r * J.Din);

    const int nk = (J.Din + 31) >> 5;
    for (int kt = 0; kt < nk; kt++) {
        const int k0 = kt * 32;
        __syncthreads();
#pragma unroll
        for (int j = 0; j < 4; j++) {
            const int k = k0 + xk + j;
            xs[xk + j][xm] = (k < J.Din) ? srow[k] : 0.0f;
        }
#pragma unroll
        for (int q = 0; q < 4; q++) {
            const int kk = wk + 8 * q, k = k0 + kk;
            float4 wv = make_float4(0.f, 0.f, 0.f, 0.f);
            if (k < J.Din)
                wv = *(const float4*)(J.W + (size_t)k * 1024 + n0 + wc);
            *(float4*)&ws[kk][wc] = wv;
        }
        __syncthreads();
#pragma unroll 8
        for (int kk = 0; kk < 32; kk++) {
            const float4 x = *(const float4*)&xs[kk][m0];
            const float4 w = *(const float4*)&ws[kk][n0t];
            acc[0][0] = fmaf(x.x, w.x, acc[0][0]);
            acc[0][1] = fmaf(x.x, w.y, acc[0][1]);
            acc[0][2] = fmaf(x.x, w.z, acc[0][2]);
            acc[0][3] = fmaf(x.x, w.w, acc[0][3]);
            acc[1][0] = fmaf(x.y, w.x, acc[1][0]);
            acc[1][1] = fmaf(x.y, w.y, acc[1][1]);
            acc[1][2] = fmaf(x.y, w.z, acc[1][2]);
            acc[1][3] = fmaf(x.y, w.w, acc[1][3]);
            acc[2][0] = fmaf(x.z, w.x, acc[2][0]);
            acc[2][1] = fmaf(x.z, w.y, acc[2][1]);
            acc[2][2] = fmaf(x.z, w.z, acc[2][2]);
            acc[2][3] = fmaf(x.z, w.w, acc[2][3]);
            acc[3][0] = fmaf(x.w, w.x, acc[3][0]);
            acc[3][1] = fmaf(x.w, w.y, acc[3][1]);
            acc[3][2] = fmaf(x.w, w.z, acc[3][2]);
            acc[3][3] = fmaf(x.w, w.w, acc[3][3]);
        }
    }
#pragma unroll
    for (int a = 0; a < 4; a++) {
        *(float4*)(J.zx + (size_t)(r0 + m0 + a) * 1024 + n0 + n0t) =
            make_float4(acc[a][0], acc[a][1], acc[a][2], acc[a][3]);
    }
}

// ---------------- embedding v3 (unchanged) ----------------
__global__ void __launch_bounds__(128) embed_kernel(
    const int* __restrict__ word_ids,
    const int* __restrict__ pos_ids,
    const float* __restrict__ w_emb,
    const float* __restrict__ p_emb,
    const float* __restrict__ W,
    const float* __restrict__ bias,
    float* __restrict__ out,
    int nrows,
    const int* __restrict__ len,
    int per_b, int per_item)
{
    const int r0 = blockIdx.x * 8;
    {
        const int b = r0 / per_b;
        const int item = (r0 - b * per_b) / per_item;
        if (item >= len[b]) return;
    }
    __shared__ __align__(16) float xs[EDINc][10];
    __shared__ int wid_s[8], pid_s[8];
    const int tid = threadIdx.x;

    if (tid < 8) {
        int row = r0 + tid;
        wid_s[tid] = (row < nrows) ? word_ids[row] : 0;
        pid_s[tid] = (row < nrows) ? pos_ids[row] : 0;
    }
    __syncthreads();

    for (int idx = tid; idx < 8 * EDINc; idx += 128) {
        int r = idx / EDINc, k = idx - r * EDINc;
        float v;
        if (k < WDIMc) v = w_emb[wid_s[r] * WDIMc + k];
        else           v = p_emb[pid_s[r] * POSDc + (k - WDIMc)];
        xs[k][r] = v;
    }
    __syncthreads();

    const int ri = tid >> 5;
    const int s0 = 2 * ri;
    const int n0 = (tid & 31) * 4;
    const float4 bv = *(const float4*)(bias + n0);
    const float* Wn = W + n0;

    float a00 = 0.f, a01 = 0.f, a02 = 0.f, a03 = 0.f;
    float a10 = 0.f, a11 = 0.f, a12 = 0.f, a13 = 0.f;

    float4 w0 = *(const float4*)(Wn + 0 * FCc);
    float4 w1 = *(const float4*)(Wn + 1 * FCc);
    float4 w2 = *(const float4*)(Wn + 2 * FCc);
    float4 w3 = *(const float4*)(Wn + 3 * FCc);
#pragma unroll 1
    for (int k = 0; k < 348; k += 4) {
        float4 p0, p1, p2, p3;
        p0 = (k + 4 < EDINc) ? *(const float4*)(Wn + (size_t)(k + 4) * FCc) : w0;
        p1 = (k + 5 < EDINc) ? *(const float4*)(Wn + (size_t)(k + 5) * FCc) : w1;
        p2 = (k + 6 < EDINc) ? *(const float4*)(Wn + (size_t)(k + 6) * FCc) : w2;
        p3 = (k + 7 < EDINc) ? *(const float4*)(Wn + (size_t)(k + 7) * FCc) : w3;
        const float2 x0 = *(const float2*)&xs[k + 0][s0];
        const float2 x1 = *(const float2*)&xs[k + 1][s0];
        const float2 x2 = *(const float2*)&xs[k + 2][s0];
        const float2 x3 = *(const float2*)&xs[k + 3][s0];
        a00 = fmaf(x0.x, w0.x, a00); a01 = fmaf(x0.x, w0.y, a01);
        a02 = fmaf(x0.x, w0.z, a02); a03 = fmaf(x0.x, w0.w, a03);
        a10 = fmaf(x0.y, w0.x, a10); a11 = fmaf(x0.y, w0.y, a11);
        a12 = fmaf(x0.y, w0.z, a12); a13 = fmaf(x0.y, w0.w, a13);
        a00 = fmaf(x1.x, w1.x, a00); a01 = fmaf(x1.x, w1.y, a01);
        a02 = fmaf(x1.x, w1.z, a02); a03 = fmaf(x1.x, w1.w, a03);
        a10 = fmaf(x1.y, w1.x, a10); a11 = fmaf(x1.y, w1.y, a11);
        a12 = fmaf(x1.y, w1.z, a12); a13 = fmaf(x1.y, w1.w, a13);
        a00 = fmaf(x2.x, w2.x, a00); a01 = fmaf(x2.x, w2.y, a01);
        a02 = fmaf(x2.x, w2.z, a02); a03 = fmaf(x2.x, w2.w, a03);
        a10 = fmaf(x2.y, w2.x, a10); a11 = fmaf(x2.y, w2.y, a11);
        a12 = fmaf(x2.y, w2.z, a12); a13 = fmaf(x2.y, w2.w, a13);
        a00 = fmaf(x3.x, w3.x, a00); a01 = fmaf(x3.x, w3.y, a01);
        a02 = fmaf(x3.x, w3.z, a02); a03 = fmaf(x3.x, w3.w, a03);
        a10 = fmaf(x3.y, w3.x, a10); a11 = fmaf(x3.y, w3.y, a11);
        a12 = fmaf(x3.y, w3.z, a12); a13 = fmaf(x3.y, w3.w, a13);
        w0 = p0; w1 = p1; w2 = p2; w3 = p3;
    }
    {
        const float2 x0 = *(const float2*)&xs[348][s0];
        const float2 x1 = *(const float2*)&xs[349][s0];
        a00 = fmaf(x0.x, w0.x, a00); a01 = fmaf(x0.x, w0.y, a01);
        a02 = fmaf(x0.x, w0.z, a02); a03 = fmaf(x0.x, w0.w, a03);
        a10 = fmaf(x0.y, w0.x, a10); a11 = fmaf(x0.y, w0.y, a11);
        a12 = fmaf(x0.y, w0.z, a12); a13 = fmaf(x0.y, w0.w, a13);
        a00 = fmaf(x1.x, w1.x, a00); a01 = fmaf(x1.x, w1.y, a01);
        a02 = fmaf(x1.x, w1.z, a02); a03 = fmaf(x1.x, w1.w, a03);
        a10 = fmaf(x1.y, w1.x, a10); a11 = fmaf(x1.y, w1.y, a11);
        a12 = fmaf(x1.y, w1.z, a12); a13 = fmaf(x1.y, w1.w, a13);
    }

    const int rowA = r0 + s0, rowB = r0 + s0 + 1;
    if (rowA < nrows)
        *(float4*)(out + (size_t)rowA * FCc + n0) = make_float4(
            fmaxf(a00 + bv.x, 0.f), fmaxf(a01 + bv.y, 0.f),
            fmaxf(a02 + bv.z, 0.f), fmaxf(a03 + bv.w, 0.f));
    if (rowB < nrows)
        *(float4*)(out + (size_t)rowB * FCc + n0) = make_float4(
            fmaxf(a10 + bv.x, 0.f), fmaxf(a11 + bv.y, 0.f),
            fmaxf(a12 + bv.z, 0.f), fmaxf(a13 + bv.w, 0.f));
}

// ---------------- compose v4 (unchanged) ----------------
__global__ void __launch_bounds__(128) compose_kernel(
    const int* __restrict__ comp_word_id,
    const float* __restrict__ comp_emb,
    const int* __restrict__ comp_action_id,
    const int* __restrict__ comp_action_len,
    const float* __restrict__ a_emb,
    const float* __restrict__ rec_W,
    const float* __restrict__ rec_b,
    const int* __restrict__ stack_len,
    float* __restrict__ stack_emb)
{
    const int seq0 = blockIdx.x * CSEQ;
    {
        const int b = seq0 / STKc;
        const int stk0 = seq0 - b * STKc;
        if (stk0 >= stack_len[b]) return;
    }
    const int tid = threadIdx.x;

    __shared__ float vals[8][CSEQ][FCc];
    __shared__ __align__(16) float xs[RDINc][10];
    __shared__ int wid[CSEQ][16];
    __shared__ int act[CSEQ][8];
    __shared__ int alen[CSEQ];
    __shared__ signed char ihs[CSEQ][8], idds[CSEQ][8];

    {
        const int ss = tid >> 4, slot = tid & 15;
        wid[ss][slot] = comp_word_id[(seq0 + ss) * 16 + slot];
        if (tid < CSEQ * 8) {
            const int s2 = tid >> 3, n = tid & 7;
            act[s2][n] = comp_action_id[(seq0 + s2) * 8 + n];
        }
        if (tid < CSEQ) alen[tid] = comp_action_len[seq0 + tid];
    }
    __syncthreads();
    if (tid < CSEQ * 8) {
        const int ss = tid >> 3, n = tid & 7;
        const int hn = wid[ss][2 * n], dn = wid[ss][2 * n + 1];
        int ih = -1, idd = -1;
        for (int m = 0; m < n; m++) {
            const int hm = wid[ss][2 * m];
            if (hm == hn) ih = m;
            if (hm == dn) idd = m;
        }
        ihs[ss][n] = (signed char)ih;
        idds[ss][n] = (signed char)idd;
    }
    __syncthreads();

    const int mi = tid & 3,  ni = tid >> 2;
    const int s0 = mi * 2,   n0 = ni * 4;
    const float4 bn = *(const float4*)(rec_b + n0);
    const float* Wn = rec_W + n0;

    for (int n = 0; n < 8; n++) {
#pragma unroll
        for (int ss = 0; ss < CSEQ; ss++) {
            const int ih = ihs[ss][n], idd = idds[ss][n];
            const int an = act[ss][n];
#pragma unroll
            for (int j = 0; j < 3; j++) {
                const int k = tid + j * 128;
                if (k < RDINc) {
                    float v;
                    if (k < FCc) {
                        v = (ih >= 0) ? vals[ih][ss][k]
                                      : comp_emb[((size_t)(seq0 + ss) * 16 + 2 * n) * FCc + k];
                    } else if (k < FCc + CADc) {
                        v = a_emb[an * CADc + (k - FCc)];
                    } else {
                        const int kk = k - (FCc + CADc);
                        v = (idd >= 0) ? vals[idd][ss][kk]
                                       : comp_emb[((size_t)(seq0 + ss) * 16 + 2 * n + 1) * FCc + kk];
                    }
                    xs[k][ss] = v;
                }
            }
        }
        __syncthreads();

        float a00 = 0.f, a01 = 0.f, a02 = 0.f, a03 = 0.f;
        float a10 = 0.f, a11 = 0.f, a12 = 0.f, a13 = 0.f;

        float4 w[8];
#pragma unroll
        for (int j = 0; j < 8; j++)
            w[j] = *(const float4*)(Wn + (size_t)j * FCc);

#pragma unroll 1
        for (int k = 0; k < 296; k += 8) {
            float4 p[8];
#pragma unroll
            for (int j = 0; j < 8; j++)
                p[j] = *(const float4*)(Wn + (size_t)(k + 8 + j) * FCc);
#pragma unroll
            for (int j = 0; j < 8; j++) {
                const float2 x = *(const float2*)&xs[k + j][s0];
                a00 = fmaf(x.x, w[j].x, a00); a01 = fmaf(x.x, w[j].y, a01);
                a02 = fmaf(x.x, w[j].z, a02); a03 = fmaf(x.x, w[j].w, a03);
                a10 = fmaf(x.y, w[j].x, a10); a11 = fmaf(x.y, w[j].y, a11);
                a12 = fmaf(x.y, w[j].z, a12); a13 = fmaf(x.y, w[j].w, a13);
            }
#pragma unroll
            for (int j = 0; j < 8; j++) w[j] = p[j];
        }
#pragma unroll
        for (int j = 0; j < 8; j++) {
            const float2 x = *(const float2*)&xs[296 + j][s0];
            a00 = fmaf(x.x, w[j].x, a00); a01 = fmaf(x.x, w[j].y, a01);
            a02 = fmaf(x.x, w[j].z, a02); a03 = fmaf(x.x, w[j].w, a03);
            a10 = fmaf(x.y, w[j].x, a10); a11 = fmaf(x.y, w[j].y, a11);
            a12 = fmaf(x.y, w[j].z, a12); a13 = fmaf(x.y, w[j].w, a13);
        }
#pragma unroll
        for (int j = 0; j < 2; j++) {
            const float4 wt = *(const float4*)(Wn + (size_t)(304 + j) * FCc);
            const float2 x = *(const float2*)&xs[304 + j][s0];
            a00 = fmaf(x.x, wt.x, a00); a01 = fmaf(x.x, wt.y, a01);
            a02 = fmaf(x.x, wt.z, a02); a03 = fmaf(x.x, wt.w, a03);
            a10 = fmaf(x.y, wt.x, a10); a11 = fmaf(x.y, wt.y, a11);
            a12 = fmaf(x.y, wt.z, a12); a13 = fmaf(x.y, wt.w, a13);
        }

        *(float4*)&vals[n][s0 + 0][n0] = make_float4(
            tanhf(a00 + bn.x), tanhf(a01 + bn.y), tanhf(a02 + bn.z), tanhf(a03 + bn.w));
        *(float4*)&vals[n][s0 + 1][n0] = make_float4(
            tanhf(a10 + bn.x), tanhf(a11 + bn.y), tanhf(a12 + bn.z), tanhf(a13 + bn.w));
        __syncthreads();
    }

#pragma unroll
    for (int ss = 0; ss < CSEQ; ss++) {
        const int al = alen[ss];
        const float v = (al == 0)
            ? comp_emb[(size_t)(seq0 + ss) * 16 * FCc + tid]
            : vals[al - 1][ss][tid];
        stack_emb[(size_t)(seq0 + ss) * FCc + tid] = v;
    }
}

// ---------------- output head ----------------
__global__ void final_kernel(const int* __restrict__ l0,
                             const int* __restrict__ l1,
                             const int* __restrict__ l2,
                             const float* __restrict__ fW,
                             const float* __restrict__ fb,
                             float* __restrict__ out) {
    const int b = blockIdx.x;
    const int tid = threadIdx.x;
    __shared__ float hcat[3 * Uc];
    for (int idx = tid; idx < 3 * Uc; idx += 128) {
        const int L = idx >> 8;
        const int col = idx & 255;
        const int len = ((L == 0) ? l0 : (L == 1) ? l1 : l2)[b];
        const int j = g_inv[L][b];
        hcat[idx] = g_h1[L][(len - 1) & 1][j * Uc + col];
    }
    __syncthreads();
    if (tid < NOUTc) {
        float acc = fb[tid];
#pragma unroll 2
        for (int k = 0; k < 3 * Uc; k++) acc = fmaf(hcat[k], fW[k * NOUTc + tid], acc);
        out[b * NOUTc + tid] = acc;
    }
}

// ---------------- host driver (single stream, no resource creation) ----------------
extern "C" void kernel_launch(void* const* d_in, const int* in_sizes, int n_in,
                              void* d_out, int out_size) {
    const int*   buff_word_id   = (const int*)d_in[0];
    const int*   buff_pos_id    = (const int*)d_in[1];
    const int*   comp_word_id   = (const int*)d_in[2];
    const int*   comp_pos_id    = (const int*)d_in[3];
    const int*   comp_action_id = (const int*)d_in[4];
    const int*   comp_action_len= (const int*)d_in[5];
    const int*   history_action_id = (const int*)d_in[6];
    const int*   stack_length   = (const int*)d_in[7];
    const int*   buff_length    = (const int*)d_in[8];
    const int*   history_action_length = (const int*)d_in[9];
    const float* p_emb      = (const float*)d_in[10];
    const float* comp_a_emb = (const float*)d_in[11];
    const float* hist_a_emb = (const float*)d_in[12];
    const float* w_emb      = (const float*)d_in[13];
    const float* emb_W      = (const float*)d_in[14];
    const float* emb_b      = (const float*)d_in[15];
    const float* rec_W      = (const float*)d_in[16];
    const float* rec_b      = (const float*)d_in[17];
    const float* W0s[3] = { (const float*)d_in[18], (const float*)d_in[22], (const float*)d_in[26] };
    const float* b0s[3] = { (const float*)d_in[19], (const float*)d_in[23], (const float*)d_in[27] };
    const float* W1s[3] = { (const float*)d_in[20], (const float*)d_in[24], (const float*)d_in[28] };
    const float* b1s[3] = { (const float*)d_in[21], (const float*)d_in[25], (const float*)d_in[29] };
    const float* fW  = (const float*)d_in[30];
    const float* fb  = (const float*)d_in[31];
    float* out = (float*)d_out;

    float *buff_emb_p, *comp_emb_p, *stack_emb_p;
    float *zx0_p, *zx1_p, *zx2_p;
    float *c0_p, *c1_p, *h0_p, *h1_p;
    unsigned* bar_p;
    cudaGetSymbolAddress((void**)&buff_emb_p,  g_buff_emb);
    cudaGetSymbolAddress((void**)&comp_emb_p,  g_comp_emb);
    cudaGetSymbolAddress((void**)&stack_emb_p, g_stack_emb);
    cudaGetSymbolAddress((void**)&zx0_p, g_zx0);
    cudaGetSymbolAddress((void**)&zx1_p, g_zx1);
    cudaGetSymbolAddress((void**)&zx2_p, g_zx2);
    cudaGetSymbolAddress((void**)&c0_p, g_c0);
    cudaGetSymbolAddress((void**)&c1_p, g_c1);
    cudaGetSymbolAddress((void**)&h0_p, g_h0);
    cudaGetSymbolAddress((void**)&h1_p, g_h1);
    cudaGetSymbolAddress((void**)&bar_p, g_bar);

    const size_t SB = (size_t)Bc * Uc;

    cudaMemsetAsync(bar_p, 0, sizeof(unsigned));
    cudaMemsetAsync(c0_p, 0, 3 * SB * sizeof(float));
    cudaMemsetAsync(c1_p, 0, 3 * SB * sizeof(float));
    cudaMemsetAsync(h0_p, 0, 3 * 2 * SB * sizeof(float));
    cudaMemsetAsync(h1_p, 0, 3 * 2 * SB * sizeof(float));

    // length sort + per-step active counts
    sort_kernel<<<3, 128>>>(stack_length, buff_length, history_action_length);

    // embeddings (dead-block skipping)
    const int nbuff = Bc * BUFFc;
    embed_kernel<<<(nbuff + 7) / 8, 128>>>(buff_word_id, buff_pos_id, w_emb, p_emb,
                                           emb_W, emb_b, buff_emb_p, nbuff,
                                           buff_length, BUFFc, 1);
    const int ncomp = Bc * STKc * 16;
    embed_kernel<<<(ncomp + 7) / 8, 128>>>(comp_word_id, comp_pos_id, w_emb, p_emb,
                                           emb_W, emb_b, comp_emb_p, ncomp,
                                           stack_length, STKc * 16, 16);

    // recursive compose
    compose_kernel<<<Bc * STKc / CSEQ, 128>>>(comp_word_id, comp_emb_p,
                                              comp_action_id, comp_action_len,
                                              comp_a_emb, rec_W, rec_b,
                                              stack_length, stack_emb_p);

    // x-projections for layer0
    {
        XJobs xj;
        xj.j[0] = XJob{ stack_emb_p, nullptr, nullptr, W0s[0], zx0_p,
                        stack_length, Bc * STKc,  FCc, STKc };
        xj.j[1] = XJob{ buff_emb_p,  nullptr, nullptr, W0s[1], zx1_p,
                        buff_length, Bc * BUFFc, FCc, BUFFc };
        xj.j[2] = XJob{ nullptr, history_action_id, hist_a_emb, W0s[2], zx2_p,
                        history_action_length, Bc * HISTc, 50, HISTc };
        xproj_kernel<<<dim3(384 * 8, 3), 256>>>(xj);
    }

    // persistent fused loop
    {
        PParams P;
        for (int L = 0; L < 3; L++) {
            const int din = (L == 2) ? 50 : FCc;
            P.W0h[L] = W0s[L] + (size_t)din * 1024;
            P.b0[L]  = b0s[L];
            P.W1a[L] = W1s[L];
            P.W1b[L] = W1s[L] + (size_t)256 * 1024;
            P.b1[L]  = b1s[L];
        }
        lstm_loop_kernel<<<NBLK, 128>>>(P);
    }

    // output head
    final_kernel<<<Bc, 128>>>(stack_length, buff_length, history_action_length,
                              fW, fb, out);
}